// round 2
// baseline (speedup 1.0000x reference)
#include <cuda_runtime.h>
#include <math.h>

#define BB 2
#define LL 2048
#define HH 16
#define DH 32
#define DM 512
#define SCALE 0.044194173824159216f  /* 1/sqrt(512) */

// Scratch (allowed: __device__ globals, no runtime allocation)
__device__ float g_q[BB*HH*LL*DH];
__device__ float g_k[BB*HH*LL*DH];
__device__ float g_v[BB*HH*LL*DH];
__device__ float g_p[HH*LL*DH];
__device__ float g_ctx[BB*HH*LL*DH];

// ---------------------------------------------------------------------------
// GEMM: C[m,n] = sum_k A[m,k] * W[n,k] + bias[n],  K = N = 512
// amode: 0 = A row-major [M,512]; 1 = A is head-layout ctx [B,H,L,32]
// omode: 0 = C row-major [M,512]; 1 = C head-layout [(b*H+h)*L + l]*32 + d
// ---------------------------------------------------------------------------
#define GBM 128
#define GBN 64
#define GBK 16

__global__ __launch_bounds__(256, 3)
void gemm512(const float* __restrict__ A, const float* __restrict__ W,
             const float* __restrict__ bias, float* __restrict__ C,
             int M, int amode, int omode)
{
    __shared__ float As[GBK][GBM + 4];
    __shared__ float Ws[GBK][GBN + 4];

    const int m0 = blockIdx.y * GBM;
    const int n0 = blockIdx.x * GBN;
    const int tid = threadIdx.x;
    const int tx = tid & 15;   // 16 groups of 4 cols
    const int ty = tid >> 4;   // 16 groups of 8 rows

    float acc[8][4];
#pragma unroll
    for (int i = 0; i < 8; i++)
#pragma unroll
        for (int j = 0; j < 4; j++) acc[i][j] = 0.f;

    for (int k0 = 0; k0 < DM; k0 += GBK) {
        // Load A tile: 128x16 = 2048 elems, 8 per thread
#pragma unroll
        for (int t = 0; t < 8; t++) {
            int idx = tid + t * 256;
            int m = idx >> 4, k = idx & 15;
            int gm = m0 + m;
            int e  = k0 + k;
            float av;
            if (amode == 0) {
                av = A[(size_t)gm * DM + e];
            } else {
                int b = gm / LL, l = gm % LL;
                av = A[(((size_t)b * HH + (e >> 5)) * LL + l) * DH + (e & 31)];
            }
            As[k][m] = av;
        }
        // Load W tile: 64x16 = 1024 elems, 4 per thread
#pragma unroll
        for (int t = 0; t < 4; t++) {
            int idx = tid + t * 256;
            int n = idx >> 4, k = idx & 15;
            Ws[k][n] = W[(size_t)(n0 + n) * DM + k0 + k];
        }
        __syncthreads();

#pragma unroll
        for (int kk = 0; kk < GBK; kk++) {
            float a[8], b[4];
#pragma unroll
            for (int i = 0; i < 8; i++) a[i] = As[kk][ty * 8 + i];
#pragma unroll
            for (int j = 0; j < 4; j++) b[j] = Ws[kk][tx * 4 + j];
#pragma unroll
            for (int i = 0; i < 8; i++)
#pragma unroll
                for (int j = 0; j < 4; j++) acc[i][j] += a[i] * b[j];
        }
        __syncthreads();
    }

#pragma unroll
    for (int i = 0; i < 8; i++) {
        int m = m0 + ty * 8 + i;
#pragma unroll
        for (int j = 0; j < 4; j++) {
            int n = n0 + tx * 4 + j;
            float val = acc[i][j] + (bias ? bias[n] : 0.f);
            if (omode == 0) {
                C[(size_t)m * DM + n] = val;
            } else {
                int b = m / LL, l = m % LL;
                C[(((size_t)b * HH + (n >> 5)) * LL + l) * DH + (n & 31)] = val;
            }
        }
    }
}

// ---------------------------------------------------------------------------
// Fused flash-style attention with Transformer-XL relative shift.
// One thread per query row i. TI=128 rows per block, TJ=32 keys per step.
// Shifted pos score: r = j-i.
//   r <= 0 : (q_i   + vb) . p[L-1+r]
//   r == 1 : 0                               (zero row in pband)
//   r >= 2 : (q_{i+1}+vb) . p[r-2]
// ---------------------------------------------------------------------------
#define TI 128
#define TJ 32
#define PBW (TI + TJ - 1)   /* 159 */

__global__ __launch_bounds__(128, 4)
void attn_kernel(const float* __restrict__ qd, const float* __restrict__ kd,
                 const float* __restrict__ vd, const float* __restrict__ pd,
                 const float* __restrict__ ub, const float* __restrict__ vb,
                 float* __restrict__ ctx)
{
    __shared__ float Ks[TJ][DH];          // broadcast reads
    __shared__ float Vs[TJ][DH];          // broadcast reads
    __shared__ float qvs[TI + 1][DH + 1]; // +1 pad: conflict-free row-varying reads
    __shared__ float pband[PBW][DH + 1];  // +1 pad

    const int tid = threadIdx.x;
    const int I0 = blockIdx.x * TI;
    const int h = blockIdx.y, b = blockIdx.z;

    const float* qbase = qd + (size_t)(b * HH + h) * LL * DH;
    const float* kbase = kd + (size_t)(b * HH + h) * LL * DH;
    const float* vbase = vd + (size_t)(b * HH + h) * LL * DH;
    const float* pbase = pd + (size_t)h * LL * DH;

    const int i = I0 + tid;

    // v_bias for this head, in registers (reused for all qvs fills)
    float vbh[DH];
#pragma unroll
    for (int c = 0; c < DH; c++) vbh[c] = vb[h * DH + c];

    // q + u_bias in registers
    float qu[DH];
#pragma unroll
    for (int c = 0; c < DH; c++) qu[c] = qbase[(size_t)i * DH + c] + ub[h * DH + c];

    // q + v_bias rows I0..I0+TI in shared (row I0+TI needed for the r>=2 branch).
    // float4 staging: 8 vec4 per row, (TI+1)*8 = 1032 vec4 total.
    for (int idx = tid; idx < (TI + 1) * 8; idx += 128) {
        int rrow = idx >> 3, c4 = idx & 7;
        int g = I0 + rrow;
        float4 qv;
        if (g < LL) {
            qv = *(const float4*)(qbase + (size_t)g * DH + c4 * 4);
            qv.x += vbh[c4 * 4 + 0]; qv.y += vbh[c4 * 4 + 1];
            qv.z += vbh[c4 * 4 + 2]; qv.w += vbh[c4 * 4 + 3];
        } else {
            qv = make_float4(0.f, 0.f, 0.f, 0.f);
        }
        qvs[rrow][c4 * 4 + 0] = qv.x;
        qvs[rrow][c4 * 4 + 1] = qv.y;
        qvs[rrow][c4 * 4 + 2] = qv.z;
        qvs[rrow][c4 * 4 + 3] = qv.w;
    }

    float acc[DH];
#pragma unroll
    for (int c = 0; c < DH; c++) acc[c] = 0.f;
    float rmax = -INFINITY, rsum = 0.f;

    for (int J0 = 0; J0 < LL; J0 += TJ) {
        __syncthreads();
        // K / V tile: TJ*8 = 256 vec4 each; thread handles 2 vec4 per array
        {
            int jr = tid >> 3, c4 = tid & 7;           // 16 rows covered
            *(float4*)&Ks[jr][c4 * 4]      = *(const float4*)(kbase + (size_t)(J0 + jr) * DH + c4 * 4);
            *(float4*)&Ks[jr + 16][c4 * 4] = *(const float4*)(kbase + (size_t)(J0 + jr + 16) * DH + c4 * 4);
            *(float4*)&Vs[jr][c4 * 4]      = *(const float4*)(vbase + (size_t)(J0 + jr) * DH + c4 * 4);
            *(float4*)&Vs[jr + 16][c4 * 4] = *(const float4*)(vbase + (size_t)(J0 + jr + 16) * DH + c4 * 4);
        }
        // p band indexed by rr = r - rmin, rmin = J0 - I0 - (TI-1); PBW*8 = 1272 vec4
        for (int idx = tid; idx < PBW * 8; idx += 128) {
            int rr = idx >> 3, c4 = idx & 7;
            int r = rr + J0 - I0 - (TI - 1);
            float4 pv = make_float4(0.f, 0.f, 0.f, 0.f);
            if (r <= 0)      pv = *(const float4*)(pbase + (size_t)(LL - 1 + r) * DH + c4 * 4);
            else if (r >= 2) pv = *(const float4*)(pbase + (size_t)(r - 2) * DH + c4 * 4);
            pband[rr][c4 * 4 + 0] = pv.x;  // r==1 stays 0
            pband[rr][c4 * 4 + 1] = pv.y;
            pband[rr][c4 * 4 + 2] = pv.z;
            pband[rr][c4 * 4 + 3] = pv.w;
        }
        __syncthreads();

#pragma unroll 4
        for (int jj = 0; jj < TJ; jj++) {
            const int r  = J0 + jj - i;
            const int rr = jj + (TI - 1) - tid;       // in [0, PBW)
            const float* qrow = qvs[tid + (r >= 1)];  // i or i+1
            const float* prow = pband[rr];
            const float* krow = Ks[jj];
            float s = 0.f, sp = 0.f;
#pragma unroll
            for (int c = 0; c < DH; c++) {
                s  += qu[c]   * krow[c];
                sp += qrow[c] * prow[c];
            }
            s = (s + sp) * SCALE;

            if (s > rmax) {
                float corr = __expf(rmax - s);  // first iter: exp(-inf)=0
                rsum *= corr;
#pragma unroll
                for (int c = 0; c < DH; c++) acc[c] *= corr;
                rmax = s;
            }
            float w = __expf(s - rmax);
            rsum += w;
            const float* vrow = Vs[jj];
#pragma unroll
            for (int c = 0; c < DH; c++) acc[c] += w * vrow[c];
        }
    }

    const float inv = 1.f / rsum;
    float* obase = ctx + (size_t)(b * HH + h) * LL * DH;
#pragma unroll
    for (int c = 0; c < DH; c += 4) {
        float4 o = make_float4(acc[c] * inv, acc[c + 1] * inv, acc[c + 2] * inv, acc[c + 3] * inv);
        *(float4*)(obase + (size_t)i * DH + c) = o;
    }
}

// ---------------------------------------------------------------------------
extern "C" void kernel_launch(void* const* d_in, const int* in_sizes, int n_in,
                              void* d_out, int out_size)
{
    const float* query = (const float*)d_in[0];
    const float* key   = (const float*)d_in[1];
    const float* value = (const float*)d_in[2];
    const float* pos   = (const float*)d_in[3];
    const float* Wq    = (const float*)d_in[4];
    const float* bq    = (const float*)d_in[5];
    const float* Wk    = (const float*)d_in[6];
    const float* bk    = (const float*)d_in[7];
    const float* Wv    = (const float*)d_in[8];
    const float* bv    = (const float*)d_in[9];
    const float* Wp    = (const float*)d_in[10];
    const float* ub    = (const float*)d_in[11];
    const float* vb    = (const float*)d_in[12];
    const float* Wo    = (const float*)d_in[13];
    const float* bo    = (const float*)d_in[14];

    float *pq, *pk, *pv, *pp, *pctx;
    cudaGetSymbolAddress((void**)&pq,   g_q);
    cudaGetSymbolAddress((void**)&pk,   g_k);
    cudaGetSymbolAddress((void**)&pv,   g_v);
    cudaGetSymbolAddress((void**)&pp,   g_p);
    cudaGetSymbolAddress((void**)&pctx, g_ctx);

    dim3 gblk(DM / GBN, (BB * LL) / GBM);   // (8, 32)
    dim3 gblkP(DM / GBN, LL / GBM);         // (8, 16)

    // Projections: heads layout outputs
    gemm512<<<gblk,  256>>>(query, Wq, bq,      pq,   BB * LL, 0, 1);
    gemm512<<<gblk,  256>>>(key,   Wk, bk,      pk,   BB * LL, 0, 1);
    gemm512<<<gblk,  256>>>(value, Wv, bv,      pv,   BB * LL, 0, 1);
    gemm512<<<gblkP, 256>>>(pos,   Wp, nullptr, pp,   LL,      0, 1);

    // Fused attention
    attn_kernel<<<dim3(LL / TI, HH, BB), 128>>>(pq, pk, pv, pp, ub, vb, pctx);

    // Output projection: ctx (head layout) @ Wo^T + bo -> plain [B*L, 512]
    gemm512<<<gblk, 256>>>(pctx, Wo, bo, (float*)d_out, BB * LL, 1, 0);
}

// round 3
// speedup vs baseline: 1.1019x; 1.1019x over previous
#include <cuda_runtime.h>
#include <math.h>
#include <stdint.h>

#define BB 2
#define LL 2048
#define HH 16
#define DH 32
#define DM 512
#define SCALE 0.044194173824159216f  /* 1/sqrt(512) */

// Scratch (allowed: __device__ globals, no runtime allocation)
__device__ float g_q[BB*HH*LL*DH];
__device__ float g_k[BB*HH*LL*DH];
__device__ float g_v[BB*HH*LL*DH];
__device__ float g_p[HH*LL*DH];
__device__ float g_ctx[BB*HH*LL*DH];

// ---------------------------------------------------------------------------
// GEMM: C[m,n] = sum_k A[m,k] * W[n,k] + bias[n],  K = N = 512  (unchanged)
// ---------------------------------------------------------------------------
#define GBM 128
#define GBN 64
#define GBK 16

__global__ __launch_bounds__(256, 3)
void gemm512(const float* __restrict__ A, const float* __restrict__ W,
             const float* __restrict__ bias, float* __restrict__ C,
             int M, int amode, int omode)
{
    __shared__ float As[GBK][GBM + 4];
    __shared__ float Ws[GBK][GBN + 4];

    const int m0 = blockIdx.y * GBM;
    const int n0 = blockIdx.x * GBN;
    const int tid = threadIdx.x;
    const int tx = tid & 15;
    const int ty = tid >> 4;

    float acc[8][4];
#pragma unroll
    for (int i = 0; i < 8; i++)
#pragma unroll
        for (int j = 0; j < 4; j++) acc[i][j] = 0.f;

    for (int k0 = 0; k0 < DM; k0 += GBK) {
#pragma unroll
        for (int t = 0; t < 8; t++) {
            int idx = tid + t * 256;
            int m = idx >> 4, k = idx & 15;
            int gm = m0 + m;
            int e  = k0 + k;
            float av;
            if (amode == 0) {
                av = A[(size_t)gm * DM + e];
            } else {
                int b = gm / LL, l = gm % LL;
                av = A[(((size_t)b * HH + (e >> 5)) * LL + l) * DH + (e & 31)];
            }
            As[k][m] = av;
        }
#pragma unroll
        for (int t = 0; t < 4; t++) {
            int idx = tid + t * 256;
            int n = idx >> 4, k = idx & 15;
            Ws[k][n] = W[(size_t)(n0 + n) * DM + k0 + k];
        }
        __syncthreads();

#pragma unroll
        for (int kk = 0; kk < GBK; kk++) {
            float a[8], b[4];
#pragma unroll
            for (int i = 0; i < 8; i++) a[i] = As[kk][ty * 8 + i];
#pragma unroll
            for (int j = 0; j < 4; j++) b[j] = Ws[kk][tx * 4 + j];
#pragma unroll
            for (int i = 0; i < 8; i++)
#pragma unroll
                for (int j = 0; j < 4; j++) acc[i][j] += a[i] * b[j];
        }
        __syncthreads();
    }

#pragma unroll
    for (int i = 0; i < 8; i++) {
        int m = m0 + ty * 8 + i;
#pragma unroll
        for (int j = 0; j < 4; j++) {
            int n = n0 + tx * 4 + j;
            float val = acc[i][j] + (bias ? bias[n] : 0.f);
            if (omode == 0) {
                C[(size_t)m * DM + n] = val;
            } else {
                int b = m / LL, l = m % LL;
                C[(((size_t)b * HH + (n >> 5)) * LL + l) * DH + (n & 31)] = val;
            }
        }
    }
}

// ---------------------------------------------------------------------------
// MMA-based fused attention with Transformer-XL relative shift.
// TI=64 query rows per block, TJ=32 keys per step, 4 warps (128 threads).
//  - S_c (64x32) = Qu @ K^T           via mma.m16n8k8.tf32
//  - W   (64x96) = Qv @ Pband^T       via mma.m16n8k8.tf32 (+1 scalar row)
//  - epilogue: 2 threads per row (16 dh channels each), online softmax + PV
// Shift: r=j-i;  r<=0 -> p[L-1+r];  r==1 -> 0;  r>=2 -> row i+1, p[r-2]
// ---------------------------------------------------------------------------
#define TI 64
#define TJ 32
#define PBR 96          /* band rows staged (need 95, pad to 96) */
#define QSTR 36
#define SSTR 34
#define WSTR 98

#define SQU_OFF 0
#define SQV_OFF (SQU_OFF + TI * QSTR)          /* 2304  */
#define SK_OFF  (SQV_OFF + (TI + 1) * QSTR)    /* 4644  */
#define SV_OFF  (SK_OFF + TJ * QSTR)           /* 5796  */
#define SP_OFF  (SV_OFF + TJ * QSTR)           /* 6948  */
#define SS_OFF  (SP_OFF + PBR * QSTR)          /* 10404 */
#define SW_OFF  (SS_OFF + TI * SSTR)           /* 12580 */
#define SMEM_FLOATS (SW_OFF + (TI + 1) * WSTR) /* 18950 */
#define SMEM_BYTES (SMEM_FLOATS * 4)           /* 75800 */

__device__ __forceinline__ uint32_t f2tf(float x) {
    uint32_t u;
    asm("cvt.rna.tf32.f32 %0, %1;" : "=r"(u) : "f"(x));
    return u;
}

__device__ __forceinline__ void mma_tf32(float& d0, float& d1, float& d2, float& d3,
                                         uint32_t a0, uint32_t a1, uint32_t a2, uint32_t a3,
                                         uint32_t b0, uint32_t b1) {
    asm volatile(
        "mma.sync.aligned.m16n8k8.row.col.f32.tf32.tf32.f32 "
        "{%0,%1,%2,%3}, {%4,%5,%6,%7}, {%8,%9}, {%0,%1,%2,%3};\n"
        : "+f"(d0), "+f"(d1), "+f"(d2), "+f"(d3)
        : "r"(a0), "r"(a1), "r"(a2), "r"(a3), "r"(b0), "r"(b1));
}

__global__ __launch_bounds__(128)
void attn_mma(const float* __restrict__ qd, const float* __restrict__ kd,
              const float* __restrict__ vd, const float* __restrict__ pd,
              const float* __restrict__ ub, const float* __restrict__ vb,
              float* __restrict__ ctx)
{
    extern __shared__ float sm[];
    float* sQu = sm + SQU_OFF;
    float* sQv = sm + SQV_OFF;
    float* sK  = sm + SK_OFF;
    float* sV  = sm + SV_OFF;
    float* sP  = sm + SP_OFF;
    float* sS  = sm + SS_OFF;
    float* sW  = sm + SW_OFF;

    const int tid  = threadIdx.x;
    const int lane = tid & 31;
    const int warp = tid >> 5;
    const int I0 = blockIdx.x * TI;
    const int h = blockIdx.y, b = blockIdx.z;

    const float* qbase = qd + (size_t)(b * HH + h) * LL * DH;
    const float* kbase = kd + (size_t)(b * HH + h) * LL * DH;
    const float* vbase = vd + (size_t)(b * HH + h) * LL * DH;
    const float* pbase = pd + (size_t)h * LL * DH;

    // ---- stage Qu = q + u_bias (rows I0..I0+63), Qv = q + v_bias (rows I0..I0+64)
    for (int idx = tid; idx < TI * 8; idx += 128) {
        int row = idx >> 3, c4 = idx & 7;
        float4 q  = *(const float4*)(qbase + (size_t)(I0 + row) * DH + c4 * 4);
        float4 u4 = *(const float4*)(ub + h * DH + c4 * 4);
        float4 o = make_float4(q.x + u4.x, q.y + u4.y, q.z + u4.z, q.w + u4.w);
        *(float4*)&sQu[row * QSTR + c4 * 4] = o;
    }
    for (int idx = tid; idx < (TI + 1) * 8; idx += 128) {
        int row = idx >> 3, c4 = idx & 7;
        int g = I0 + row;
        float4 o = make_float4(0.f, 0.f, 0.f, 0.f);
        if (g < LL) {
            float4 q  = *(const float4*)(qbase + (size_t)g * DH + c4 * 4);
            float4 v4 = *(const float4*)(vb + h * DH + c4 * 4);
            o = make_float4(q.x + v4.x, q.y + v4.y, q.z + v4.z, q.w + v4.w);
        }
        *(float4*)&sQv[row * QSTR + c4 * 4] = o;
    }
    __syncthreads();

    // ---- hoist A fragments (constant per block): warp w covers rows 16w..16w+15
    const int ar = 16 * warp + (lane >> 2);
    const int ac = lane & 3;
    uint32_t au[4][4], av[4][4];
#pragma unroll
    for (int kt = 0; kt < 4; kt++) {
        int c = kt * 8 + ac;
        au[kt][0] = f2tf(sQu[ar * QSTR + c]);
        au[kt][1] = f2tf(sQu[(ar + 8) * QSTR + c]);
        au[kt][2] = f2tf(sQu[ar * QSTR + c + 4]);
        au[kt][3] = f2tf(sQu[(ar + 8) * QSTR + c + 4]);
        av[kt][0] = f2tf(sQv[ar * QSTR + c]);
        av[kt][1] = f2tf(sQv[(ar + 8) * QSTR + c]);
        av[kt][2] = f2tf(sQv[ar * QSTR + c + 4]);
        av[kt][3] = f2tf(sQv[(ar + 8) * QSTR + c + 4]);
    }

    // ---- epilogue thread mapping: 2 threads per query row
    const int ii  = tid >> 1;
    const int ch0 = (tid & 1) * 16;
    const int qi  = I0 + ii;

    float acc[16];
#pragma unroll
    for (int c = 0; c < 16; c++) acc[c] = 0.f;
    float rmax = -INFINITY, rsum = 0.f;

    for (int J0 = 0; J0 < LL; J0 += TJ) {
        __syncthreads();  // previous epilogue done

        // stage K, V (TJ=32 rows x 8 float4)
        for (int idx = tid; idx < TJ * 8; idx += 128) {
            int row = idx >> 3, c4 = idx & 7;
            *(float4*)&sK[row * QSTR + c4 * 4] =
                *(const float4*)(kbase + (size_t)(J0 + row) * DH + c4 * 4);
            *(float4*)&sV[row * QSTR + c4 * 4] =
                *(const float4*)(vbase + (size_t)(J0 + row) * DH + c4 * 4);
        }
        // stage P band: rr <-> r = rr + rmin, rmin = J0-I0-(TI-1)
        const int rmin = J0 - I0 - (TI - 1);
        for (int idx = tid; idx < PBR * 8; idx += 128) {
            int rr = idx >> 3, c4 = idx & 7;
            int r = rr + rmin;
            float4 pv = make_float4(0.f, 0.f, 0.f, 0.f);
            if (r <= 0)      pv = *(const float4*)(pbase + (size_t)(LL - 1 + r) * DH + c4 * 4);
            else if (r >= 2 && r <= LL + 1)
                             pv = *(const float4*)(pbase + (size_t)(r - 2) * DH + c4 * 4);
            *(float4*)&sP[rr * QSTR + c4 * 4] = pv;   // r==1 stays zero
        }
        __syncthreads();

        // ---- content mma: S_c (64x32)
#pragma unroll
        for (int nt = 0; nt < 4; nt++) {
            float d0 = 0.f, d1 = 0.f, d2 = 0.f, d3 = 0.f;
#pragma unroll
            for (int kt = 0; kt < 4; kt++) {
                int bn = nt * 8 + (lane >> 2);
                int bk = kt * 8 + (lane & 3);
                uint32_t b0 = f2tf(sK[bn * QSTR + bk]);
                uint32_t b1 = f2tf(sK[bn * QSTR + bk + 4]);
                mma_tf32(d0, d1, d2, d3, au[kt][0], au[kt][1], au[kt][2], au[kt][3], b0, b1);
            }
            int sr = 16 * warp + (lane >> 2);
            int sc = nt * 8 + 2 * (lane & 3);
            *(float2*)&sS[sr * SSTR + sc]       = make_float2(d0, d1);
            *(float2*)&sS[(sr + 8) * SSTR + sc] = make_float2(d2, d3);
        }
        // ---- band mma: W (64x96)
#pragma unroll
        for (int nt = 0; nt < 12; nt++) {
            float d0 = 0.f, d1 = 0.f, d2 = 0.f, d3 = 0.f;
#pragma unroll
            for (int kt = 0; kt < 4; kt++) {
                int bn = nt * 8 + (lane >> 2);
                int bk = kt * 8 + (lane & 3);
                uint32_t b0 = f2tf(sP[bn * QSTR + bk]);
                uint32_t b1 = f2tf(sP[bn * QSTR + bk + 4]);
                mma_tf32(d0, d1, d2, d3, av[kt][0], av[kt][1], av[kt][2], av[kt][3], b0, b1);
            }
            int wr = 16 * warp + (lane >> 2);
            int wc = nt * 8 + 2 * (lane & 3);
            *(float2*)&sW[wr * WSTR + wc]       = make_float2(d0, d1);
            *(float2*)&sW[(wr + 8) * WSTR + wc] = make_float2(d2, d3);
        }
        // ---- extra W row (Qv row 64), only rr<TJ ever gathered from row 64
        if (tid < TJ) {
            float s = 0.f;
#pragma unroll
            for (int c = 0; c < DH; c++) s += sQv[TI * QSTR + c] * sP[tid * QSTR + c];
            sW[TI * WSTR + tid] = s;
        }
        __syncthreads();

        // ---- epilogue: online softmax + PV (fp32)
#pragma unroll 4
        for (int jj = 0; jj < TJ; jj++) {
            int r    = J0 + jj - qi;
            int rr   = jj + (TI - 1) - ii;
            int wrow = ii + (r >= 1);
            float s = (sS[ii * SSTR + jj] + sW[wrow * WSTR + rr]) * SCALE;

            if (s > rmax) {
                float corr = __expf(rmax - s);   // first iter: exp(-inf)=0
                rsum *= corr;
#pragma unroll
                for (int c = 0; c < 16; c++) acc[c] *= corr;
                rmax = s;
            }
            float w = __expf(s - rmax);
            rsum += w;
            const float4* vr = (const float4*)&sV[jj * QSTR + ch0];
            float4 v0 = vr[0], v1 = vr[1], v2 = vr[2], v3 = vr[3];
            acc[0]  += w * v0.x;  acc[1]  += w * v0.y;  acc[2]  += w * v0.z;  acc[3]  += w * v0.w;
            acc[4]  += w * v1.x;  acc[5]  += w * v1.y;  acc[6]  += w * v1.z;  acc[7]  += w * v1.w;
            acc[8]  += w * v2.x;  acc[9]  += w * v2.y;  acc[10] += w * v2.z;  acc[11] += w * v2.w;
            acc[12] += w * v3.x;  acc[13] += w * v3.y;  acc[14] += w * v3.z;  acc[15] += w * v3.w;
        }
    }

    const float inv = 1.f / rsum;
    float* obase = ctx + (size_t)(b * HH + h) * LL * DH + (size_t)qi * DH + ch0;
    float4 o0 = make_float4(acc[0] * inv,  acc[1] * inv,  acc[2] * inv,  acc[3] * inv);
    float4 o1 = make_float4(acc[4] * inv,  acc[5] * inv,  acc[6] * inv,  acc[7] * inv);
    float4 o2 = make_float4(acc[8] * inv,  acc[9] * inv,  acc[10] * inv, acc[11] * inv);
    float4 o3 = make_float4(acc[12] * inv, acc[13] * inv, acc[14] * inv, acc[15] * inv);
    ((float4*)obase)[0] = o0;
    ((float4*)obase)[1] = o1;
    ((float4*)obase)[2] = o2;
    ((float4*)obase)[3] = o3;
}

// ---------------------------------------------------------------------------
extern "C" void kernel_launch(void* const* d_in, const int* in_sizes, int n_in,
                              void* d_out, int out_size)
{
    const float* query = (const float*)d_in[0];
    const float* key   = (const float*)d_in[1];
    const float* value = (const float*)d_in[2];
    const float* pos   = (const float*)d_in[3];
    const float* Wq    = (const float*)d_in[4];
    const float* bq    = (const float*)d_in[5];
    const float* Wk    = (const float*)d_in[6];
    const float* bk    = (const float*)d_in[7];
    const float* Wv    = (const float*)d_in[8];
    const float* bv    = (const float*)d_in[9];
    const float* Wp    = (const float*)d_in[10];
    const float* ub    = (const float*)d_in[11];
    const float* vb    = (const float*)d_in[12];
    const float* Wo    = (const float*)d_in[13];
    const float* bo    = (const float*)d_in[14];

    float *pq, *pk, *pv, *pp, *pctx;
    cudaGetSymbolAddress((void**)&pq,   g_q);
    cudaGetSymbolAddress((void**)&pk,   g_k);
    cudaGetSymbolAddress((void**)&pv,   g_v);
    cudaGetSymbolAddress((void**)&pp,   g_p);
    cudaGetSymbolAddress((void**)&pctx, g_ctx);

    static int attr_set = 0;
    if (!attr_set) {
        cudaFuncSetAttribute(attn_mma, cudaFuncAttributeMaxDynamicSharedMemorySize, SMEM_BYTES);
        attr_set = 1;
    }

    dim3 gblk(DM / GBN, (BB * LL) / GBM);   // (8, 32)
    dim3 gblkP(DM / GBN, LL / GBM);         // (8, 16)

    // Projections: heads layout outputs
    gemm512<<<gblk,  256>>>(query, Wq, bq,      pq,   BB * LL, 0, 1);
    gemm512<<<gblk,  256>>>(key,   Wk, bk,      pk,   BB * LL, 0, 1);
    gemm512<<<gblk,  256>>>(value, Wv, bv,      pv,   BB * LL, 0, 1);
    gemm512<<<gblkP, 256>>>(pos,   Wp, nullptr, pp,   LL,      0, 1);

    // Fused attention (tensor-core scores + scalar online softmax/PV)
    attn_mma<<<dim3(LL / TI, HH, BB), 128, SMEM_BYTES>>>(pq, pk, pv, pp, ub, vb, pctx);

    // Output projection: ctx (head layout) @ Wo^T + bo -> plain [B*L, 512]
    gemm512<<<gblk, 256>>>(pctx, Wo, bo, (float*)d_out, BB * LL, 1, 0);
}

// round 5
// speedup vs baseline: 1.7172x; 1.5584x over previous
#include <cuda_runtime.h>
#include <math.h>
#include <stdint.h>

#define BB 2
#define LL 2048
#define HH 16
#define DH 32
#define DM 512
#define SCALE 0.044194173824159216f  /* 1/sqrt(512) */

__device__ float g_q[BB*HH*LL*DH];
__device__ float g_k[BB*HH*LL*DH];
__device__ float g_v[BB*HH*LL*DH];
__device__ float g_p[HH*LL*DH];
__device__ float g_ctx[BB*HH*LL*DH];

// ---------------------------------------------------------------------------
// GEMM (unchanged): C[m,n] = sum_k A[m,k] * W[n,k] + bias[n]
// ---------------------------------------------------------------------------
#define GBM 128
#define GBN 64
#define GBK 16

__global__ __launch_bounds__(256, 3)
void gemm512(const float* __restrict__ A, const float* __restrict__ W,
             const float* __restrict__ bias, float* __restrict__ C,
             int M, int amode, int omode)
{
    __shared__ float As[GBK][GBM + 4];
    __shared__ float Ws[GBK][GBN + 4];

    const int m0 = blockIdx.y * GBM;
    const int n0 = blockIdx.x * GBN;
    const int tid = threadIdx.x;
    const int tx = tid & 15;
    const int ty = tid >> 4;

    float acc[8][4];
#pragma unroll
    for (int i = 0; i < 8; i++)
#pragma unroll
        for (int j = 0; j < 4; j++) acc[i][j] = 0.f;

    for (int k0 = 0; k0 < DM; k0 += GBK) {
#pragma unroll
        for (int t = 0; t < 8; t++) {
            int idx = tid + t * 256;
            int m = idx >> 4, k = idx & 15;
            int gm = m0 + m;
            int e  = k0 + k;
            float av;
            if (amode == 0) {
                av = A[(size_t)gm * DM + e];
            } else {
                int b = gm / LL, l = gm % LL;
                av = A[(((size_t)b * HH + (e >> 5)) * LL + l) * DH + (e & 31)];
            }
            As[k][m] = av;
        }
#pragma unroll
        for (int t = 0; t < 4; t++) {
            int idx = tid + t * 256;
            int n = idx >> 4, k = idx & 15;
            Ws[k][n] = W[(size_t)(n0 + n) * DM + k0 + k];
        }
        __syncthreads();

#pragma unroll
        for (int kk = 0; kk < GBK; kk++) {
            float a[8], b[4];
#pragma unroll
            for (int i = 0; i < 8; i++) a[i] = As[kk][ty * 8 + i];
#pragma unroll
            for (int j = 0; j < 4; j++) b[j] = Ws[kk][tx * 4 + j];
#pragma unroll
            for (int i = 0; i < 8; i++)
#pragma unroll
                for (int j = 0; j < 4; j++) acc[i][j] += a[i] * b[j];
        }
        __syncthreads();
    }

#pragma unroll
    for (int i = 0; i < 8; i++) {
        int m = m0 + ty * 8 + i;
#pragma unroll
        for (int j = 0; j < 4; j++) {
            int n = n0 + tx * 4 + j;
            float val = acc[i][j] + (bias ? bias[n] : 0.f);
            if (omode == 0) {
                C[(size_t)m * DM + n] = val;
            } else {
                int b = m / LL, l = m % LL;
                C[(((size_t)b * HH + (n >> 5)) * LL + l) * DH + (n & 31)] = val;
            }
        }
    }
}

// ---------------------------------------------------------------------------
// Ring-band MMA attention. TI=64 rows/block, TJ=64 keys/tile, 256 threads.
// Warps 0-3: content S = Qu@K^T (64x64).  Warps 4-7: band W (new 64 r-cols).
// W[row][r] = Qv[row] . pshift(r) is computed ONCE per column (ring of 128).
// Shift: r=j-i; r<=0 -> p[L-1+r]; r==1 -> 0; r>=2 -> row i+1 uses p[r-2]
//        (epilogue reads W[ii + (r>=1)][slot(r)], extra row 64 handles wrap)
// ---------------------------------------------------------------------------
#define TI 64
#define TJ 64
#define QSTR 36
#define SSTR 68
#define WSTR 132
#define RING 128

#define SQU_OFF 0
#define SQV_OFF (SQU_OFF + TI * QSTR)             /* 2304  */
#define SK_OFF  (SQV_OFF + (TI + 1) * QSTR)       /* 4644  */
#define SV_OFF  (SK_OFF + TJ * QSTR)              /* 6948  */
#define SP_OFF  (SV_OFF + TJ * QSTR)              /* 9252  */
#define SS_OFF  (SP_OFF + RING * QSTR)            /* 13860 */
#define SW_OFF  (SS_OFF + TI * SSTR)              /* 18212 */
#define SMEM_FLOATS (SW_OFF + (TI + 1) * WSTR)    /* 26792 */
#define SMEM_BYTES (SMEM_FLOATS * 4)              /* 107168 */

__device__ __forceinline__ void mma_tf32(float& d0, float& d1, float& d2, float& d3,
                                         uint32_t a0, uint32_t a1, uint32_t a2, uint32_t a3,
                                         uint32_t b0, uint32_t b1) {
    asm volatile(
        "mma.sync.aligned.m16n8k8.row.col.f32.tf32.tf32.f32 "
        "{%0,%1,%2,%3}, {%4,%5,%6,%7}, {%8,%9}, {%0,%1,%2,%3};\n"
        : "+f"(d0), "+f"(d1), "+f"(d2), "+f"(d3)
        : "r"(a0), "r"(a1), "r"(a2), "r"(a3), "r"(b0), "r"(b1));
}

__global__ __launch_bounds__(256)
void attn_mma(const float* __restrict__ qd, const float* __restrict__ kd,
              const float* __restrict__ vd, const float* __restrict__ pd,
              const float* __restrict__ ub, const float* __restrict__ vb,
              float* __restrict__ ctx)
{
    extern __shared__ float sm[];
    float* sQu = sm + SQU_OFF;
    float* sQv = sm + SQV_OFF;
    float* sK  = sm + SK_OFF;
    float* sV  = sm + SV_OFF;
    float* sP  = sm + SP_OFF;
    float* sS  = sm + SS_OFF;
    float* sW  = sm + SW_OFF;

    const int tid  = threadIdx.x;
    const int lane = tid & 31;
    const int warp = tid >> 5;
    const int I0 = blockIdx.x * TI;
    const int h = blockIdx.y, b = blockIdx.z;

    const float* qbase = qd + (size_t)(b * HH + h) * LL * DH;
    const float* kbase = kd + (size_t)(b * HH + h) * LL * DH;
    const float* vbase = vd + (size_t)(b * HH + h) * LL * DH;
    const float* pbase = pd + (size_t)h * LL * DH;

    // ---- stage Qu (64 rows) and Qv (65 rows)
    for (int idx = tid; idx < TI * 8; idx += 256) {
        int row = idx >> 3, c4 = idx & 7;
        float4 q  = *(const float4*)(qbase + (size_t)(I0 + row) * DH + c4 * 4);
        float4 u4 = *(const float4*)(ub + h * DH + c4 * 4);
        *(float4*)&sQu[row * QSTR + c4 * 4] =
            make_float4(q.x + u4.x, q.y + u4.y, q.z + u4.z, q.w + u4.w);
    }
    for (int idx = tid; idx < (TI + 1) * 8; idx += 256) {
        int row = idx >> 3, c4 = idx & 7;
        int g = I0 + row;
        float4 o = make_float4(0.f, 0.f, 0.f, 0.f);
        if (g < LL) {
            float4 q  = *(const float4*)(qbase + (size_t)g * DH + c4 * 4);
            float4 v4 = *(const float4*)(vb + h * DH + c4 * 4);
            o = make_float4(q.x + v4.x, q.y + v4.y, q.z + v4.z, q.w + v4.w);
        }
        *(float4*)&sQv[row * QSTR + c4 * 4] = o;
    }
    __syncthreads();

    // ---- hoist A fragments (raw fp32 bits as tf32)
    // content warps (0-3): rows 16*warp; band warps (4-7): rows 16*(warp-4)
    const int mwarp = warp & 3;
    const int ar = 16 * mwarp + (lane >> 2);
    const int ac = lane & 3;
    const float* aQ = (warp < 4) ? sQu : sQv;
    uint32_t afr[4][4];
#pragma unroll
    for (int kt = 0; kt < 4; kt++) {
        int c = kt * 8 + ac;
        afr[kt][0] = __float_as_uint(aQ[ar * QSTR + c]);
        afr[kt][1] = __float_as_uint(aQ[(ar + 8) * QSTR + c]);
        afr[kt][2] = __float_as_uint(aQ[ar * QSTR + c + 4]);
        afr[kt][3] = __float_as_uint(aQ[(ar + 8) * QSTR + c + 4]);
    }

    // ---- epilogue mapping: 4 threads per row, 8 channels each
    const int ii  = tid >> 2;
    const int ch0 = (tid & 3) * 8;
    const int qi  = I0 + ii;

    float acc[8];
#pragma unroll
    for (int c = 0; c < 8; c++) acc[c] = 0.f;
    float rmax = -INFINITY, rsum = 0.f;

    // =============== prologue: band columns r in [-I0-64, -I0-1] ===============
    {
        const int r0 = -I0 - 64;
        const int slotbase = (r0 + 4096) & (RING - 1);   // multiple of 64
        for (int idx = tid; idx < 64 * 8; idx += 256) {
            int t = idx >> 3, c4 = idx & 7;
            int r = r0 + t;
            int slot = slotbase + t;
            float4 pv = make_float4(0.f, 0.f, 0.f, 0.f);
            if (r <= 0) { if (r >= 1 - LL) pv = *(const float4*)(pbase + (size_t)(LL - 1 + r) * DH + c4 * 4); }
            else if (r >= 2 && r <= LL + 1) pv = *(const float4*)(pbase + (size_t)(r - 2) * DH + c4 * 4);
            *(float4*)&sP[slot * QSTR + c4 * 4] = pv;
        }
        __syncthreads();
        if (warp >= 4) {
#pragma unroll
            for (int nt = 0; nt < 8; nt++) {
                float d0 = 0.f, d1 = 0.f, d2 = 0.f, d3 = 0.f;
#pragma unroll
                for (int kt = 0; kt < 4; kt++) {
                    int bn = slotbase + nt * 8 + (lane >> 2);
                    int bk = kt * 8 + (lane & 3);
                    uint32_t b0 = __float_as_uint(sP[bn * QSTR + bk]);
                    uint32_t b1 = __float_as_uint(sP[bn * QSTR + bk + 4]);
                    mma_tf32(d0, d1, d2, d3, afr[kt][0], afr[kt][1], afr[kt][2], afr[kt][3], b0, b1);
                }
                int wr = 16 * mwarp + (lane >> 2);
                int wc = slotbase + nt * 8 + 2 * (lane & 3);
                *(float2*)&sW[wr * WSTR + wc]       = make_float2(d0, d1);
                *(float2*)&sW[(wr + 8) * WSTR + wc] = make_float2(d2, d3);
            }
        }
        if (tid >= 192) {  // extra row 64 (warps 6-7)
            int t = tid - 192;
            float s = 0.f;
#pragma unroll
            for (int c = 0; c < DH; c++) s += sQv[TI * QSTR + c] * sP[(slotbase + t) * QSTR + c];
            sW[TI * WSTR + slotbase + t] = s;
        }
    }

    // =============== main loop over key tiles ===============
    for (int J0 = 0; J0 < LL; J0 += TJ) {
        __syncthreads();   // prev epilogue / prologue done

        // stage K,V (64 rows) and new P columns r in [J0-I0, J0-I0+63]
        for (int idx = tid; idx < TJ * 8; idx += 256) {
            int row = idx >> 3, c4 = idx & 7;
            *(float4*)&sK[row * QSTR + c4 * 4] =
                *(const float4*)(kbase + (size_t)(J0 + row) * DH + c4 * 4);
            *(float4*)&sV[row * QSTR + c4 * 4] =
                *(const float4*)(vbase + (size_t)(J0 + row) * DH + c4 * 4);
        }
        const int r0 = J0 - I0;
        const int slotbase = (r0 + 4096) & (RING - 1);
        for (int idx = tid; idx < 64 * 8; idx += 256) {
            int t = idx >> 3, c4 = idx & 7;
            int r = r0 + t;
            int slot = slotbase + t;
            float4 pv = make_float4(0.f, 0.f, 0.f, 0.f);
            if (r <= 0) { if (r >= 1 - LL) pv = *(const float4*)(pbase + (size_t)(LL - 1 + r) * DH + c4 * 4); }
            else if (r >= 2 && r <= LL + 1) pv = *(const float4*)(pbase + (size_t)(r - 2) * DH + c4 * 4);
            *(float4*)&sP[slot * QSTR + c4 * 4] = pv;
        }
        __syncthreads();

        if (warp < 4) {
            // ---- content: S (64x64) = Qu @ K^T
#pragma unroll
            for (int nt = 0; nt < 8; nt++) {
                float d0 = 0.f, d1 = 0.f, d2 = 0.f, d3 = 0.f;
#pragma unroll
                for (int kt = 0; kt < 4; kt++) {
                    int bn = nt * 8 + (lane >> 2);
                    int bk = kt * 8 + (lane & 3);
                    uint32_t b0 = __float_as_uint(sK[bn * QSTR + bk]);
                    uint32_t b1 = __float_as_uint(sK[bn * QSTR + bk + 4]);
                    mma_tf32(d0, d1, d2, d3, afr[kt][0], afr[kt][1], afr[kt][2], afr[kt][3], b0, b1);
                }
                int sr = 16 * mwarp + (lane >> 2);
                int sc = nt * 8 + 2 * (lane & 3);
                *(float2*)&sS[sr * SSTR + sc]       = make_float2(d0, d1);
                *(float2*)&sS[(sr + 8) * SSTR + sc] = make_float2(d2, d3);
            }
        } else {
            // ---- band: 64 new W columns
#pragma unroll
            for (int nt = 0; nt < 8; nt++) {
                float d0 = 0.f, d1 = 0.f, d2 = 0.f, d3 = 0.f;
#pragma unroll
                for (int kt = 0; kt < 4; kt++) {
                    int bn = slotbase + nt * 8 + (lane >> 2);
                    int bk = kt * 8 + (lane & 3);
                    uint32_t b0 = __float_as_uint(sP[bn * QSTR + bk]);
                    uint32_t b1 = __float_as_uint(sP[bn * QSTR + bk + 4]);
                    mma_tf32(d0, d1, d2, d3, afr[kt][0], afr[kt][1], afr[kt][2], afr[kt][3], b0, b1);
                }
                int wr = 16 * mwarp + (lane >> 2);
                int wc = slotbase + nt * 8 + 2 * (lane & 3);
                *(float2*)&sW[wr * WSTR + wc]       = make_float2(d0, d1);
                *(float2*)&sW[(wr + 8) * WSTR + wc] = make_float2(d2, d3);
            }
        }
        if (tid >= 192) {  // extra row 64 for new columns
            int t = tid - 192;
            float s = 0.f;
#pragma unroll
            for (int c = 0; c < DH; c++) s += sQv[TI * QSTR + c] * sP[(slotbase + t) * QSTR + c];
            sW[TI * WSTR + slotbase + t] = s;
        }
        __syncthreads();

        // ---- epilogue: chunks of 16, amortized rescale
#pragma unroll
        for (int jc = 0; jc < TJ; jc += 16) {
            float sa[16];
#pragma unroll
            for (int k4 = 0; k4 < 4; k4++) {
                float4 s4 = *(const float4*)&sS[ii * SSTR + jc + k4 * 4];
                sa[k4 * 4 + 0] = s4.x; sa[k4 * 4 + 1] = s4.y;
                sa[k4 * 4 + 2] = s4.z; sa[k4 * 4 + 3] = s4.w;
            }
            float cmax = -INFINITY;
#pragma unroll
            for (int t = 0; t < 16; t++) {
                int jj = jc + t;
                int r = J0 + jj - qi;
                int slot = (r + 4096) & (RING - 1);
                int wrow = ii + (r >= 1);
                sa[t] = (sa[t] + sW[wrow * WSTR + slot]) * SCALE;
                cmax = fmaxf(cmax, sa[t]);
            }
            if (cmax > rmax) {
                float corr = __expf(rmax - cmax);   // first chunk: exp(-inf)=0
                rsum *= corr;
#pragma unroll
                for (int c = 0; c < 8; c++) acc[c] *= corr;
                rmax = cmax;
            }
#pragma unroll
            for (int t = 0; t < 16; t++) {
                float w = __expf(sa[t] - rmax);
                rsum += w;
                const float4* vr = (const float4*)&sV[(jc + t) * QSTR + ch0];
                float4 v0 = vr[0], v1 = vr[1];
                acc[0] += w * v0.x; acc[1] += w * v0.y; acc[2] += w * v0.z; acc[3] += w * v0.w;
                acc[4] += w * v1.x; acc[5] += w * v1.y; acc[6] += w * v1.z; acc[7] += w * v1.w;
            }
        }
    }

    const float inv = 1.f / rsum;
    float* obase = ctx + (size_t)(b * HH + h) * LL * DH + (size_t)qi * DH + ch0;
    ((float4*)obase)[0] = make_float4(acc[0] * inv, acc[1] * inv, acc[2] * inv, acc[3] * inv);
    ((float4*)obase)[1] = make_float4(acc[4] * inv, acc[5] * inv, acc[6] * inv, acc[7] * inv);
}

// ---------------------------------------------------------------------------
extern "C" void kernel_launch(void* const* d_in, const int* in_sizes, int n_in,
                              void* d_out, int out_size)
{
    const float* query = (const float*)d_in[0];
    const float* key   = (const float*)d_in[1];
    const float* value = (const float*)d_in[2];
    const float* pos   = (const float*)d_in[3];
    const float* Wq    = (const float*)d_in[4];
    const float* bq    = (const float*)d_in[5];
    const float* Wk    = (const float*)d_in[6];
    const float* bk    = (const float*)d_in[7];
    const float* Wv    = (const float*)d_in[8];
    const float* bv    = (const float*)d_in[9];
    const float* Wp    = (const float*)d_in[10];
    const float* ub    = (const float*)d_in[11];
    const float* vb    = (const float*)d_in[12];
    const float* Wo    = (const float*)d_in[13];
    const float* bo    = (const float*)d_in[14];

    float *pq, *pk, *pv, *pp, *pctx;
    cudaGetSymbolAddress((void**)&pq,   g_q);
    cudaGetSymbolAddress((void**)&pk,   g_k);
    cudaGetSymbolAddress((void**)&pv,   g_v);
    cudaGetSymbolAddress((void**)&pp,   g_p);
    cudaGetSymbolAddress((void**)&pctx, g_ctx);

    static int attr_set = 0;
    if (!attr_set) {
        cudaFuncSetAttribute(attn_mma, cudaFuncAttributeMaxDynamicSharedMemorySize, SMEM_BYTES);
        attr_set = 1;
    }

    dim3 gblk(DM / GBN, (BB * LL) / GBM);   // (8, 32)
    dim3 gblkP(DM / GBN, LL / GBM);         // (8, 16)

    gemm512<<<gblk,  256>>>(query, Wq, bq,      pq,   BB * LL, 0, 1);
    gemm512<<<gblk,  256>>>(key,   Wk, bk,      pk,   BB * LL, 0, 1);
    gemm512<<<gblk,  256>>>(value, Wv, bv,      pv,   BB * LL, 0, 1);
    gemm512<<<gblkP, 256>>>(pos,   Wp, nullptr, pp,   LL,      0, 1);

    attn_mma<<<dim3(LL / TI, HH, BB), 256, SMEM_BYTES>>>(pq, pk, pv, pp, ub, vb, pctx);

    gemm512<<<gblk, 256>>>(pctx, Wo, bo, (float*)d_out, BB * LL, 1, 0);
}

// round 7
// speedup vs baseline: 3.1565x; 1.8382x over previous
#include <cuda_runtime.h>
#include <math.h>
#include <stdint.h>

#define BB 2
#define LL 2048
#define HH 16
#define DH 32
#define DM 512
#define SCALE 0.044194173824159216f  /* 1/sqrt(512) */

__device__ float g_q[BB*HH*LL*DH];
__device__ float g_k[BB*HH*LL*DH];
__device__ float g_v[BB*HH*LL*DH];
__device__ float g_p[HH*LL*DH];
__device__ float g_ctx[BB*HH*LL*DH];

// round-to-nearest tf32 (returned as fp32 bit pattern; low 13 mantissa bits 0)
__device__ __forceinline__ float f2tf(float x) {
    uint32_t u;
    asm("cvt.rna.tf32.f32 %0, %1;" : "=r"(u) : "f"(x));
    return __uint_as_float(u);
}
__device__ __forceinline__ float4 f2tf4(float4 v) {
    return make_float4(f2tf(v.x), f2tf(v.y), f2tf(v.z), f2tf(v.w));
}

__device__ __forceinline__ void mma_tf32(float& d0, float& d1, float& d2, float& d3,
                                         uint32_t a0, uint32_t a1, uint32_t a2, uint32_t a3,
                                         uint32_t b0, uint32_t b1) {
    asm volatile(
        "mma.sync.aligned.m16n8k8.row.col.f32.tf32.tf32.f32 "
        "{%0,%1,%2,%3}, {%4,%5,%6,%7}, {%8,%9}, {%0,%1,%2,%3};\n"
        : "+f"(d0), "+f"(d1), "+f"(d2), "+f"(d3)
        : "r"(a0), "r"(a1), "r"(a2), "r"(a3), "r"(b0), "r"(b1));
}

// ---------------------------------------------------------------------------
// tf32 tensor-core GEMM: C[m,n] = sum_k A[m,k]*W[n,k] + bias[n], K=N=512.
// Operands rounded to tf32 (rna) at staging; MMA consumes raw bits.
// ---------------------------------------------------------------------------
#define TGM 128
#define TGN 64
#define TGK 32
#define GASTR 36
#define GBSTR 36

__global__ __launch_bounds__(256)
void gemm512_tc(const float* __restrict__ A, const float* __restrict__ W,
                const float* __restrict__ bias, float* __restrict__ C,
                int amode, int omode)
{
    __shared__ float As[TGM * GASTR];
    __shared__ float Bs[TGN * GBSTR];

    const int tid  = threadIdx.x;
    const int lane = tid & 31;
    const int warp = tid >> 5;
    const int g = lane >> 2;
    const int t = lane & 3;
    const int m0 = blockIdx.y * TGM;
    const int n0 = blockIdx.x * TGN;

    float acc[8][4];
#pragma unroll
    for (int nt = 0; nt < 8; nt++)
#pragma unroll
        for (int j = 0; j < 4; j++) acc[nt][j] = 0.f;

    for (int k0 = 0; k0 < DM; k0 += TGK) {
        // stage A tile 128x32 (4 float4/thread), rna-rounded to tf32
#pragma unroll
        for (int i = 0; i < 4; i++) {
            int idx = tid + i * 256;
            int row = idx >> 3, c4 = idx & 7;
            int gm = m0 + row;
            float4 v;
            if (amode == 0) {
                v = *(const float4*)(A + (size_t)gm * DM + k0 + c4 * 4);
            } else {
                int b = gm >> 11, l = gm & (LL - 1);
                int head = k0 >> 5;   // TGK=32 == DH, so one head per chunk
                v = *(const float4*)(A + (((size_t)b * HH + head) * LL + l) * DH + c4 * 4);
            }
            *(float4*)&As[row * GASTR + c4 * 4] = f2tf4(v);
        }
        // stage W tile 64x32 (2 float4/thread), rna-rounded
#pragma unroll
        for (int i = 0; i < 2; i++) {
            int idx = tid + i * 256;
            int row = idx >> 3, c4 = idx & 7;
            float4 v = *(const float4*)(W + (size_t)(n0 + row) * DM + k0 + c4 * 4);
            *(float4*)&Bs[row * GBSTR + c4 * 4] = f2tf4(v);
        }
        __syncthreads();

#pragma unroll
        for (int kt = 0; kt < 4; kt++) {
            int c  = kt * 8 + t;
            int ar = warp * 16 + g;
            uint32_t a0 = __float_as_uint(As[ar * GASTR + c]);
            uint32_t a1 = __float_as_uint(As[(ar + 8) * GASTR + c]);
            uint32_t a2 = __float_as_uint(As[ar * GASTR + c + 4]);
            uint32_t a3 = __float_as_uint(As[(ar + 8) * GASTR + c + 4]);
#pragma unroll
            for (int nt = 0; nt < 8; nt++) {
                uint32_t b0 = __float_as_uint(Bs[(nt * 8 + g) * GBSTR + c]);
                uint32_t b1 = __float_as_uint(Bs[(nt * 8 + g) * GBSTR + c + 4]);
                mma_tf32(acc[nt][0], acc[nt][1], acc[nt][2], acc[nt][3],
                         a0, a1, a2, a3, b0, b1);
            }
        }
        __syncthreads();
    }

    const int sr = warp * 16 + g;
#pragma unroll
    for (int nt = 0; nt < 8; nt++) {
        int sc = nt * 8 + 2 * t;
        int n  = n0 + sc;
        float b0v = bias ? bias[n]     : 0.f;
        float b1v = bias ? bias[n + 1] : 0.f;
        float2 p0 = make_float2(acc[nt][0] + b0v, acc[nt][1] + b1v);
        float2 p1 = make_float2(acc[nt][2] + b0v, acc[nt][3] + b1v);
        if (omode == 0) {
            *(float2*)(C + (size_t)(m0 + sr) * DM + n)     = p0;
            *(float2*)(C + (size_t)(m0 + sr + 8) * DM + n) = p1;
        } else {
            int head = n >> 5, d = n & 31;
            int gm = m0 + sr;
            int b = gm >> 11, l = gm & (LL - 1);
            float* base = C + (((size_t)b * HH + head) * LL + l) * DH + d;
            *(float2*)(base)            = p0;
            *(float2*)(base + 8 * DH)   = p1;   // row +8, same batch (tile-aligned)
        }
    }
}

// ---------------------------------------------------------------------------
// Ring-band MMA attention + FA2-style tensor-core PV.
// TI=64 rows/block, TJ=64 keys/tile, 256 threads.
// All MMA operands rna-rounded to tf32 at staging.
// Shift: r=j-i; r<=0 -> p[L-1+r]; r==1 -> 0; r>=2 -> row i+1 uses p[r-2]
// ---------------------------------------------------------------------------
#define TI 64
#define TJ 64
#define QSTR 36
#define SSTR 68
#define WSTR 132
#define RING 128

#define SQU_OFF 0
#define SQV_OFF (SQU_OFF + TI * QSTR)             /* 2304  */
#define SK_OFF  (SQV_OFF + (TI + 1) * QSTR)       /* 4644  */
#define SV_OFF  (SK_OFF + TJ * QSTR)              /* 6948  */
#define SP_OFF  (SV_OFF + TJ * QSTR)              /* 9252  */
#define SS_OFF  (SP_OFF + RING * QSTR)            /* 13860 */
#define SW_OFF  (SS_OFF + TI * SSTR)              /* 18212 */
#define SC_OFF  (SW_OFF + (TI + 1) * WSTR)        /* 26792 */
#define SMEM_FLOATS (SC_OFF + TI)                 /* 26856 */
#define SMEM_BYTES (SMEM_FLOATS * 4)              /* 107424 */

__global__ __launch_bounds__(256, 2)
void attn_mma(const float* __restrict__ qd, const float* __restrict__ kd,
              const float* __restrict__ vd, const float* __restrict__ pd,
              const float* __restrict__ ub, const float* __restrict__ vb,
              float* __restrict__ ctx)
{
    extern __shared__ float sm[];
    float* sQu = sm + SQU_OFF;
    float* sQv = sm + SQV_OFF;
    float* sK  = sm + SK_OFF;
    float* sV  = sm + SV_OFF;
    float* sP  = sm + SP_OFF;
    float* sS  = sm + SS_OFF;    // scores, then in-place softmax weights P
    float* sW  = sm + SW_OFF;
    float* sCorr = sm + SC_OFF;

    const int tid  = threadIdx.x;
    const int lane = tid & 31;
    const int warp = tid >> 5;
    const int I0 = blockIdx.x * TI;
    const int h = blockIdx.y, b = blockIdx.z;

    const float* qbase = qd + (size_t)(b * HH + h) * LL * DH;
    const float* kbase = kd + (size_t)(b * HH + h) * LL * DH;
    const float* vbase = vd + (size_t)(b * HH + h) * LL * DH;
    const float* pbase = pd + (size_t)h * LL * DH;

    // ---- stage Qu (64 rows) and Qv (65 rows), rna-rounded
    for (int idx = tid; idx < TI * 8; idx += 256) {
        int row = idx >> 3, c4 = idx & 7;
        float4 q  = *(const float4*)(qbase + (size_t)(I0 + row) * DH + c4 * 4);
        float4 u4 = *(const float4*)(ub + h * DH + c4 * 4);
        *(float4*)&sQu[row * QSTR + c4 * 4] =
            f2tf4(make_float4(q.x + u4.x, q.y + u4.y, q.z + u4.z, q.w + u4.w));
    }
    for (int idx = tid; idx < (TI + 1) * 8; idx += 256) {
        int row = idx >> 3, c4 = idx & 7;
        int g = I0 + row;
        float4 o = make_float4(0.f, 0.f, 0.f, 0.f);
        if (g < LL) {
            float4 q  = *(const float4*)(qbase + (size_t)g * DH + c4 * 4);
            float4 v4 = *(const float4*)(vb + h * DH + c4 * 4);
            o = f2tf4(make_float4(q.x + v4.x, q.y + v4.y, q.z + v4.z, q.w + v4.w));
        }
        *(float4*)&sQv[row * QSTR + c4 * 4] = o;
    }
    __syncthreads();

    // ---- hoist score-MMA A fragments (pre-rounded bits)
    const int mwarp = warp & 3;
    const int ar = 16 * mwarp + (lane >> 2);
    const int ac = lane & 3;
    const float* aQ = (warp < 4) ? sQu : sQv;
    uint32_t afr[4][4];
#pragma unroll
    for (int kt = 0; kt < 4; kt++) {
        int c = kt * 8 + ac;
        afr[kt][0] = __float_as_uint(aQ[ar * QSTR + c]);
        afr[kt][1] = __float_as_uint(aQ[(ar + 8) * QSTR + c]);
        afr[kt][2] = __float_as_uint(aQ[ar * QSTR + c + 4]);
        afr[kt][3] = __float_as_uint(aQ[(ar + 8) * QSTR + c + 4]);
    }

    // ---- persistent PV accumulators: warp w -> rows 16*(w&3), channels (w>>2)*16
    const int nch0 = (warp >> 2) * 16;
    float dacc[2][4];
#pragma unroll
    for (int nt = 0; nt < 2; nt++)
#pragma unroll
        for (int j = 0; j < 4; j++) dacc[nt][j] = 0.f;

    // ---- softmax state (thread = (row, chunk))
    const int srow  = tid >> 2;
    const int schnk = tid & 3;
    float rmax = -INFINITY, rsum = 0.f;

    // =============== prologue: band columns r in [-I0-64, -I0-1] ===============
    {
        const int r0 = -I0 - 64;
        const int slotbase = (r0 + 4096) & (RING - 1);   // multiple of 64
        for (int idx = tid; idx < 64 * 8; idx += 256) {
            int t = idx >> 3, c4 = idx & 7;
            int r = r0 + t;
            int slot = slotbase + t;
            float4 pv = make_float4(0.f, 0.f, 0.f, 0.f);
            if (r <= 0) { if (r >= 1 - LL) pv = f2tf4(*(const float4*)(pbase + (size_t)(LL - 1 + r) * DH + c4 * 4)); }
            else if (r >= 2 && r <= LL + 1) pv = f2tf4(*(const float4*)(pbase + (size_t)(r - 2) * DH + c4 * 4));
            *(float4*)&sP[slot * QSTR + c4 * 4] = pv;
        }
        __syncthreads();
        if (warp >= 4) {
#pragma unroll
            for (int nt = 0; nt < 8; nt++) {
                float d0 = 0.f, d1 = 0.f, d2 = 0.f, d3 = 0.f;
#pragma unroll
                for (int kt = 0; kt < 4; kt++) {
                    int bn = slotbase + nt * 8 + (lane >> 2);
                    int bk = kt * 8 + (lane & 3);
                    uint32_t b0 = __float_as_uint(sP[bn * QSTR + bk]);
                    uint32_t b1 = __float_as_uint(sP[bn * QSTR + bk + 4]);
                    mma_tf32(d0, d1, d2, d3, afr[kt][0], afr[kt][1], afr[kt][2], afr[kt][3], b0, b1);
                }
                int wr = 16 * mwarp + (lane >> 2);
                int wc = slotbase + nt * 8 + 2 * (lane & 3);
                *(float2*)&sW[wr * WSTR + wc]       = make_float2(d0, d1);
                *(float2*)&sW[(wr + 8) * WSTR + wc] = make_float2(d2, d3);
            }
        }
        if (tid >= 192) {  // extra row 64 (warps 6-7)
            int t = tid - 192;
            float s = 0.f;
#pragma unroll
            for (int c = 0; c < DH; c++) s += sQv[TI * QSTR + c] * sP[(slotbase + t) * QSTR + c];
            sW[TI * WSTR + slotbase + t] = s;
        }
    }

    // =============== main loop over key tiles ===============
    for (int J0 = 0; J0 < LL; J0 += TJ) {
        __syncthreads();   // prev PV / prologue done

        // stage K,V (rounded) and new P ring columns r in [J0-I0, J0-I0+63]
        for (int idx = tid; idx < TJ * 8; idx += 256) {
            int row = idx >> 3, c4 = idx & 7;
            *(float4*)&sK[row * QSTR + c4 * 4] =
                f2tf4(*(const float4*)(kbase + (size_t)(J0 + row) * DH + c4 * 4));
            *(float4*)&sV[row * QSTR + c4 * 4] =
                f2tf4(*(const float4*)(vbase + (size_t)(J0 + row) * DH + c4 * 4));
        }
        const int r0 = J0 - I0;
        const int slotbase = (r0 + 4096) & (RING - 1);
        for (int idx = tid; idx < 64 * 8; idx += 256) {
            int t = idx >> 3, c4 = idx & 7;
            int r = r0 + t;
            int slot = slotbase + t;
            float4 pv = make_float4(0.f, 0.f, 0.f, 0.f);
            if (r <= 0) { if (r >= 1 - LL) pv = f2tf4(*(const float4*)(pbase + (size_t)(LL - 1 + r) * DH + c4 * 4)); }
            else if (r >= 2 && r <= LL + 1) pv = f2tf4(*(const float4*)(pbase + (size_t)(r - 2) * DH + c4 * 4));
            *(float4*)&sP[slot * QSTR + c4 * 4] = pv;
        }
        __syncthreads();

        if (warp < 4) {
            // ---- content: S (64x64) = Qu @ K^T
#pragma unroll
            for (int nt = 0; nt < 8; nt++) {
                float d0 = 0.f, d1 = 0.f, d2 = 0.f, d3 = 0.f;
#pragma unroll
                for (int kt = 0; kt < 4; kt++) {
                    int bn = nt * 8 + (lane >> 2);
                    int bk = kt * 8 + (lane & 3);
                    uint32_t b0 = __float_as_uint(sK[bn * QSTR + bk]);
                    uint32_t b1 = __float_as_uint(sK[bn * QSTR + bk + 4]);
                    mma_tf32(d0, d1, d2, d3, afr[kt][0], afr[kt][1], afr[kt][2], afr[kt][3], b0, b1);
                }
                int sr = 16 * mwarp + (lane >> 2);
                int sc = nt * 8 + 2 * (lane & 3);
                *(float2*)&sS[sr * SSTR + sc]       = make_float2(d0, d1);
                *(float2*)&sS[(sr + 8) * SSTR + sc] = make_float2(d2, d3);
            }
        } else {
            // ---- band: 64 new W columns
#pragma unroll
            for (int nt = 0; nt < 8; nt++) {
                float d0 = 0.f, d1 = 0.f, d2 = 0.f, d3 = 0.f;
#pragma unroll
                for (int kt = 0; kt < 4; kt++) {
                    int bn = slotbase + nt * 8 + (lane >> 2);
                    int bk = kt * 8 + (lane & 3);
                    uint32_t b0 = __float_as_uint(sP[bn * QSTR + bk]);
                    uint32_t b1 = __float_as_uint(sP[bn * QSTR + bk + 4]);
                    mma_tf32(d0, d1, d2, d3, afr[kt][0], afr[kt][1], afr[kt][2], afr[kt][3], b0, b1);
                }
                int wr = 16 * mwarp + (lane >> 2);
                int wc = slotbase + nt * 8 + 2 * (lane & 3);
                *(float2*)&sW[wr * WSTR + wc]       = make_float2(d0, d1);
                *(float2*)&sW[(wr + 8) * WSTR + wc] = make_float2(d2, d3);
            }
        }
        if (tid >= 192) {  // extra row 64 for new columns
            int t = tid - 192;
            float s = 0.f;
#pragma unroll
            for (int c = 0; c < DH; c++) s += sQv[TI * QSTR + c] * sP[(slotbase + t) * QSTR + c];
            sW[TI * WSTR + slotbase + t] = s;
        }
        __syncthreads();

        // ---- softmax phase: thread (srow, schnk) owns 16 columns, once
        {
            float s[16];
#pragma unroll
            for (int k4 = 0; k4 < 4; k4++) {
                float4 s4 = *(const float4*)&sS[srow * SSTR + schnk * 16 + k4 * 4];
                s[k4 * 4 + 0] = s4.x; s[k4 * 4 + 1] = s4.y;
                s[k4 * 4 + 2] = s4.z; s[k4 * 4 + 3] = s4.w;
            }
            const int qi = I0 + srow;
            float cmax = -INFINITY;
#pragma unroll
            for (int tt = 0; tt < 16; tt++) {
                int jj = schnk * 16 + tt;
                int r = J0 + jj - qi;
                int slot = (r + 4096) & (RING - 1);
                int wrow = srow + (r >= 1);
                s[tt] = (s[tt] + sW[wrow * WSTR + slot]) * SCALE;
                cmax = fmaxf(cmax, s[tt]);
            }
            cmax = fmaxf(cmax, __shfl_xor_sync(0xffffffffu, cmax, 1));
            cmax = fmaxf(cmax, __shfl_xor_sync(0xffffffffu, cmax, 2));
            float mnew = fmaxf(rmax, cmax);
            float corr = __expf(rmax - mnew);     // first tile: exp(-inf)=0
            float csum = 0.f;
#pragma unroll
            for (int tt = 0; tt < 16; tt++) {
                // rna-round weight to tf32 so rsum matches the P the MMA consumes
                float w = f2tf(__expf(s[tt] - mnew));
                s[tt] = w;
                csum += w;
            }
            csum += __shfl_xor_sync(0xffffffffu, csum, 1);
            csum += __shfl_xor_sync(0xffffffffu, csum, 2);
            rsum = rsum * corr + csum;
            rmax = mnew;
#pragma unroll
            for (int k4 = 0; k4 < 4; k4++)
                *(float4*)&sS[srow * SSTR + schnk * 16 + k4 * 4] =
                    make_float4(s[k4 * 4], s[k4 * 4 + 1], s[k4 * 4 + 2], s[k4 * 4 + 3]);
            if (schnk == 0) sCorr[srow] = corr;
        }
        __syncthreads();

        // ---- PV MMA: rescale fragments, then O += P @ V
        {
            const int prow = 16 * mwarp + (lane >> 2);
            float c0 = sCorr[prow];
            float c1 = sCorr[prow + 8];
#pragma unroll
            for (int nt = 0; nt < 2; nt++) {
                dacc[nt][0] *= c0; dacc[nt][1] *= c0;
                dacc[nt][2] *= c1; dacc[nt][3] *= c1;
            }
#pragma unroll
            for (int kt = 0; kt < 8; kt++) {
                int c = kt * 8 + (lane & 3);
                uint32_t a0 = __float_as_uint(sS[prow * SSTR + c]);
                uint32_t a1 = __float_as_uint(sS[(prow + 8) * SSTR + c]);
                uint32_t a2 = __float_as_uint(sS[prow * SSTR + c + 4]);
                uint32_t a3 = __float_as_uint(sS[(prow + 8) * SSTR + c + 4]);
#pragma unroll
                for (int nt = 0; nt < 2; nt++) {
                    int bn = nch0 + nt * 8 + (lane >> 2);
                    uint32_t b0 = __float_as_uint(sV[c * QSTR + bn]);
                    uint32_t b1 = __float_as_uint(sV[(c + 4) * QSTR + bn]);
                    mma_tf32(dacc[nt][0], dacc[nt][1], dacc[nt][2], dacc[nt][3],
                             a0, a1, a2, a3, b0, b1);
                }
            }
        }
    }

    // ---- finalize: 1/rsum per row, scale fragments, store
    __syncthreads();
    if (schnk == 0) sCorr[srow] = 1.f / rsum;
    __syncthreads();
    {
        const int prow = 16 * mwarp + (lane >> 2);
        float i0v = sCorr[prow];
        float i1v = sCorr[prow + 8];
        float* ob = ctx + (size_t)(b * HH + h) * LL * DH;
#pragma unroll
        for (int nt = 0; nt < 2; nt++) {
            int sc = nch0 + nt * 8 + 2 * (lane & 3);
            *(float2*)(ob + (size_t)(I0 + prow) * DH + sc) =
                make_float2(dacc[nt][0] * i0v, dacc[nt][1] * i0v);
            *(float2*)(ob + (size_t)(I0 + prow + 8) * DH + sc) =
                make_float2(dacc[nt][2] * i1v, dacc[nt][3] * i1v);
        }
    }
}

// ---------------------------------------------------------------------------
extern "C" void kernel_launch(void* const* d_in, const int* in_sizes, int n_in,
                              void* d_out, int out_size)
{
    const float* query = (const float*)d_in[0];
    const float* key   = (const float*)d_in[1];
    const float* value = (const float*)d_in[2];
    const float* pos   = (const float*)d_in[3];
    const float* Wq    = (const float*)d_in[4];
    const float* bq    = (const float*)d_in[5];
    const float* Wk    = (const float*)d_in[6];
    const float* bk    = (const float*)d_in[7];
    const float* Wv    = (const float*)d_in[8];
    const float* bv    = (const float*)d_in[9];
    const float* Wp    = (const float*)d_in[10];
    const float* ub    = (const float*)d_in[11];
    const float* vb    = (const float*)d_in[12];
    const float* Wo    = (const float*)d_in[13];
    const float* bo    = (const float*)d_in[14];

    float *pq, *pk, *pv, *pp, *pctx;
    cudaGetSymbolAddress((void**)&pq,   g_q);
    cudaGetSymbolAddress((void**)&pk,   g_k);
    cudaGetSymbolAddress((void**)&pv,   g_v);
    cudaGetSymbolAddress((void**)&pp,   g_p);
    cudaGetSymbolAddress((void**)&pctx, g_ctx);

    static int attr_set = 0;
    if (!attr_set) {
        cudaFuncSetAttribute(attn_mma, cudaFuncAttributeMaxDynamicSharedMemorySize, SMEM_BYTES);
        attr_set = 1;
    }

    dim3 gblk(DM / TGN, (BB * LL) / TGM);   // (8, 32)
    dim3 gblkP(DM / TGN, LL / TGM);         // (8, 16)

    gemm512_tc<<<gblk,  256>>>(query, Wq, bq,      pq, 0, 1);
    gemm512_tc<<<gblk,  256>>>(key,   Wk, bk,      pk, 0, 1);
    gemm512_tc<<<gblk,  256>>>(value, Wv, bv,      pv, 0, 1);
    gemm512_tc<<<gblkP, 256>>>(pos,   Wp, nullptr, pp, 0, 1);

    attn_mma<<<dim3(LL / TI, HH, BB), 256, SMEM_BYTES>>>(pq, pk, pv, pp, ub, vb, pctx);

    gemm512_tc<<<gblk, 256>>>(pctx, Wo, bo, (float*)d_out, 1, 0);
}

// round 8
// speedup vs baseline: 3.6166x; 1.1457x over previous
#include <cuda_runtime.h>
#include <math.h>
#include <stdint.h>

#define BB 2
#define LL 2048
#define HH 16
#define DH 32
#define DM 512
#define SCALE 0.044194173824159216f  /* 1/sqrt(512) */

__device__ float g_q[BB*HH*LL*DH];
__device__ float g_k[BB*HH*LL*DH];
__device__ float g_v[BB*HH*LL*DH];
__device__ float g_p[HH*LL*DH];
__device__ float g_ctx[BB*HH*LL*DH];

// round-to-nearest tf32, returned as raw bits for mma
__device__ __forceinline__ uint32_t f2tfu(float x) {
    uint32_t u;
    asm("cvt.rna.tf32.f32 %0, %1;" : "=r"(u) : "f"(x));
    return u;
}
__device__ __forceinline__ float f2tf(float x) { return __uint_as_float(f2tfu(x)); }
__device__ __forceinline__ float4 f2tf4(float4 v) {
    return make_float4(f2tf(v.x), f2tf(v.y), f2tf(v.z), f2tf(v.w));
}

__device__ __forceinline__ void mma_tf32(float& d0, float& d1, float& d2, float& d3,
                                         uint32_t a0, uint32_t a1, uint32_t a2, uint32_t a3,
                                         uint32_t b0, uint32_t b1) {
    asm volatile(
        "mma.sync.aligned.m16n8k8.row.col.f32.tf32.tf32.f32 "
        "{%0,%1,%2,%3}, {%4,%5,%6,%7}, {%8,%9}, {%0,%1,%2,%3};\n"
        : "+f"(d0), "+f"(d1), "+f"(d2), "+f"(d3)
        : "r"(a0), "r"(a1), "r"(a2), "r"(a3), "r"(b0), "r"(b1));
}

__device__ __forceinline__ void cp16(uint32_t dst, const void* src, int szbytes) {
    asm volatile("cp.async.cg.shared.global [%0], [%1], 16, %2;\n"
                 :: "r"(dst), "l"(src), "r"(szbytes));
}
__device__ __forceinline__ void cp_commit() {
    asm volatile("cp.async.commit_group;\n" ::: "memory");
}
__device__ __forceinline__ void cp_wait0() {
    asm volatile("cp.async.wait_group 0;\n" ::: "memory");
}

// ---------------------------------------------------------------------------
// tf32 GEMM core, cp.async double-buffered over 16 K-chunks.
// C[m,n] = sum_k A[m,k]*W[n,k] + bias[n].  rna rounding at consumption.
// ---------------------------------------------------------------------------
#define TGM 128
#define TGN 64
#define TGK 32
#define GASTR 36
#define GBSTR 36
#define GSMEM_FLOATS (2 * (TGM * GASTR + TGN * GBSTR))
#define GSMEM_BYTES (GSMEM_FLOATS * 4)   /* 55296 */

__device__ __forceinline__ void gemm_core(
    const float* __restrict__ A, const float* __restrict__ W,
    const float* __restrict__ bias, float* __restrict__ C,
    int amode, int omode, float* smem)
{
    const int tid  = threadIdx.x;
    const int lane = tid & 31;
    const int warp = tid >> 5;
    const int g = lane >> 2;
    const int t = lane & 3;
    const int m0 = blockIdx.y * TGM;
    const int n0 = blockIdx.x * TGN;

    float* As = smem;
    float* Bs = smem + 2 * TGM * GASTR;
    const uint32_t smb = (uint32_t)__cvta_generic_to_shared(smem);

    float acc[8][4];
#pragma unroll
    for (int nt = 0; nt < 8; nt++)
#pragma unroll
        for (int j = 0; j < 4; j++) acc[nt][j] = 0.f;

    auto issue = [&](int k0, int buf) {
#pragma unroll
        for (int i = 0; i < 4; i++) {
            int idx = tid + i * 256;
            int row = idx >> 3, c4 = idx & 7;
            int gm = m0 + row;
            const float* src;
            if (amode == 0) {
                src = A + (size_t)gm * DM + k0 + c4 * 4;
            } else {
                int b = gm >> 11, l = gm & (LL - 1);
                int head = k0 >> 5;
                src = A + (((size_t)b * HH + head) * LL + l) * DH + c4 * 4;
            }
            cp16(smb + (uint32_t)((buf * TGM * GASTR + row * GASTR + c4 * 4) * 4), src, 16);
        }
#pragma unroll
        for (int i = 0; i < 2; i++) {
            int idx = tid + i * 256;
            int row = idx >> 3, c4 = idx & 7;
            const float* src = W + (size_t)(n0 + row) * DM + k0 + c4 * 4;
            cp16(smb + (uint32_t)((2 * TGM * GASTR + buf * TGN * GBSTR + row * GBSTR + c4 * 4) * 4), src, 16);
        }
    };

    issue(0, 0);
    cp_commit();

    for (int c = 0; c < 16; c++) {
        cp_wait0();
        __syncthreads();
        if (c < 15) issue((c + 1) * TGK, (c + 1) & 1);
        cp_commit();

        const float* Ab = As + (c & 1) * TGM * GASTR;
        const float* Bb = Bs + (c & 1) * TGN * GBSTR;
#pragma unroll
        for (int kt = 0; kt < 4; kt++) {
            int cc = kt * 8 + t;
            int ar = warp * 16 + g;
            uint32_t a0 = f2tfu(Ab[ar * GASTR + cc]);
            uint32_t a1 = f2tfu(Ab[(ar + 8) * GASTR + cc]);
            uint32_t a2 = f2tfu(Ab[ar * GASTR + cc + 4]);
            uint32_t a3 = f2tfu(Ab[(ar + 8) * GASTR + cc + 4]);
#pragma unroll
            for (int nt = 0; nt < 8; nt++) {
                uint32_t b0 = f2tfu(Bb[(nt * 8 + g) * GBSTR + cc]);
                uint32_t b1 = f2tfu(Bb[(nt * 8 + g) * GBSTR + cc + 4]);
                mma_tf32(acc[nt][0], acc[nt][1], acc[nt][2], acc[nt][3],
                         a0, a1, a2, a3, b0, b1);
            }
        }
    }

    const int sr = warp * 16 + g;
#pragma unroll
    for (int nt = 0; nt < 8; nt++) {
        int sc = nt * 8 + 2 * t;
        int n  = n0 + sc;
        float b0v = bias ? bias[n]     : 0.f;
        float b1v = bias ? bias[n + 1] : 0.f;
        float2 p0 = make_float2(acc[nt][0] + b0v, acc[nt][1] + b1v);
        float2 p1 = make_float2(acc[nt][2] + b0v, acc[nt][3] + b1v);
        if (omode == 0) {
            *(float2*)(C + (size_t)(m0 + sr) * DM + n)     = p0;
            *(float2*)(C + (size_t)(m0 + sr + 8) * DM + n) = p1;
        } else {
            int head = n >> 5, d = n & 31;
            int gm = m0 + sr;
            int b = gm >> 11, l = gm & (LL - 1);
            float* base = C + (((size_t)b * HH + head) * LL + l) * DH + d;
            *(float2*)(base)          = p0;
            *(float2*)(base + 8 * DH) = p1;
        }
    }
}

__global__ __launch_bounds__(256)
void qkv_gemm(const float* __restrict__ q, const float* __restrict__ k,
              const float* __restrict__ v,
              const float* __restrict__ Wq, const float* __restrict__ Wk,
              const float* __restrict__ Wv,
              const float* __restrict__ bq, const float* __restrict__ bk,
              const float* __restrict__ bv,
              float* __restrict__ oq, float* __restrict__ ok, float* __restrict__ ov)
{
    extern __shared__ float smem[];
    int z = blockIdx.z;
    const float* A = (z == 0) ? q : (z == 1) ? k : v;
    const float* W = (z == 0) ? Wq : (z == 1) ? Wk : Wv;
    const float* b = (z == 0) ? bq : (z == 1) ? bk : bv;
    float* C = (z == 0) ? oq : (z == 1) ? ok : ov;
    gemm_core(A, W, b, C, 0, 1, smem);
}

__global__ __launch_bounds__(256)
void one_gemm(const float* __restrict__ A, const float* __restrict__ W,
              const float* __restrict__ bias, float* __restrict__ C,
              int amode, int omode)
{
    extern __shared__ float smem[];
    gemm_core(A, W, bias, C, amode, omode, smem);
}

// ---------------------------------------------------------------------------
// Ring-band MMA attention, cp.async double-buffered K/V/P.
// K/V buf1 reuses sQu / sQv[0..63] (dead after fragment hoist).
// sP = two 64-column buffers (band MMA only reads fresh columns; history in sW).
// Shift: r=j-i; r<=0 -> p[L-1+r]; r==1 -> 0; r>=2 -> row i+1 uses p[r-2]
// ---------------------------------------------------------------------------
#define TI 64
#define TJ 64
#define QSTR 36
#define SSTR 68
#define WSTR 132
#define RING 128

#define SQU_OFF 0
#define SQV_OFF (SQU_OFF + TI * QSTR)             /* 2304  */
#define SK_OFF  (SQV_OFF + (TI + 1) * QSTR)       /* 4644  */
#define SV_OFF  (SK_OFF + TJ * QSTR)              /* 6948  */
#define SP_OFF  (SV_OFF + TJ * QSTR)              /* 9252  */
#define SS_OFF  (SP_OFF + RING * QSTR)            /* 13860 */
#define SW_OFF  (SS_OFF + TI * SSTR)              /* 18212 */
#define SC_OFF  (SW_OFF + (TI + 1) * WSTR)        /* 26792 */
#define SMEM_FLOATS (SC_OFF + TI)                 /* 26856 */
#define SMEM_BYTES (SMEM_FLOATS * 4)              /* 107424 */

__global__ __launch_bounds__(256, 2)
void attn_mma(const float* __restrict__ qd, const float* __restrict__ kd,
              const float* __restrict__ vd, const float* __restrict__ pd,
              const float* __restrict__ ub, const float* __restrict__ vb,
              float* __restrict__ ctx)
{
    extern __shared__ float sm[];
    float* sS  = sm + SS_OFF;
    float* sW  = sm + SW_OFF;
    float* sCorr = sm + SC_OFF;
    const uint32_t smb = (uint32_t)__cvta_generic_to_shared(sm);

    const int tid  = threadIdx.x;
    const int lane = tid & 31;
    const int warp = tid >> 5;
    const int I0 = blockIdx.x * TI;
    const int h = blockIdx.y, b = blockIdx.z;

    const float* qbase = qd + (size_t)(b * HH + h) * LL * DH;
    const float* kbase = kd + (size_t)(b * HH + h) * LL * DH;
    const float* vbase = vd + (size_t)(b * HH + h) * LL * DH;
    const float* pbase = pd + (size_t)h * LL * DH;

    const int KbufOff[2] = {SK_OFF, SQU_OFF};
    const int VbufOff[2] = {SV_OFF, SQV_OFF};
    const int PbufOff[2] = {SP_OFF, SP_OFF + 64 * QSTR};

    // ---- stage Qu (64 rows) and Qv (65 rows), rna-rounded
    for (int idx = tid; idx < TI * 8; idx += 256) {
        int row = idx >> 3, c4 = idx & 7;
        float4 q  = *(const float4*)(qbase + (size_t)(I0 + row) * DH + c4 * 4);
        float4 u4 = *(const float4*)(ub + h * DH + c4 * 4);
        *(float4*)&sm[SQU_OFF + row * QSTR + c4 * 4] =
            f2tf4(make_float4(q.x + u4.x, q.y + u4.y, q.z + u4.z, q.w + u4.w));
    }
    for (int idx = tid; idx < (TI + 1) * 8; idx += 256) {
        int row = idx >> 3, c4 = idx & 7;
        int g = I0 + row;
        float4 o = make_float4(0.f, 0.f, 0.f, 0.f);
        if (g < LL) {
            float4 q  = *(const float4*)(qbase + (size_t)g * DH + c4 * 4);
            float4 v4 = *(const float4*)(vb + h * DH + c4 * 4);
            o = f2tf4(make_float4(q.x + v4.x, q.y + v4.y, q.z + v4.z, q.w + v4.w));
        }
        *(float4*)&sm[SQV_OFF + row * QSTR + c4 * 4] = o;
    }
    __syncthreads();

    // ---- hoist score-MMA A fragments (pre-rounded); sQu/sQv[0..63] dead after
    const int mwarp = warp & 3;
    const int ar = 16 * mwarp + (lane >> 2);
    const int ac = lane & 3;
    const float* aQ = (warp < 4) ? (sm + SQU_OFF) : (sm + SQV_OFF);
    uint32_t afr[4][4];
#pragma unroll
    for (int kt = 0; kt < 4; kt++) {
        int c = kt * 8 + ac;
        afr[kt][0] = __float_as_uint(aQ[ar * QSTR + c]);
        afr[kt][1] = __float_as_uint(aQ[(ar + 8) * QSTR + c]);
        afr[kt][2] = __float_as_uint(aQ[ar * QSTR + c + 4]);
        afr[kt][3] = __float_as_uint(aQ[(ar + 8) * QSTR + c + 4]);
    }

    const int nch0 = (warp >> 2) * 16;
    float dacc[2][4];
#pragma unroll
    for (int nt = 0; nt < 2; nt++)
#pragma unroll
        for (int j = 0; j < 4; j++) dacc[nt][j] = 0.f;

    const int srow  = tid >> 2;
    const int schnk = tid & 3;
    float rmax = -INFINITY, rsum = 0.f;

    // prefetch issue for tile at J0 -> buffers nb
    auto issue_tile = [&](int J0, int nb) {
#pragma unroll
        for (int i = 0; i < 2; i++) {
            int idx = tid + i * 256;
            int row = idx >> 3, c4 = idx & 7;
            cp16(smb + (uint32_t)((KbufOff[nb] + row * QSTR + c4 * 4) * 4),
                 kbase + (size_t)(J0 + row) * DH + c4 * 4, 16);
            cp16(smb + (uint32_t)((VbufOff[nb] + row * QSTR + c4 * 4) * 4),
                 vbase + (size_t)(J0 + row) * DH + c4 * 4, 16);
            int r = J0 - I0 + row;
            const float* psrc = pbase;
            int sz = 0;
            if (r <= 0) { if (r >= 1 - LL) { psrc = pbase + (size_t)(LL - 1 + r) * DH + c4 * 4; sz = 16; } }
            else if (r >= 2 && r <= LL + 1) { psrc = pbase + (size_t)(r - 2) * DH + c4 * 4; sz = 16; }
            cp16(smb + (uint32_t)((PbufOff[nb] + row * QSTR + c4 * 4) * 4), psrc, sz);
        }
    };

    // =============== prologue: band cols r in [-I0-64, -I0-1] into Pbuf[1] ======
    {
        const int r0 = -I0 - 64;
        for (int idx = tid; idx < 64 * 8; idx += 256) {
            int t = idx >> 3, c4 = idx & 7;
            int r = r0 + t;
            float4 pv = make_float4(0.f, 0.f, 0.f, 0.f);
            if (r <= 0) { if (r >= 1 - LL) pv = f2tf4(*(const float4*)(pbase + (size_t)(LL - 1 + r) * DH + c4 * 4)); }
            else if (r >= 2 && r <= LL + 1) pv = f2tf4(*(const float4*)(pbase + (size_t)(r - 2) * DH + c4 * 4));
            *(float4*)&sm[PbufOff[1] + t * QSTR + c4 * 4] = pv;
        }
        __syncthreads();

        // kick off tile-0 loads while prologue W computes
        issue_tile(0, 0);
        cp_commit();

        const int slotbase = (r0 + 4096) & (RING - 1);   // multiple of 64
        const float* Pb = sm + PbufOff[1];
        if (warp >= 4) {
#pragma unroll
            for (int nt = 0; nt < 8; nt++) {
                float d0 = 0.f, d1 = 0.f, d2 = 0.f, d3 = 0.f;
#pragma unroll
                for (int kt = 0; kt < 4; kt++) {
                    int bn = nt * 8 + (lane >> 2);
                    int bk = kt * 8 + (lane & 3);
                    uint32_t b0 = f2tfu(Pb[bn * QSTR + bk]);
                    uint32_t b1 = f2tfu(Pb[bn * QSTR + bk + 4]);
                    mma_tf32(d0, d1, d2, d3, afr[kt][0], afr[kt][1], afr[kt][2], afr[kt][3], b0, b1);
                }
                int wr = 16 * mwarp + (lane >> 2);
                int wc = slotbase + nt * 8 + 2 * (lane & 3);
                *(float2*)&sW[wr * WSTR + wc]       = make_float2(d0, d1);
                *(float2*)&sW[(wr + 8) * WSTR + wc] = make_float2(d2, d3);
            }
        }
        if (tid >= 192) {
            int t = tid - 192;
            float s = 0.f;
#pragma unroll
            for (int c = 0; c < DH; c++)
                s += sm[SQV_OFF + TI * QSTR + c] * f2tf(Pb[t * QSTR + c]);
            sW[TI * WSTR + slotbase + t] = s;
        }
    }

    // =============== main loop over key tiles ===============
    int cur = 0;
    for (int J0 = 0; J0 < LL; J0 += TJ) {
        cp_wait0();
        __syncthreads();   // loads visible; prev tile fully done

        if (J0 + TJ < LL) issue_tile(J0 + TJ, cur ^ 1);
        cp_commit();

        const int slotbase = ((J0 - I0) + 4096) & (RING - 1);
        const float* Kb = sm + KbufOff[cur];
        const float* Vb = sm + VbufOff[cur];
        const float* Pb = sm + PbufOff[cur];

        if (warp < 4) {
            // ---- content: S (64x64) = Qu @ K^T
#pragma unroll
            for (int nt = 0; nt < 8; nt++) {
                float d0 = 0.f, d1 = 0.f, d2 = 0.f, d3 = 0.f;
#pragma unroll
                for (int kt = 0; kt < 4; kt++) {
                    int bn = nt * 8 + (lane >> 2);
                    int bk = kt * 8 + (lane & 3);
                    uint32_t b0 = f2tfu(Kb[bn * QSTR + bk]);
                    uint32_t b1 = f2tfu(Kb[bn * QSTR + bk + 4]);
                    mma_tf32(d0, d1, d2, d3, afr[kt][0], afr[kt][1], afr[kt][2], afr[kt][3], b0, b1);
                }
                int sr = 16 * mwarp + (lane >> 2);
                int sc = nt * 8 + 2 * (lane & 3);
                *(float2*)&sS[sr * SSTR + sc]       = make_float2(d0, d1);
                *(float2*)&sS[(sr + 8) * SSTR + sc] = make_float2(d2, d3);
            }
        } else {
            // ---- band: 64 new W columns from fresh P
#pragma unroll
            for (int nt = 0; nt < 8; nt++) {
                float d0 = 0.f, d1 = 0.f, d2 = 0.f, d3 = 0.f;
#pragma unroll
                for (int kt = 0; kt < 4; kt++) {
                    int bn = nt * 8 + (lane >> 2);
                    int bk = kt * 8 + (lane & 3);
                    uint32_t b0 = f2tfu(Pb[bn * QSTR + bk]);
                    uint32_t b1 = f2tfu(Pb[bn * QSTR + bk + 4]);
                    mma_tf32(d0, d1, d2, d3, afr[kt][0], afr[kt][1], afr[kt][2], afr[kt][3], b0, b1);
                }
                int wr = 16 * mwarp + (lane >> 2);
                int wc = slotbase + nt * 8 + 2 * (lane & 3);
                *(float2*)&sW[wr * WSTR + wc]       = make_float2(d0, d1);
                *(float2*)&sW[(wr + 8) * WSTR + wc] = make_float2(d2, d3);
            }
        }
        if (tid >= 192) {
            int t = tid - 192;
            float s = 0.f;
#pragma unroll
            for (int c = 0; c < DH; c++)
                s += sm[SQV_OFF + TI * QSTR + c] * f2tf(Pb[t * QSTR + c]);
            sW[TI * WSTR + slotbase + t] = s;
        }
        __syncthreads();

        // ---- softmax: thread (srow, schnk) owns 16 columns
        {
            float s[16];
#pragma unroll
            for (int k4 = 0; k4 < 4; k4++) {
                float4 s4 = *(const float4*)&sS[srow * SSTR + schnk * 16 + k4 * 4];
                s[k4 * 4 + 0] = s4.x; s[k4 * 4 + 1] = s4.y;
                s[k4 * 4 + 2] = s4.z; s[k4 * 4 + 3] = s4.w;
            }
            const int qi = I0 + srow;
            float cmax = -INFINITY;
#pragma unroll
            for (int tt = 0; tt < 16; tt++) {
                int jj = schnk * 16 + tt;
                int r = J0 + jj - qi;
                int slot = (r + 4096) & (RING - 1);
                int wrow = srow + (r >= 1);
                s[tt] = (s[tt] + sW[wrow * WSTR + slot]) * SCALE;
                cmax = fmaxf(cmax, s[tt]);
            }
            cmax = fmaxf(cmax, __shfl_xor_sync(0xffffffffu, cmax, 1));
            cmax = fmaxf(cmax, __shfl_xor_sync(0xffffffffu, cmax, 2));
            float mnew = fmaxf(rmax, cmax);
            float corr = __expf(rmax - mnew);
            float csum = 0.f;
#pragma unroll
            for (int tt = 0; tt < 16; tt++) {
                float w = f2tf(__expf(s[tt] - mnew));
                s[tt] = w;
                csum += w;
            }
            csum += __shfl_xor_sync(0xffffffffu, csum, 1);
            csum += __shfl_xor_sync(0xffffffffu, csum, 2);
            rsum = rsum * corr + csum;
            rmax = mnew;
#pragma unroll
            for (int k4 = 0; k4 < 4; k4++)
                *(float4*)&sS[srow * SSTR + schnk * 16 + k4 * 4] =
                    make_float4(s[k4 * 4], s[k4 * 4 + 1], s[k4 * 4 + 2], s[k4 * 4 + 3]);
            if (schnk == 0) sCorr[srow] = corr;
        }
        __syncthreads();

        // ---- PV MMA: rescale persistent fragments, then O += P @ V
        {
            const int prow = 16 * mwarp + (lane >> 2);
            float c0 = sCorr[prow];
            float c1 = sCorr[prow + 8];
#pragma unroll
            for (int nt = 0; nt < 2; nt++) {
                dacc[nt][0] *= c0; dacc[nt][1] *= c0;
                dacc[nt][2] *= c1; dacc[nt][3] *= c1;
            }
#pragma unroll
            for (int kt = 0; kt < 8; kt++) {
                int c = kt * 8 + (lane & 3);
                uint32_t a0 = __float_as_uint(sS[prow * SSTR + c]);
                uint32_t a1 = __float_as_uint(sS[(prow + 8) * SSTR + c]);
                uint32_t a2 = __float_as_uint(sS[prow * SSTR + c + 4]);
                uint32_t a3 = __float_as_uint(sS[(prow + 8) * SSTR + c + 4]);
#pragma unroll
                for (int nt = 0; nt < 2; nt++) {
                    int bn = nch0 + nt * 8 + (lane >> 2);
                    uint32_t b0 = f2tfu(Vb[c * QSTR + bn]);
                    uint32_t b1 = f2tfu(Vb[(c + 4) * QSTR + bn]);
                    mma_tf32(dacc[nt][0], dacc[nt][1], dacc[nt][2], dacc[nt][3],
                             a0, a1, a2, a3, b0, b1);
                }
            }
        }
        cur ^= 1;
    }

    // ---- finalize
    __syncthreads();
    if (schnk == 0) sCorr[srow] = 1.f / rsum;
    __syncthreads();
    {
        const int prow = 16 * mwarp + (lane >> 2);
        float i0v = sCorr[prow];
        float i1v = sCorr[prow + 8];
        float* ob = ctx + (size_t)(b * HH + h) * LL * DH;
#pragma unroll
        for (int nt = 0; nt < 2; nt++) {
            int sc = nch0 + nt * 8 + 2 * (lane & 3);
            *(float2*)(ob + (size_t)(I0 + prow) * DH + sc) =
                make_float2(dacc[nt][0] * i0v, dacc[nt][1] * i0v);
            *(float2*)(ob + (size_t)(I0 + prow + 8) * DH + sc) =
                make_float2(dacc[nt][2] * i1v, dacc[nt][3] * i1v);
        }
    }
}

// ---------------------------------------------------------------------------
extern "C" void kernel_launch(void* const* d_in, const int* in_sizes, int n_in,
                              void* d_out, int out_size)
{
    const float* query = (const float*)d_in[0];
    const float* key   = (const float*)d_in[1];
    const float* value = (const float*)d_in[2];
    const float* pos   = (const float*)d_in[3];
    const float* Wq    = (const float*)d_in[4];
    const float* bq    = (const float*)d_in[5];
    const float* Wk    = (const float*)d_in[6];
    const float* bk    = (const float*)d_in[7];
    const float* Wv    = (const float*)d_in[8];
    const float* bv    = (const float*)d_in[9];
    const float* Wp    = (const float*)d_in[10];
    const float* ub    = (const float*)d_in[11];
    const float* vb    = (const float*)d_in[12];
    const float* Wo    = (const float*)d_in[13];
    const float* bo    = (const float*)d_in[14];

    float *pq, *pk, *pv, *pp, *pctx;
    cudaGetSymbolAddress((void**)&pq,   g_q);
    cudaGetSymbolAddress((void**)&pk,   g_k);
    cudaGetSymbolAddress((void**)&pv,   g_v);
    cudaGetSymbolAddress((void**)&pp,   g_p);
    cudaGetSymbolAddress((void**)&pctx, g_ctx);

    static int attr_set = 0;
    if (!attr_set) {
        cudaFuncSetAttribute(attn_mma, cudaFuncAttributeMaxDynamicSharedMemorySize, SMEM_BYTES);
        cudaFuncSetAttribute(qkv_gemm, cudaFuncAttributeMaxDynamicSharedMemorySize, GSMEM_BYTES);
        cudaFuncSetAttribute(one_gemm, cudaFuncAttributeMaxDynamicSharedMemorySize, GSMEM_BYTES);
        attr_set = 1;
    }

    // fused Q/K/V projections + P projection
    qkv_gemm<<<dim3(DM / TGN, (BB * LL) / TGM, 3), 256, GSMEM_BYTES>>>(
        query, key, value, Wq, Wk, Wv, bq, bk, bv, pq, pk, pv);
    one_gemm<<<dim3(DM / TGN, LL / TGM), 256, GSMEM_BYTES>>>(pos, Wp, nullptr, pp, 0, 1);

    attn_mma<<<dim3(LL / TI, HH, BB), 256, SMEM_BYTES>>>(pq, pk, pv, pp, ub, vb, pctx);

    one_gemm<<<dim3(DM / TGN, (BB * LL) / TGM), 256, GSMEM_BYTES>>>(
        pctx, Wo, bo, (float*)d_out, 1, 0);
}

// round 9
// speedup vs baseline: 3.8447x; 1.0631x over previous
#include <cuda_runtime.h>
#include <math.h>
#include <stdint.h>

#define BB 2
#define LL 2048
#define HH 16
#define DH 32
#define DM 512
#define SCALE 0.044194173824159216f  /* 1/sqrt(512) */

__device__ float g_q[BB*HH*LL*DH];
__device__ float g_k[BB*HH*LL*DH];
__device__ float g_v[BB*HH*LL*DH];
__device__ float g_p[HH*LL*DH];
__device__ float g_ctx[BB*HH*LL*DH];
__device__ float g_wbuf[5*DM*DM];     // pre-rounded Wq,Wk,Wv,Wp,Wo

// round-to-nearest tf32
__device__ __forceinline__ uint32_t f2tfu(float x) {
    uint32_t u;
    asm("cvt.rna.tf32.f32 %0, %1;" : "=r"(u) : "f"(x));
    return u;
}
__device__ __forceinline__ float f2tf(float x) { return __uint_as_float(f2tfu(x)); }
__device__ __forceinline__ float4 f2tf4(float4 v) {
    return make_float4(f2tf(v.x), f2tf(v.y), f2tf(v.z), f2tf(v.w));
}

__device__ __forceinline__ void mma_tf32(float& d0, float& d1, float& d2, float& d3,
                                         uint32_t a0, uint32_t a1, uint32_t a2, uint32_t a3,
                                         uint32_t b0, uint32_t b1) {
    asm volatile(
        "mma.sync.aligned.m16n8k8.row.col.f32.tf32.tf32.f32 "
        "{%0,%1,%2,%3}, {%4,%5,%6,%7}, {%8,%9}, {%0,%1,%2,%3};\n"
        : "+f"(d0), "+f"(d1), "+f"(d2), "+f"(d3)
        : "r"(a0), "r"(a1), "r"(a2), "r"(a3), "r"(b0), "r"(b1));
}

__device__ __forceinline__ void cp16(uint32_t dst, const void* src, int szbytes) {
    asm volatile("cp.async.cg.shared.global [%0], [%1], 16, %2;\n"
                 :: "r"(dst), "l"(src), "r"(szbytes));
}
__device__ __forceinline__ void cp_commit() {
    asm volatile("cp.async.commit_group;\n" ::: "memory");
}
__device__ __forceinline__ void cp_wait0() {
    asm volatile("cp.async.wait_group 0;\n" ::: "memory");
}

// ---------------------------------------------------------------------------
// preround: round weight matrices to tf32 once. grid (256,1,5)
// ---------------------------------------------------------------------------
__global__ __launch_bounds__(256)
void preround(const float* __restrict__ w0, const float* __restrict__ w1,
              const float* __restrict__ w2, const float* __restrict__ w3,
              const float* __restrict__ w4)
{
    const float* src[5] = {w0, w1, w2, w3, w4};
    int z = blockIdx.z;
    int i = (blockIdx.x * 256 + threadIdx.x) * 4;
    float4 v = *(const float4*)(src[z] + i);
    *(float4*)(g_wbuf + z * DM * DM + i) = f2tf4(v);
}

// ---------------------------------------------------------------------------
// tf32 GEMM core, cp.async double-buffered. W assumed pre-rounded.
// AROUND: apply tf32 rounding to A at consumption (raw fp32 inputs).
// oround: round outputs (intermediate tensors consumed raw downstream).
// ---------------------------------------------------------------------------
#define TGM 128
#define TGN 64
#define TGK 32
#define GASTR 36
#define GBSTR 36
#define GSMEM_FLOATS (2 * (TGM * GASTR + TGN * GBSTR))
#define GSMEM_BYTES (GSMEM_FLOATS * 4)   /* 55296 */

template<int AROUND>
__device__ __forceinline__ void gemm_core(
    const float* __restrict__ A, const float* __restrict__ W,
    const float* __restrict__ bias, float* __restrict__ C,
    int amode, int omode, int oround, float* smem)
{
    const int tid  = threadIdx.x;
    const int lane = tid & 31;
    const int warp = tid >> 5;
    const int g = lane >> 2;
    const int t = lane & 3;
    const int m0 = blockIdx.y * TGM;
    const int n0 = blockIdx.x * TGN;

    float* As = smem;
    float* Bs = smem + 2 * TGM * GASTR;
    const uint32_t smb = (uint32_t)__cvta_generic_to_shared(smem);

    float acc[8][4];
#pragma unroll
    for (int nt = 0; nt < 8; nt++)
#pragma unroll
        for (int j = 0; j < 4; j++) acc[nt][j] = 0.f;

    auto issue = [&](int k0, int buf) {
#pragma unroll
        for (int i = 0; i < 4; i++) {
            int idx = tid + i * 256;
            int row = idx >> 3, c4 = idx & 7;
            int gm = m0 + row;
            const float* src;
            if (amode == 0) {
                src = A + (size_t)gm * DM + k0 + c4 * 4;
            } else {
                int b = gm >> 11, l = gm & (LL - 1);
                int head = k0 >> 5;
                src = A + (((size_t)b * HH + head) * LL + l) * DH + c4 * 4;
            }
            cp16(smb + (uint32_t)((buf * TGM * GASTR + row * GASTR + c4 * 4) * 4), src, 16);
        }
#pragma unroll
        for (int i = 0; i < 2; i++) {
            int idx = tid + i * 256;
            int row = idx >> 3, c4 = idx & 7;
            const float* src = W + (size_t)(n0 + row) * DM + k0 + c4 * 4;
            cp16(smb + (uint32_t)((2 * TGM * GASTR + buf * TGN * GBSTR + row * GBSTR + c4 * 4) * 4), src, 16);
        }
    };

    issue(0, 0);
    cp_commit();

    for (int c = 0; c < 16; c++) {
        cp_wait0();
        __syncthreads();
        if (c < 15) issue((c + 1) * TGK, (c + 1) & 1);
        cp_commit();

        const float* Ab = As + (c & 1) * TGM * GASTR;
        const float* Bb = Bs + (c & 1) * TGN * GBSTR;
#pragma unroll
        for (int kt = 0; kt < 4; kt++) {
            int cc = kt * 8 + t;
            int ar = warp * 16 + g;
            uint32_t a0, a1, a2, a3;
            if (AROUND) {
                a0 = f2tfu(Ab[ar * GASTR + cc]);
                a1 = f2tfu(Ab[(ar + 8) * GASTR + cc]);
                a2 = f2tfu(Ab[ar * GASTR + cc + 4]);
                a3 = f2tfu(Ab[(ar + 8) * GASTR + cc + 4]);
            } else {
                a0 = __float_as_uint(Ab[ar * GASTR + cc]);
                a1 = __float_as_uint(Ab[(ar + 8) * GASTR + cc]);
                a2 = __float_as_uint(Ab[ar * GASTR + cc + 4]);
                a3 = __float_as_uint(Ab[(ar + 8) * GASTR + cc + 4]);
            }
#pragma unroll
            for (int nt = 0; nt < 8; nt++) {
                uint32_t b0 = __float_as_uint(Bb[(nt * 8 + g) * GBSTR + cc]);
                uint32_t b1 = __float_as_uint(Bb[(nt * 8 + g) * GBSTR + cc + 4]);
                mma_tf32(acc[nt][0], acc[nt][1], acc[nt][2], acc[nt][3],
                         a0, a1, a2, a3, b0, b1);
            }
        }
    }

    const int sr = warp * 16 + g;
#pragma unroll
    for (int nt = 0; nt < 8; nt++) {
        int sc = nt * 8 + 2 * t;
        int n  = n0 + sc;
        float b0v = bias ? bias[n]     : 0.f;
        float b1v = bias ? bias[n + 1] : 0.f;
        float2 p0 = make_float2(acc[nt][0] + b0v, acc[nt][1] + b1v);
        float2 p1 = make_float2(acc[nt][2] + b0v, acc[nt][3] + b1v);
        if (oround) {
            p0 = make_float2(f2tf(p0.x), f2tf(p0.y));
            p1 = make_float2(f2tf(p1.x), f2tf(p1.y));
        }
        if (omode == 0) {
            *(float2*)(C + (size_t)(m0 + sr) * DM + n)     = p0;
            *(float2*)(C + (size_t)(m0 + sr + 8) * DM + n) = p1;
        } else {
            int head = n >> 5, d = n & 31;
            int gm = m0 + sr;
            int b = gm >> 11, l = gm & (LL - 1);
            float* base = C + (((size_t)b * HH + head) * LL + l) * DH + d;
            *(float2*)(base)          = p0;
            *(float2*)(base + 8 * DH) = p1;
        }
    }
}

// z=0: Q (out unrounded; attn re-rounds after bias add)
// z=1: K, z=2: V, z=3: P (outs pre-rounded); z=3 guards M=2048
__global__ __launch_bounds__(256)
void qkvp_gemm(const float* __restrict__ q, const float* __restrict__ k,
               const float* __restrict__ v, const float* __restrict__ p,
               const float* __restrict__ bq, const float* __restrict__ bk,
               const float* __restrict__ bv,
               float* __restrict__ oq, float* __restrict__ ok,
               float* __restrict__ ov, float* __restrict__ op)
{
    extern __shared__ float smem[];
    int z = blockIdx.z;
    if (z == 3 && blockIdx.y >= LL / TGM) return;
    const float* A = (z == 0) ? q : (z == 1) ? k : (z == 2) ? v : p;
    const float* W = g_wbuf + z * DM * DM;
    const float* b = (z == 0) ? bq : (z == 1) ? bk : (z == 2) ? bv : nullptr;
    float* C = (z == 0) ? oq : (z == 1) ? ok : (z == 2) ? ov : op;
    gemm_core<1>(A, W, b, C, 0, 1, (z != 0), smem);
}

__global__ __launch_bounds__(256)
void wo_gemm(const float* __restrict__ A, const float* __restrict__ bias,
             float* __restrict__ C)
{
    extern __shared__ float smem[];
    gemm_core<0>(A, g_wbuf + 4 * DM * DM, bias, C, 1, 0, 0, smem);
}

// ---------------------------------------------------------------------------
// Ring-band MMA attention; K/V/P pre-rounded -> raw-bit consumption.
// Shift: r=j-i; r<=0 -> p[L-1+r]; r==1 -> 0; r>=2 -> row i+1 uses p[r-2]
// ---------------------------------------------------------------------------
#define TI 64
#define TJ 64
#define QSTR 36
#define SSTR 68
#define WSTR 132
#define RING 128

#define SQU_OFF 0
#define SQV_OFF (SQU_OFF + TI * QSTR)             /* 2304  */
#define SK_OFF  (SQV_OFF + (TI + 1) * QSTR)       /* 4644  */
#define SV_OFF  (SK_OFF + TJ * QSTR)              /* 6948  */
#define SP_OFF  (SV_OFF + TJ * QSTR)              /* 9252  */
#define SS_OFF  (SP_OFF + RING * QSTR)            /* 13860 */
#define SW_OFF  (SS_OFF + TI * SSTR)              /* 18212 */
#define SC_OFF  (SW_OFF + (TI + 1) * WSTR)        /* 26792 */
#define SMEM_FLOATS (SC_OFF + TI)                 /* 26856 */
#define SMEM_BYTES (SMEM_FLOATS * 4)              /* 107424 */

__global__ __launch_bounds__(256, 2)
void attn_mma(const float* __restrict__ qd, const float* __restrict__ kd,
              const float* __restrict__ vd, const float* __restrict__ pd,
              const float* __restrict__ ub, const float* __restrict__ vb,
              float* __restrict__ ctx)
{
    extern __shared__ float sm[];
    float* sS  = sm + SS_OFF;
    float* sW  = sm + SW_OFF;
    float* sCorr = sm + SC_OFF;
    const uint32_t smb = (uint32_t)__cvta_generic_to_shared(sm);

    const int tid  = threadIdx.x;
    const int lane = tid & 31;
    const int warp = tid >> 5;
    const int I0 = blockIdx.x * TI;
    const int h = blockIdx.y, b = blockIdx.z;

    const float* qbase = qd + (size_t)(b * HH + h) * LL * DH;
    const float* kbase = kd + (size_t)(b * HH + h) * LL * DH;
    const float* vbase = vd + (size_t)(b * HH + h) * LL * DH;
    const float* pbase = pd + (size_t)h * LL * DH;

    const int KbufOff[2] = {SK_OFF, SQU_OFF};
    const int VbufOff[2] = {SV_OFF, SQV_OFF};
    const int PbufOff[2] = {SP_OFF, SP_OFF + 64 * QSTR};

    // ---- stage Qu (64 rows) and Qv (65 rows); q unrounded, round after bias
    for (int idx = tid; idx < TI * 8; idx += 256) {
        int row = idx >> 3, c4 = idx & 7;
        float4 q  = *(const float4*)(qbase + (size_t)(I0 + row) * DH + c4 * 4);
        float4 u4 = *(const float4*)(ub + h * DH + c4 * 4);
        *(float4*)&sm[SQU_OFF + row * QSTR + c4 * 4] =
            f2tf4(make_float4(q.x + u4.x, q.y + u4.y, q.z + u4.z, q.w + u4.w));
    }
    for (int idx = tid; idx < (TI + 1) * 8; idx += 256) {
        int row = idx >> 3, c4 = idx & 7;
        int g = I0 + row;
        float4 o = make_float4(0.f, 0.f, 0.f, 0.f);
        if (g < LL) {
            float4 q  = *(const float4*)(qbase + (size_t)g * DH + c4 * 4);
            float4 v4 = *(const float4*)(vb + h * DH + c4 * 4);
            o = f2tf4(make_float4(q.x + v4.x, q.y + v4.y, q.z + v4.z, q.w + v4.w));
        }
        *(float4*)&sm[SQV_OFF + row * QSTR + c4 * 4] = o;
    }
    __syncthreads();

    // ---- hoist score-MMA A fragments; sQu/sQv[0..63] dead after
    const int mwarp = warp & 3;
    const int ar = 16 * mwarp + (lane >> 2);
    const int ac = lane & 3;
    const float* aQ = (warp < 4) ? (sm + SQU_OFF) : (sm + SQV_OFF);
    uint32_t afr[4][4];
#pragma unroll
    for (int kt = 0; kt < 4; kt++) {
        int c = kt * 8 + ac;
        afr[kt][0] = __float_as_uint(aQ[ar * QSTR + c]);
        afr[kt][1] = __float_as_uint(aQ[(ar + 8) * QSTR + c]);
        afr[kt][2] = __float_as_uint(aQ[ar * QSTR + c + 4]);
        afr[kt][3] = __float_as_uint(aQ[(ar + 8) * QSTR + c + 4]);
    }

    const int nch0 = (warp >> 2) * 16;
    float dacc[2][4];
#pragma unroll
    for (int nt = 0; nt < 2; nt++)
#pragma unroll
        for (int j = 0; j < 4; j++) dacc[nt][j] = 0.f;

    const int srow  = tid >> 2;
    const int schnk = tid & 3;
    float rmax = -INFINITY, rsum = 0.f;

    auto issue_tile = [&](int J0, int nb) {
#pragma unroll
        for (int i = 0; i < 2; i++) {
            int idx = tid + i * 256;
            int row = idx >> 3, c4 = idx & 7;
            cp16(smb + (uint32_t)((KbufOff[nb] + row * QSTR + c4 * 4) * 4),
                 kbase + (size_t)(J0 + row) * DH + c4 * 4, 16);
            cp16(smb + (uint32_t)((VbufOff[nb] + row * QSTR + c4 * 4) * 4),
                 vbase + (size_t)(J0 + row) * DH + c4 * 4, 16);
            int r = J0 - I0 + row;
            const float* psrc = pbase;
            int sz = 0;
            if (r <= 0) { if (r >= 1 - LL) { psrc = pbase + (size_t)(LL - 1 + r) * DH + c4 * 4; sz = 16; } }
            else if (r >= 2 && r <= LL + 1) { psrc = pbase + (size_t)(r - 2) * DH + c4 * 4; sz = 16; }
            cp16(smb + (uint32_t)((PbufOff[nb] + row * QSTR + c4 * 4) * 4), psrc, sz);
        }
    };

    // =============== prologue: band cols r in [-I0-64, -I0-1] into Pbuf[1] ======
    {
        const int r0 = -I0 - 64;
        for (int idx = tid; idx < 64 * 8; idx += 256) {
            int t = idx >> 3, c4 = idx & 7;
            int r = r0 + t;
            float4 pv = make_float4(0.f, 0.f, 0.f, 0.f);
            if (r <= 0) { if (r >= 1 - LL) pv = *(const float4*)(pbase + (size_t)(LL - 1 + r) * DH + c4 * 4); }
            else if (r >= 2 && r <= LL + 1) pv = *(const float4*)(pbase + (size_t)(r - 2) * DH + c4 * 4);
            *(float4*)&sm[PbufOff[1] + t * QSTR + c4 * 4] = pv;
        }
        __syncthreads();

        issue_tile(0, 0);
        cp_commit();

        const int slotbase = (r0 + 4096) & (RING - 1);
        const float* Pb = sm + PbufOff[1];
        if (warp >= 4) {
#pragma unroll
            for (int nt = 0; nt < 8; nt++) {
                float d0 = 0.f, d1 = 0.f, d2 = 0.f, d3 = 0.f;
#pragma unroll
                for (int kt = 0; kt < 4; kt++) {
                    int bn = nt * 8 + (lane >> 2);
                    int bk = kt * 8 + (lane & 3);
                    uint32_t b0 = __float_as_uint(Pb[bn * QSTR + bk]);
                    uint32_t b1 = __float_as_uint(Pb[bn * QSTR + bk + 4]);
                    mma_tf32(d0, d1, d2, d3, afr[kt][0], afr[kt][1], afr[kt][2], afr[kt][3], b0, b1);
                }
                int wr = 16 * mwarp + (lane >> 2);
                int wc = slotbase + nt * 8 + 2 * (lane & 3);
                *(float2*)&sW[wr * WSTR + wc]       = make_float2(d0, d1);
                *(float2*)&sW[(wr + 8) * WSTR + wc] = make_float2(d2, d3);
            }
        }
        if (tid >= 192) {
            int t = tid - 192;
            float s = 0.f;
#pragma unroll
            for (int c = 0; c < DH; c++)
                s += sm[SQV_OFF + TI * QSTR + c] * Pb[t * QSTR + c];
            sW[TI * WSTR + slotbase + t] = s;
        }
    }

    // =============== main loop over key tiles ===============
    int cur = 0;
    for (int J0 = 0; J0 < LL; J0 += TJ) {
        cp_wait0();
        __syncthreads();

        if (J0 + TJ < LL) issue_tile(J0 + TJ, cur ^ 1);
        cp_commit();

        const int slotbase = ((J0 - I0) + 4096) & (RING - 1);
        const float* Kb = sm + KbufOff[cur];
        const float* Vb = sm + VbufOff[cur];
        const float* Pb = sm + PbufOff[cur];

        if (warp < 4) {
#pragma unroll
            for (int nt = 0; nt < 8; nt++) {
                float d0 = 0.f, d1 = 0.f, d2 = 0.f, d3 = 0.f;
#pragma unroll
                for (int kt = 0; kt < 4; kt++) {
                    int bn = nt * 8 + (lane >> 2);
                    int bk = kt * 8 + (lane & 3);
                    uint32_t b0 = __float_as_uint(Kb[bn * QSTR + bk]);
                    uint32_t b1 = __float_as_uint(Kb[bn * QSTR + bk + 4]);
                    mma_tf32(d0, d1, d2, d3, afr[kt][0], afr[kt][1], afr[kt][2], afr[kt][3], b0, b1);
                }
                int sr = 16 * mwarp + (lane >> 2);
                int sc = nt * 8 + 2 * (lane & 3);
                *(float2*)&sS[sr * SSTR + sc]       = make_float2(d0, d1);
                *(float2*)&sS[(sr + 8) * SSTR + sc] = make_float2(d2, d3);
            }
        } else {
#pragma unroll
            for (int nt = 0; nt < 8; nt++) {
                float d0 = 0.f, d1 = 0.f, d2 = 0.f, d3 = 0.f;
#pragma unroll
                for (int kt = 0; kt < 4; kt++) {
                    int bn = nt * 8 + (lane >> 2);
                    int bk = kt * 8 + (lane & 3);
                    uint32_t b0 = __float_as_uint(Pb[bn * QSTR + bk]);
                    uint32_t b1 = __float_as_uint(Pb[bn * QSTR + bk + 4]);
                    mma_tf32(d0, d1, d2, d3, afr[kt][0], afr[kt][1], afr[kt][2], afr[kt][3], b0, b1);
                }
                int wr = 16 * mwarp + (lane >> 2);
                int wc = slotbase + nt * 8 + 2 * (lane & 3);
                *(float2*)&sW[wr * WSTR + wc]       = make_float2(d0, d1);
                *(float2*)&sW[(wr + 8) * WSTR + wc] = make_float2(d2, d3);
            }
        }
        if (tid >= 192) {
            int t = tid - 192;
            float s = 0.f;
#pragma unroll
            for (int c = 0; c < DH; c++)
                s += sm[SQV_OFF + TI * QSTR + c] * Pb[t * QSTR + c];
            sW[TI * WSTR + slotbase + t] = s;
        }
        __syncthreads();

        // ---- softmax: thread (srow, schnk) owns 16 columns
        {
            float s[16];
#pragma unroll
            for (int k4 = 0; k4 < 4; k4++) {
                float4 s4 = *(const float4*)&sS[srow * SSTR + schnk * 16 + k4 * 4];
                s[k4 * 4 + 0] = s4.x; s[k4 * 4 + 1] = s4.y;
                s[k4 * 4 + 2] = s4.z; s[k4 * 4 + 3] = s4.w;
            }
            const int qi = I0 + srow;
            float cmax = -INFINITY;
#pragma unroll
            for (int tt = 0; tt < 16; tt++) {
                int jj = schnk * 16 + tt;
                int r = J0 + jj - qi;
                int slot = (r + 4096) & (RING - 1);
                int wrow = srow + (r >= 1);
                s[tt] = (s[tt] + sW[wrow * WSTR + slot]) * SCALE;
                cmax = fmaxf(cmax, s[tt]);
            }
            cmax = fmaxf(cmax, __shfl_xor_sync(0xffffffffu, cmax, 1));
            cmax = fmaxf(cmax, __shfl_xor_sync(0xffffffffu, cmax, 2));
            float mnew = fmaxf(rmax, cmax);
            float corr = __expf(rmax - mnew);
            float csum = 0.f;
#pragma unroll
            for (int tt = 0; tt < 16; tt++) {
                float w = f2tf(__expf(s[tt] - mnew));
                s[tt] = w;
                csum += w;
            }
            csum += __shfl_xor_sync(0xffffffffu, csum, 1);
            csum += __shfl_xor_sync(0xffffffffu, csum, 2);
            rsum = rsum * corr + csum;
            rmax = mnew;
#pragma unroll
            for (int k4 = 0; k4 < 4; k4++)
                *(float4*)&sS[srow * SSTR + schnk * 16 + k4 * 4] =
                    make_float4(s[k4 * 4], s[k4 * 4 + 1], s[k4 * 4 + 2], s[k4 * 4 + 3]);
            if (schnk == 0) sCorr[srow] = corr;
        }
        __syncthreads();

        // ---- PV MMA
        {
            const int prow = 16 * mwarp + (lane >> 2);
            float c0 = sCorr[prow];
            float c1 = sCorr[prow + 8];
#pragma unroll
            for (int nt = 0; nt < 2; nt++) {
                dacc[nt][0] *= c0; dacc[nt][1] *= c0;
                dacc[nt][2] *= c1; dacc[nt][3] *= c1;
            }
#pragma unroll
            for (int kt = 0; kt < 8; kt++) {
                int c = kt * 8 + (lane & 3);
                uint32_t a0 = __float_as_uint(sS[prow * SSTR + c]);
                uint32_t a1 = __float_as_uint(sS[(prow + 8) * SSTR + c]);
                uint32_t a2 = __float_as_uint(sS[prow * SSTR + c + 4]);
                uint32_t a3 = __float_as_uint(sS[(prow + 8) * SSTR + c + 4]);
#pragma unroll
                for (int nt = 0; nt < 2; nt++) {
                    int bn = nch0 + nt * 8 + (lane >> 2);
                    uint32_t b0 = __float_as_uint(Vb[c * QSTR + bn]);
                    uint32_t b1 = __float_as_uint(Vb[(c + 4) * QSTR + bn]);
                    mma_tf32(dacc[nt][0], dacc[nt][1], dacc[nt][2], dacc[nt][3],
                             a0, a1, a2, a3, b0, b1);
                }
            }
        }
        cur ^= 1;
    }

    // ---- finalize; write ctx pre-rounded (Wo gemm consumes raw)
    __syncthreads();
    if (schnk == 0) sCorr[srow] = 1.f / rsum;
    __syncthreads();
    {
        const int prow = 16 * mwarp + (lane >> 2);
        float i0v = sCorr[prow];
        float i1v = sCorr[prow + 8];
        float* ob = ctx + (size_t)(b * HH + h) * LL * DH;
#pragma unroll
        for (int nt = 0; nt < 2; nt++) {
            int sc = nch0 + nt * 8 + 2 * (lane & 3);
            *(float2*)(ob + (size_t)(I0 + prow) * DH + sc) =
                make_float2(f2tf(dacc[nt][0] * i0v), f2tf(dacc[nt][1] * i0v));
            *(float2*)(ob + (size_t)(I0 + prow + 8) * DH + sc) =
                make_float2(f2tf(dacc[nt][2] * i1v), f2tf(dacc[nt][3] * i1v));
        }
    }
}

// ---------------------------------------------------------------------------
extern "C" void kernel_launch(void* const* d_in, const int* in_sizes, int n_in,
                              void* d_out, int out_size)
{
    const float* query = (const float*)d_in[0];
    const float* key   = (const float*)d_in[1];
    const float* value = (const float*)d_in[2];
    const float* pos   = (const float*)d_in[3];
    const float* Wq    = (const float*)d_in[4];
    const float* bq    = (const float*)d_in[5];
    const float* Wk    = (const float*)d_in[6];
    const float* bk    = (const float*)d_in[7];
    const float* Wv    = (const float*)d_in[8];
    const float* bv    = (const float*)d_in[9];
    const float* Wp    = (const float*)d_in[10];
    const float* ub    = (const float*)d_in[11];
    const float* vb    = (const float*)d_in[12];
    const float* Wo    = (const float*)d_in[13];
    const float* bo    = (const float*)d_in[14];

    float *pq, *pk, *pv, *pp, *pctx;
    cudaGetSymbolAddress((void**)&pq,   g_q);
    cudaGetSymbolAddress((void**)&pk,   g_k);
    cudaGetSymbolAddress((void**)&pv,   g_v);
    cudaGetSymbolAddress((void**)&pp,   g_p);
    cudaGetSymbolAddress((void**)&pctx, g_ctx);

    static int attr_set = 0;
    if (!attr_set) {
        cudaFuncSetAttribute(attn_mma, cudaFuncAttributeMaxDynamicSharedMemorySize, SMEM_BYTES);
        cudaFuncSetAttribute(qkvp_gemm, cudaFuncAttributeMaxDynamicSharedMemorySize, GSMEM_BYTES);
        cudaFuncSetAttribute(wo_gemm, cudaFuncAttributeMaxDynamicSharedMemorySize, GSMEM_BYTES);
        attr_set = 1;
    }

    // pre-round all weights into g_wbuf
    preround<<<dim3(DM * DM / 1024, 1, 5), 256>>>(Wq, Wk, Wv, Wp, Wo);

    // fused Q/K/V/P projections
    qkvp_gemm<<<dim3(DM / TGN, (BB * LL) / TGM, 4), 256, GSMEM_BYTES>>>(
        query, key, value, pos, bq, bk, bv, pq, pk, pv, pp);

    attn_mma<<<dim3(LL / TI, HH, BB), 256, SMEM_BYTES>>>(pq, pk, pv, pp, ub, vb, pctx);

    wo_gemm<<<dim3(DM / TGN, (BB * LL) / TGM), 256, GSMEM_BYTES>>>(
        pctx, bo, (float*)d_out);
}

// round 10
// speedup vs baseline: 4.1970x; 1.0916x over previous
#include <cuda_runtime.h>
#include <math.h>
#include <stdint.h>

#define BB 2
#define LL 2048
#define HH 16
#define DH 32
#define DM 512
#define SCALE 0.044194173824159216f  /* 1/sqrt(512) */

__device__ float g_q[BB*HH*LL*DH];
__device__ float g_k[BB*HH*LL*DH];
__device__ float g_v[BB*HH*LL*DH];
__device__ float g_p[HH*LL*DH];
__device__ float g_ctx[BB*HH*LL*DH];
__device__ float g_wbuf[5*DM*DM];     // pre-rounded Wq,Wk,Wv,Wp,Wo

// round-to-nearest tf32
__device__ __forceinline__ uint32_t f2tfu(float x) {
    uint32_t u;
    asm("cvt.rna.tf32.f32 %0, %1;" : "=r"(u) : "f"(x));
    return u;
}
__device__ __forceinline__ float f2tf(float x) { return __uint_as_float(f2tfu(x)); }
__device__ __forceinline__ float4 f2tf4(float4 v) {
    return make_float4(f2tf(v.x), f2tf(v.y), f2tf(v.z), f2tf(v.w));
}

__device__ __forceinline__ void mma_tf32(float& d0, float& d1, float& d2, float& d3,
                                         uint32_t a0, uint32_t a1, uint32_t a2, uint32_t a3,
                                         uint32_t b0, uint32_t b1) {
    asm volatile(
        "mma.sync.aligned.m16n8k8.row.col.f32.tf32.tf32.f32 "
        "{%0,%1,%2,%3}, {%4,%5,%6,%7}, {%8,%9}, {%0,%1,%2,%3};\n"
        : "+f"(d0), "+f"(d1), "+f"(d2), "+f"(d3)
        : "r"(a0), "r"(a1), "r"(a2), "r"(a3), "r"(b0), "r"(b1));
}

__device__ __forceinline__ void cp16(uint32_t dst, const void* src, int szbytes) {
    asm volatile("cp.async.cg.shared.global [%0], [%1], 16, %2;\n"
                 :: "r"(dst), "l"(src), "r"(szbytes));
}
__device__ __forceinline__ void cp_commit() {
    asm volatile("cp.async.commit_group;\n" ::: "memory");
}
template<int N>
__device__ __forceinline__ void cp_wait() {
    asm volatile("cp.async.wait_group %0;\n" :: "n"(N) : "memory");
}
#define BARSYNC(id, cnt) asm volatile("bar.sync %0, %1;" :: "r"(id), "r"(cnt) : "memory")

// ---------------------------------------------------------------------------
// preround: round weight matrices to tf32 once. grid (256,1,5)
// ---------------------------------------------------------------------------
__global__ __launch_bounds__(256)
void preround(const float* __restrict__ w0, const float* __restrict__ w1,
              const float* __restrict__ w2, const float* __restrict__ w3,
              const float* __restrict__ w4)
{
    const float* src[5] = {w0, w1, w2, w3, w4};
    int z = blockIdx.z;
    int i = (blockIdx.x * 256 + threadIdx.x) * 4;
    float4 v = *(const float4*)(src[z] + i);
    *(float4*)(g_wbuf + z * DM * DM + i) = f2tf4(v);
}

// ---------------------------------------------------------------------------
// tf32 GEMM core, cp.async double-buffered. W pre-rounded (raw consumption).
// ---------------------------------------------------------------------------
#define TGM 128
#define TGN 64
#define TGK 32
#define GASTR 36
#define GBSTR 36
#define GSMEM_FLOATS (2 * (TGM * GASTR + TGN * GBSTR))
#define GSMEM_BYTES (GSMEM_FLOATS * 4)   /* 55296 */

template<int AROUND>
__device__ __forceinline__ void gemm_core(
    const float* __restrict__ A, const float* __restrict__ W,
    const float* __restrict__ bias, float* __restrict__ C,
    int amode, int omode, int oround, float* smem)
{
    const int tid  = threadIdx.x;
    const int lane = tid & 31;
    const int warp = tid >> 5;
    const int g = lane >> 2;
    const int t = lane & 3;
    const int m0 = blockIdx.y * TGM;
    const int n0 = blockIdx.x * TGN;

    float* As = smem;
    float* Bs = smem + 2 * TGM * GASTR;
    const uint32_t smb = (uint32_t)__cvta_generic_to_shared(smem);

    float acc[8][4];
#pragma unroll
    for (int nt = 0; nt < 8; nt++)
#pragma unroll
        for (int j = 0; j < 4; j++) acc[nt][j] = 0.f;

    auto issue = [&](int k0, int buf) {
#pragma unroll
        for (int i = 0; i < 4; i++) {
            int idx = tid + i * 256;
            int row = idx >> 3, c4 = idx & 7;
            int gm = m0 + row;
            const float* src;
            if (amode == 0) {
                src = A + (size_t)gm * DM + k0 + c4 * 4;
            } else {
                int b = gm >> 11, l = gm & (LL - 1);
                int head = k0 >> 5;
                src = A + (((size_t)b * HH + head) * LL + l) * DH + c4 * 4;
            }
            cp16(smb + (uint32_t)((buf * TGM * GASTR + row * GASTR + c4 * 4) * 4), src, 16);
        }
#pragma unroll
        for (int i = 0; i < 2; i++) {
            int idx = tid + i * 256;
            int row = idx >> 3, c4 = idx & 7;
            const float* src = W + (size_t)(n0 + row) * DM + k0 + c4 * 4;
            cp16(smb + (uint32_t)((2 * TGM * GASTR + buf * TGN * GBSTR + row * GBSTR + c4 * 4) * 4), src, 16);
        }
    };

    issue(0, 0);
    cp_commit();

    for (int c = 0; c < 16; c++) {
        cp_wait<0>();
        __syncthreads();
        if (c < 15) issue((c + 1) * TGK, (c + 1) & 1);
        cp_commit();

        const float* Ab = As + (c & 1) * TGM * GASTR;
        const float* Bb = Bs + (c & 1) * TGN * GBSTR;
#pragma unroll
        for (int kt = 0; kt < 4; kt++) {
            int cc = kt * 8 + t;
            int ar = warp * 16 + g;
            uint32_t a0, a1, a2, a3;
            if (AROUND) {
                a0 = f2tfu(Ab[ar * GASTR + cc]);
                a1 = f2tfu(Ab[(ar + 8) * GASTR + cc]);
                a2 = f2tfu(Ab[ar * GASTR + cc + 4]);
                a3 = f2tfu(Ab[(ar + 8) * GASTR + cc + 4]);
            } else {
                a0 = __float_as_uint(Ab[ar * GASTR + cc]);
                a1 = __float_as_uint(Ab[(ar + 8) * GASTR + cc]);
                a2 = __float_as_uint(Ab[ar * GASTR + cc + 4]);
                a3 = __float_as_uint(Ab[(ar + 8) * GASTR + cc + 4]);
            }
#pragma unroll
            for (int nt = 0; nt < 8; nt++) {
                uint32_t b0 = __float_as_uint(Bb[(nt * 8 + g) * GBSTR + cc]);
                uint32_t b1 = __float_as_uint(Bb[(nt * 8 + g) * GBSTR + cc + 4]);
                mma_tf32(acc[nt][0], acc[nt][1], acc[nt][2], acc[nt][3],
                         a0, a1, a2, a3, b0, b1);
            }
        }
    }

    const int sr = warp * 16 + g;
#pragma unroll
    for (int nt = 0; nt < 8; nt++) {
        int sc = nt * 8 + 2 * t;
        int n  = n0 + sc;
        float b0v = bias ? bias[n]     : 0.f;
        float b1v = bias ? bias[n + 1] : 0.f;
        float2 p0 = make_float2(acc[nt][0] + b0v, acc[nt][1] + b1v);
        float2 p1 = make_float2(acc[nt][2] + b0v, acc[nt][3] + b1v);
        if (oround) {
            p0 = make_float2(f2tf(p0.x), f2tf(p0.y));
            p1 = make_float2(f2tf(p1.x), f2tf(p1.y));
        }
        if (omode == 0) {
            *(float2*)(C + (size_t)(m0 + sr) * DM + n)     = p0;
            *(float2*)(C + (size_t)(m0 + sr + 8) * DM + n) = p1;
        } else {
            int head = n >> 5, d = n & 31;
            int gm = m0 + sr;
            int b = gm >> 11, l = gm & (LL - 1);
            float* base = C + (((size_t)b * HH + head) * LL + l) * DH + d;
            *(float2*)(base)          = p0;
            *(float2*)(base + 8 * DH) = p1;
        }
    }
}

__global__ __launch_bounds__(256)
void qkvp_gemm(const float* __restrict__ q, const float* __restrict__ k,
               const float* __restrict__ v, const float* __restrict__ p,
               const float* __restrict__ bq, const float* __restrict__ bk,
               const float* __restrict__ bv,
               float* __restrict__ oq, float* __restrict__ ok,
               float* __restrict__ ov, float* __restrict__ op)
{
    extern __shared__ float smem[];
    int z = blockIdx.z;
    if (z == 3 && blockIdx.y >= LL / TGM) return;
    const float* A = (z == 0) ? q : (z == 1) ? k : (z == 2) ? v : p;
    const float* W = g_wbuf + z * DM * DM;
    const float* b = (z == 0) ? bq : (z == 1) ? bk : (z == 2) ? bv : nullptr;
    float* C = (z == 0) ? oq : (z == 1) ? ok : (z == 2) ? ov : op;
    gemm_core<1>(A, W, b, C, 0, 1, (z != 0), smem);
}

__global__ __launch_bounds__(256)
void wo_gemm(const float* __restrict__ A, const float* __restrict__ bias,
             float* __restrict__ C)
{
    extern __shared__ float smem[];
    gemm_core<0>(A, g_wbuf + 4 * DM * DM, bias, C, 1, 0, 0, smem);
}

// ---------------------------------------------------------------------------
// Warp-specialized ring-band attention.
// Warps 0-3 (producers): S(t)+W(t) MMA into REGISTERS overlapping consumers'
//   softmax+PV(t-1); write sS/sW only after bar1 ("free"); publish via bar2.
// Warps 4-7 (consumers): softmax (thread=(row,half), 32 cols) -> weights
//   in-place in sS; PV MMA (rows 16/warp, all 32 channels).
// cp.async: producers only. Groups A={K,P}, B={V}; wait_group 2 invariants.
// Shift: r=j-i; r<=0 -> p[L-1+r]; r==1 -> 0; r>=2 -> row i+1 uses p[r-2]
// ---------------------------------------------------------------------------
#define TI 64
#define TJ 64
#define QSTR 36
#define SSTR 68
#define WSTR 132
#define RING 128

#define SQU_OFF 0
#define SQV_OFF (SQU_OFF + TI * QSTR)             /* 2304  */
#define SK_OFF  (SQV_OFF + (TI + 1) * QSTR)       /* 4644  */
#define SV_OFF  (SK_OFF + TJ * QSTR)              /* 6948  */
#define SP_OFF  (SV_OFF + TJ * QSTR)              /* 9252  */
#define SS_OFF  (SP_OFF + RING * QSTR)            /* 13860 */
#define SW_OFF  (SS_OFF + TI * SSTR)              /* 18212 */
#define SC_OFF  (SW_OFF + (TI + 1) * WSTR)        /* 26792 */
#define SMEM_FLOATS (SC_OFF + TI)                 /* 26856 */
#define SMEM_BYTES (SMEM_FLOATS * 4)              /* 107424 */

__global__ __launch_bounds__(256, 2)
void attn_mma(const float* __restrict__ qd, const float* __restrict__ kd,
              const float* __restrict__ vd, const float* __restrict__ pd,
              const float* __restrict__ ub, const float* __restrict__ vb,
              float* __restrict__ ctx)
{
    extern __shared__ float sm[];
    float* sS  = sm + SS_OFF;
    float* sW  = sm + SW_OFF;
    float* sCorr = sm + SC_OFF;
    const uint32_t smb = (uint32_t)__cvta_generic_to_shared(sm);

    const int tid  = threadIdx.x;
    const int lane = tid & 31;
    const int warp = tid >> 5;
    const int I0 = blockIdx.x * TI;
    const int h = blockIdx.y, b = blockIdx.z;

    const float* qbase = qd + (size_t)(b * HH + h) * LL * DH;
    const float* kbase = kd + (size_t)(b * HH + h) * LL * DH;
    const float* vbase = vd + (size_t)(b * HH + h) * LL * DH;
    const float* pbase = pd + (size_t)h * LL * DH;

    const int KbufOff[2] = {SK_OFF, SQU_OFF};
    const int VbufOff[2] = {SV_OFF, SQV_OFF};
    const int PbufOff[2] = {SP_OFF, SP_OFF + 64 * QSTR};

    // ---- stage Qu (64 rows) and Qv (65 rows), rna-rounded (all threads)
    for (int idx = tid; idx < TI * 8; idx += 256) {
        int row = idx >> 3, c4 = idx & 7;
        float4 q  = *(const float4*)(qbase + (size_t)(I0 + row) * DH + c4 * 4);
        float4 u4 = *(const float4*)(ub + h * DH + c4 * 4);
        *(float4*)&sm[SQU_OFF + row * QSTR + c4 * 4] =
            f2tf4(make_float4(q.x + u4.x, q.y + u4.y, q.z + u4.z, q.w + u4.w));
    }
    for (int idx = tid; idx < (TI + 1) * 8; idx += 256) {
        int row = idx >> 3, c4 = idx & 7;
        int g = I0 + row;
        float4 o = make_float4(0.f, 0.f, 0.f, 0.f);
        if (g < LL) {
            float4 q  = *(const float4*)(qbase + (size_t)g * DH + c4 * 4);
            float4 v4 = *(const float4*)(vb + h * DH + c4 * 4);
            o = f2tf4(make_float4(q.x + v4.x, q.y + v4.y, q.z + v4.z, q.w + v4.w));
        }
        *(float4*)&sm[SQV_OFF + row * QSTR + c4 * 4] = o;
    }
    // ---- stage prologue band cols r in [-I0-64, -I0-1] into Pbuf[1] (all threads)
    {
        const int r0 = -I0 - 64;
        for (int idx = tid; idx < 64 * 8; idx += 256) {
            int t = idx >> 3, c4 = idx & 7;
            int r = r0 + t;
            float4 pv = make_float4(0.f, 0.f, 0.f, 0.f);
            if (r <= 0) { if (r >= 1 - LL) pv = *(const float4*)(pbase + (size_t)(LL - 1 + r) * DH + c4 * 4); }
            else if (r >= 2 && r <= LL + 1) pv = *(const float4*)(pbase + (size_t)(r - 2) * DH + c4 * 4);
            *(float4*)&sm[PbufOff[1] + t * QSTR + c4 * 4] = pv;
        }
    }
    __syncthreads();

    if (warp < 4) {
        // ========================= PRODUCER =========================
        const int pw = warp;
        const int g = lane >> 2, tq = lane & 3;

        // cp issue helpers (128 producer threads)
        auto issueKP = [&](int J0k, int J0p, int nb) {
#pragma unroll
            for (int i = 0; i < 4; i++) {
                int idx = tid + i * 128;
                int row = idx >> 3, c4 = idx & 7;
                cp16(smb + (uint32_t)((KbufOff[nb] + row * QSTR + c4 * 4) * 4),
                     kbase + (size_t)(J0k + row) * DH + c4 * 4, 16);
                int r = J0p - I0 + row;
                const float* psrc = pbase;
                int sz = 0;
                if (r <= 0) { if (r >= 1 - LL) { psrc = pbase + (size_t)(LL - 1 + r) * DH + c4 * 4; sz = 16; } }
                else if (r >= 2 && r <= LL + 1) { psrc = pbase + (size_t)(r - 2) * DH + c4 * 4; sz = 16; }
                cp16(smb + (uint32_t)((PbufOff[nb] + row * QSTR + c4 * 4) * 4), psrc, sz);
            }
        };
        auto issueV = [&](int J0k, int nb) {
#pragma unroll
            for (int i = 0; i < 4; i++) {
                int idx = tid + i * 128;
                int row = idx >> 3, c4 = idx & 7;
                cp16(smb + (uint32_t)((VbufOff[nb] + row * QSTR + c4 * 4) * 4),
                     vbase + (size_t)(J0k + row) * DH + c4 * 4, 16);
            }
        };

        // kick off tile-0 loads
        issueKP(0, 0, 0); cp_commit();   // A(0)
        issueV(0, 0);     cp_commit();   // B(0)

        // hoist Qu AND Qv fragments for rows 16pw..16pw+15
        uint32_t afu[4][4], afv[4][4];
#pragma unroll
        for (int kt = 0; kt < 4; kt++) {
            int c = kt * 8 + tq;
            int r0 = (16 * pw + g) * QSTR;
            int r1 = (16 * pw + g + 8) * QSTR;
            afu[kt][0] = __float_as_uint(sm[SQU_OFF + r0 + c]);
            afu[kt][1] = __float_as_uint(sm[SQU_OFF + r1 + c]);
            afu[kt][2] = __float_as_uint(sm[SQU_OFF + r0 + c + 4]);
            afu[kt][3] = __float_as_uint(sm[SQU_OFF + r1 + c + 4]);
            afv[kt][0] = __float_as_uint(sm[SQV_OFF + r0 + c]);
            afv[kt][1] = __float_as_uint(sm[SQV_OFF + r1 + c]);
            afv[kt][2] = __float_as_uint(sm[SQV_OFF + r0 + c + 4]);
            afv[kt][3] = __float_as_uint(sm[SQV_OFF + r1 + c + 4]);
        }

        // prologue W-mma from Pbuf[1] -> sW direct (consumers not reading yet)
        {
            const int slotbase = ((-I0 - 64) + 4096) & (RING - 1);
            const float* Pb = sm + PbufOff[1];
#pragma unroll
            for (int nt = 0; nt < 8; nt++) {
                float d0 = 0.f, d1 = 0.f, d2 = 0.f, d3 = 0.f;
#pragma unroll
                for (int kt = 0; kt < 4; kt++) {
                    int bn = nt * 8 + g;
                    int bk = kt * 8 + tq;
                    uint32_t b0 = __float_as_uint(Pb[bn * QSTR + bk]);
                    uint32_t b1 = __float_as_uint(Pb[bn * QSTR + bk + 4]);
                    mma_tf32(d0, d1, d2, d3, afv[kt][0], afv[kt][1], afv[kt][2], afv[kt][3], b0, b1);
                }
                int wr = 16 * pw + g;
                int wc = slotbase + nt * 8 + 2 * tq;
                *(float2*)&sW[wr * WSTR + wc]       = make_float2(d0, d1);
                *(float2*)&sW[(wr + 8) * WSTR + wc] = make_float2(d2, d3);
            }
            if (tid < 64) {
                float s = 0.f;
#pragma unroll
                for (int c = 0; c < DH; c++)
                    s += sm[SQV_OFF + TI * QSTR + c] * Pb[tid * QSTR + c];
                sW[TI * WSTR + slotbase + tid] = s;
            }
        }

        // main producer loop
        for (int t = 0; t < 32; t++) {
            const int J0 = t * TJ;
            const int Jn = J0 + TJ;
            const int Jc = (Jn < LL) ? Jn : (LL - TJ);   // K/V clamp (P guarded)

            issueKP(Jc, Jn, (t + 1) & 1); cp_commit();   // A(t+1)
            cp_wait<2>();                                 // A(t) complete

            const float* Kb = sm + KbufOff[t & 1];
            const float* Pb = sm + PbufOff[t & 1];

            float sreg[8][4], wreg[8][4];
#pragma unroll
            for (int nt = 0; nt < 8; nt++) {
                float s0 = 0.f, s1 = 0.f, s2 = 0.f, s3 = 0.f;
                float w0 = 0.f, w1 = 0.f, w2 = 0.f, w3 = 0.f;
#pragma unroll
                for (int kt = 0; kt < 4; kt++) {
                    int bn = nt * 8 + g;
                    int bk = kt * 8 + tq;
                    uint32_t kb0 = __float_as_uint(Kb[bn * QSTR + bk]);
                    uint32_t kb1 = __float_as_uint(Kb[bn * QSTR + bk + 4]);
                    mma_tf32(s0, s1, s2, s3, afu[kt][0], afu[kt][1], afu[kt][2], afu[kt][3], kb0, kb1);
                    uint32_t pb0 = __float_as_uint(Pb[bn * QSTR + bk]);
                    uint32_t pb1 = __float_as_uint(Pb[bn * QSTR + bk + 4]);
                    mma_tf32(w0, w1, w2, w3, afv[kt][0], afv[kt][1], afv[kt][2], afv[kt][3], pb0, pb1);
                }
                sreg[nt][0] = s0; sreg[nt][1] = s1; sreg[nt][2] = s2; sreg[nt][3] = s3;
                wreg[nt][0] = w0; wreg[nt][1] = w1; wreg[nt][2] = w2; wreg[nt][3] = w3;
            }
            float ereg = 0.f;
            if (tid < 64) {
#pragma unroll
                for (int c = 0; c < DH; c++)
                    ereg += sm[SQV_OFF + TI * QSTR + c] * Pb[tid * QSTR + c];
            }

            if (t > 0) BARSYNC(1, 256);                  // sS / ring-slots free

            issueV(Jc, (t + 1) & 1); cp_commit();        // B(t+1)
            cp_wait<2>();                                 // B(t) complete (V for consumers)

            const int slotbase = ((J0 - I0) + 4096) & (RING - 1);
            const int sr = 16 * pw + g;
#pragma unroll
            for (int nt = 0; nt < 8; nt++) {
                int sc = nt * 8 + 2 * tq;
                *(float2*)&sS[sr * SSTR + sc]       = make_float2(sreg[nt][0], sreg[nt][1]);
                *(float2*)&sS[(sr + 8) * SSTR + sc] = make_float2(sreg[nt][2], sreg[nt][3]);
                int wc = slotbase + nt * 8 + 2 * tq;
                *(float2*)&sW[sr * WSTR + wc]       = make_float2(wreg[nt][0], wreg[nt][1]);
                *(float2*)&sW[(sr + 8) * WSTR + wc] = make_float2(wreg[nt][2], wreg[nt][3]);
            }
            if (tid < 64) sW[TI * WSTR + slotbase + tid] = ereg;

            BARSYNC(2, 256);                             // publish S(t)/W(t)/V(t)
        }
        // producer exits
    } else {
        // ========================= CONSUMER =========================
        const int cw = warp - 4;
        const int ctid = tid - 128;
        const int srow = ctid >> 1;
        const int half = ctid & 1;
        const int g = lane >> 2, tq = lane & 3;
        const int qi = I0 + srow;

        float dacc[4][4];
#pragma unroll
        for (int nt = 0; nt < 4; nt++)
#pragma unroll
            for (int j = 0; j < 4; j++) dacc[nt][j] = 0.f;
        float rmax = -INFINITY, rsum = 0.f;

        for (int t = 0; t < 32; t++) {
            const int J0 = t * TJ;
            BARSYNC(2, 256);                             // wait S(t) ready

            // ---- softmax: thread (srow, half) owns 32 columns
            {
                float s[32];
#pragma unroll
                for (int k4 = 0; k4 < 8; k4++) {
                    float4 s4 = *(const float4*)&sS[srow * SSTR + half * 32 + k4 * 4];
                    s[k4 * 4 + 0] = s4.x; s[k4 * 4 + 1] = s4.y;
                    s[k4 * 4 + 2] = s4.z; s[k4 * 4 + 3] = s4.w;
                }
                float cmax = -INFINITY;
#pragma unroll
                for (int tt = 0; tt < 32; tt++) {
                    int jj = half * 32 + tt;
                    int r = J0 + jj - qi;
                    int slot = (r + 4096) & (RING - 1);
                    int wrow = srow + (r >= 1);
                    s[tt] = (s[tt] + sW[wrow * WSTR + slot]) * SCALE;
                    cmax = fmaxf(cmax, s[tt]);
                }
                cmax = fmaxf(cmax, __shfl_xor_sync(0xffffffffu, cmax, 1));
                float mnew = fmaxf(rmax, cmax);
                float corr = __expf(rmax - mnew);        // first tile: exp(-inf)=0
                float csum = 0.f;
#pragma unroll
                for (int tt = 0; tt < 32; tt++) {
                    float w = f2tf(__expf(s[tt] - mnew));
                    s[tt] = w;
                    csum += w;
                }
                csum += __shfl_xor_sync(0xffffffffu, csum, 1);
                rsum = rsum * corr + csum;
                rmax = mnew;
#pragma unroll
                for (int k4 = 0; k4 < 8; k4++)
                    *(float4*)&sS[srow * SSTR + half * 32 + k4 * 4] =
                        make_float4(s[k4 * 4], s[k4 * 4 + 1], s[k4 * 4 + 2], s[k4 * 4 + 3]);
                if (half == 0) sCorr[srow] = corr;
            }
            BARSYNC(3, 128);                             // consumer-internal

            // ---- PV MMA: rows 16cw.., all 32 channels
            {
                const float* Vb = sm + VbufOff[t & 1];
                const int prow = 16 * cw + g;
                float c0 = sCorr[prow];
                float c1 = sCorr[prow + 8];
#pragma unroll
                for (int nt = 0; nt < 4; nt++) {
                    dacc[nt][0] *= c0; dacc[nt][1] *= c0;
                    dacc[nt][2] *= c1; dacc[nt][3] *= c1;
                }
#pragma unroll
                for (int kt = 0; kt < 8; kt++) {
                    int c = kt * 8 + tq;
                    uint32_t a0 = __float_as_uint(sS[prow * SSTR + c]);
                    uint32_t a1 = __float_as_uint(sS[(prow + 8) * SSTR + c]);
                    uint32_t a2 = __float_as_uint(sS[prow * SSTR + c + 4]);
                    uint32_t a3 = __float_as_uint(sS[(prow + 8) * SSTR + c + 4]);
#pragma unroll
                    for (int nt = 0; nt < 4; nt++) {
                        int bn = nt * 8 + g;
                        uint32_t b0 = __float_as_uint(Vb[c * QSTR + bn]);
                        uint32_t b1 = __float_as_uint(Vb[(c + 4) * QSTR + bn]);
                        mma_tf32(dacc[nt][0], dacc[nt][1], dacc[nt][2], dacc[nt][3],
                                 a0, a1, a2, a3, b0, b1);
                    }
                }
            }
            if (t < 31) BARSYNC(1, 256);                 // release sS / ring slots
        }

        // ---- finalize (consumers only; producers have exited)
        BARSYNC(3, 128);
        if (half == 0) sCorr[srow] = 1.f / rsum;
        BARSYNC(3, 128);
        {
            const int prow = 16 * cw + g;
            float i0v = sCorr[prow];
            float i1v = sCorr[prow + 8];
            float* ob = ctx + (size_t)(b * HH + h) * LL * DH;
#pragma unroll
            for (int nt = 0; nt < 4; nt++) {
                int sc = nt * 8 + 2 * tq;
                *(float2*)(ob + (size_t)(I0 + prow) * DH + sc) =
                    make_float2(f2tf(dacc[nt][0] * i0v), f2tf(dacc[nt][1] * i0v));
                *(float2*)(ob + (size_t)(I0 + prow + 8) * DH + sc) =
                    make_float2(f2tf(dacc[nt][2] * i1v), f2tf(dacc[nt][3] * i1v));
            }
        }
    }
}

// ---------------------------------------------------------------------------
extern "C" void kernel_launch(void* const* d_in, const int* in_sizes, int n_in,
                              void* d_out, int out_size)
{
    const float* query = (const float*)d_in[0];
    const float* key   = (const float*)d_in[1];
    const float* value = (const float*)d_in[2];
    const float* pos   = (const float*)d_in[3];
    const float* Wq    = (const float*)d_in[4];
    const float* bq    = (const float*)d_in[5];
    const float* Wk    = (const float*)d_in[6];
    const float* bk    = (const float*)d_in[7];
    const float* Wv    = (const float*)d_in[8];
    const float* bv    = (const float*)d_in[9];
    const float* Wp    = (const float*)d_in[10];
    const float* ub    = (const float*)d_in[11];
    const float* vb    = (const float*)d_in[12];
    const float* Wo    = (const float*)d_in[13];
    const float* bo    = (const float*)d_in[14];

    float *pq, *pk, *pv, *pp, *pctx;
    cudaGetSymbolAddress((void**)&pq,   g_q);
    cudaGetSymbolAddress((void**)&pk,   g_k);
    cudaGetSymbolAddress((void**)&pv,   g_v);
    cudaGetSymbolAddress((void**)&pp,   g_p);
    cudaGetSymbolAddress((void**)&pctx, g_ctx);

    static int attr_set = 0;
    if (!attr_set) {
        cudaFuncSetAttribute(attn_mma, cudaFuncAttributeMaxDynamicSharedMemorySize, SMEM_BYTES);
        cudaFuncSetAttribute(qkvp_gemm, cudaFuncAttributeMaxDynamicSharedMemorySize, GSMEM_BYTES);
        cudaFuncSetAttribute(wo_gemm, cudaFuncAttributeMaxDynamicSharedMemorySize, GSMEM_BYTES);
        attr_set = 1;
    }

    preround<<<dim3(DM * DM / 1024, 1, 5), 256>>>(Wq, Wk, Wv, Wp, Wo);

    qkvp_gemm<<<dim3(DM / TGN, (BB * LL) / TGM, 4), 256, GSMEM_BYTES>>>(
        query, key, value, pos, bq, bk, bv, pq, pk, pv, pp);

    attn_mma<<<dim3(LL / TI, HH, BB), 256, SMEM_BYTES>>>(pq, pk, pv, pp, ub, vb, pctx);

    wo_gemm<<<dim3(DM / TGN, (BB * LL) / TGM), 256, GSMEM_BYTES>>>(
        pctx, bo, (float*)d_out);
}

// round 11
// speedup vs baseline: 5.5650x; 1.3260x over previous
#include <cuda_runtime.h>
#include <cuda_fp16.h>
#include <math.h>
#include <stdint.h>

#define BB 2
#define LL 2048
#define HH 16
#define DH 32
#define DM 512
#define SCALE 0.044194173824159216f  /* 1/sqrt(512) */

__device__ float  g_q[BB*HH*LL*DH];
__device__ __half g_kh[BB*HH*LL*DH];
__device__ __half g_vh[BB*HH*LL*DH];   // transposed [b,h,dh,l]
__device__ __half g_ph[HH*LL*DH];
__device__ float  g_ctx[BB*HH*LL*DH];
__device__ float  g_wbuf[5*DM*DM];     // pre-rounded Wq,Wk,Wv,Wp,Wo

// round-to-nearest tf32
__device__ __forceinline__ uint32_t f2tfu(float x) {
    uint32_t u;
    asm("cvt.rna.tf32.f32 %0, %1;" : "=r"(u) : "f"(x));
    return u;
}
__device__ __forceinline__ float f2tf(float x) { return __uint_as_float(f2tfu(x)); }
__device__ __forceinline__ float4 f2tf4(float4 v) {
    return make_float4(f2tf(v.x), f2tf(v.y), f2tf(v.z), f2tf(v.w));
}

__device__ __forceinline__ void mma_tf32(float& d0, float& d1, float& d2, float& d3,
                                         uint32_t a0, uint32_t a1, uint32_t a2, uint32_t a3,
                                         uint32_t b0, uint32_t b1) {
    asm volatile(
        "mma.sync.aligned.m16n8k8.row.col.f32.tf32.tf32.f32 "
        "{%0,%1,%2,%3}, {%4,%5,%6,%7}, {%8,%9}, {%0,%1,%2,%3};\n"
        : "+f"(d0), "+f"(d1), "+f"(d2), "+f"(d3)
        : "r"(a0), "r"(a1), "r"(a2), "r"(a3), "r"(b0), "r"(b1));
}
__device__ __forceinline__ void mma_f16(float& d0, float& d1, float& d2, float& d3,
                                        uint32_t a0, uint32_t a1, uint32_t a2, uint32_t a3,
                                        uint32_t b0, uint32_t b1) {
    asm volatile(
        "mma.sync.aligned.m16n8k16.row.col.f32.f16.f16.f32 "
        "{%0,%1,%2,%3}, {%4,%5,%6,%7}, {%8,%9}, {%0,%1,%2,%3};\n"
        : "+f"(d0), "+f"(d1), "+f"(d2), "+f"(d3)
        : "r"(a0), "r"(a1), "r"(a2), "r"(a3), "r"(b0), "r"(b1));
}

__device__ __forceinline__ void cp16(uint32_t dst, const void* src, int szbytes) {
    asm volatile("cp.async.cg.shared.global [%0], [%1], 16, %2;\n"
                 :: "r"(dst), "l"(src), "r"(szbytes));
}
__device__ __forceinline__ void cp_commit() {
    asm volatile("cp.async.commit_group;\n" ::: "memory");
}
template<int N>
__device__ __forceinline__ void cp_wait() {
    asm volatile("cp.async.wait_group %0;\n" :: "n"(N) : "memory");
}
#define BARSYNC(id, cnt) asm volatile("bar.sync %0, %1;" :: "r"(id), "r"(cnt) : "memory")

// ---------------------------------------------------------------------------
// preround: tf32-round weight matrices once. grid (256,1,5)
// ---------------------------------------------------------------------------
__global__ __launch_bounds__(256)
void preround(const float* __restrict__ w0, const float* __restrict__ w1,
              const float* __restrict__ w2, const float* __restrict__ w3,
              const float* __restrict__ w4)
{
    const float* src[5] = {w0, w1, w2, w3, w4};
    int z = blockIdx.z;
    int i = (blockIdx.x * 256 + threadIdx.x) * 4;
    float4 v = *(const float4*)(src[z] + i);
    *(float4*)(g_wbuf + z * DM * DM + i) = f2tf4(v);
}

// ---------------------------------------------------------------------------
// tf32 GEMM core, cp.async double-buffered. W pre-rounded.
// omode: 0 fp32 [M,512]; 1 fp32 head layout; 2 half head layout; 3 half V^T
// ---------------------------------------------------------------------------
#define TGM 128
#define TGN 64
#define TGK 32
#define GASTR 36
#define GBSTR 36
#define GSMEM_FLOATS (2 * (TGM * GASTR + TGN * GBSTR))
#define GSMEM_BYTES (GSMEM_FLOATS * 4)   /* 55296 */

template<int AROUND>
__device__ __forceinline__ void gemm_core(
    const float* __restrict__ A, const float* __restrict__ W,
    const float* __restrict__ bias, void* __restrict__ Cv,
    int amode, int omode, float* smem)
{
    const int tid  = threadIdx.x;
    const int lane = tid & 31;
    const int warp = tid >> 5;
    const int g = lane >> 2;
    const int t = lane & 3;
    const int m0 = blockIdx.y * TGM;
    const int n0 = blockIdx.x * TGN;

    float* As = smem;
    float* Bs = smem + 2 * TGM * GASTR;
    const uint32_t smb = (uint32_t)__cvta_generic_to_shared(smem);

    float acc[8][4];
#pragma unroll
    for (int nt = 0; nt < 8; nt++)
#pragma unroll
        for (int j = 0; j < 4; j++) acc[nt][j] = 0.f;

    auto issue = [&](int k0, int buf) {
#pragma unroll
        for (int i = 0; i < 4; i++) {
            int idx = tid + i * 256;
            int row = idx >> 3, c4 = idx & 7;
            int gm = m0 + row;
            const float* src;
            if (amode == 0) {
                src = A + (size_t)gm * DM + k0 + c4 * 4;
            } else {
                int b = gm >> 11, l = gm & (LL - 1);
                int head = k0 >> 5;
                src = A + (((size_t)b * HH + head) * LL + l) * DH + c4 * 4;
            }
            cp16(smb + (uint32_t)((buf * TGM * GASTR + row * GASTR + c4 * 4) * 4), src, 16);
        }
#pragma unroll
        for (int i = 0; i < 2; i++) {
            int idx = tid + i * 256;
            int row = idx >> 3, c4 = idx & 7;
            const float* src = W + (size_t)(n0 + row) * DM + k0 + c4 * 4;
            cp16(smb + (uint32_t)((2 * TGM * GASTR + buf * TGN * GBSTR + row * GBSTR + c4 * 4) * 4), src, 16);
        }
    };

    issue(0, 0);
    cp_commit();

    for (int c = 0; c < 16; c++) {
        cp_wait<0>();
        __syncthreads();
        if (c < 15) issue((c + 1) * TGK, (c + 1) & 1);
        cp_commit();

        const float* Ab = As + (c & 1) * TGM * GASTR;
        const float* Bb = Bs + (c & 1) * TGN * GBSTR;
#pragma unroll
        for (int kt = 0; kt < 4; kt++) {
            int cc = kt * 8 + t;
            int ar = warp * 16 + g;
            uint32_t a0, a1, a2, a3;
            if (AROUND) {
                a0 = f2tfu(Ab[ar * GASTR + cc]);
                a1 = f2tfu(Ab[(ar + 8) * GASTR + cc]);
                a2 = f2tfu(Ab[ar * GASTR + cc + 4]);
                a3 = f2tfu(Ab[(ar + 8) * GASTR + cc + 4]);
            } else {
                a0 = __float_as_uint(Ab[ar * GASTR + cc]);
                a1 = __float_as_uint(Ab[(ar + 8) * GASTR + cc]);
                a2 = __float_as_uint(Ab[ar * GASTR + cc + 4]);
                a3 = __float_as_uint(Ab[(ar + 8) * GASTR + cc + 4]);
            }
#pragma unroll
            for (int nt = 0; nt < 8; nt++) {
                uint32_t b0 = __float_as_uint(Bb[(nt * 8 + g) * GBSTR + cc]);
                uint32_t b1 = __float_as_uint(Bb[(nt * 8 + g) * GBSTR + cc + 4]);
                mma_tf32(acc[nt][0], acc[nt][1], acc[nt][2], acc[nt][3],
                         a0, a1, a2, a3, b0, b1);
            }
        }
    }

    const int sr = warp * 16 + g;
    const int gm = m0 + sr;
    const int bb = gm >> 11, l = gm & (LL - 1);
#pragma unroll
    for (int nt = 0; nt < 8; nt++) {
        int sc = nt * 8 + 2 * t;
        int n  = n0 + sc;
        float b0v = bias ? bias[n]     : 0.f;
        float b1v = bias ? bias[n + 1] : 0.f;
        float2 p0 = make_float2(acc[nt][0] + b0v, acc[nt][1] + b1v);
        float2 p1 = make_float2(acc[nt][2] + b0v, acc[nt][3] + b1v);
        if (omode == 0) {
            float* Cf = (float*)Cv;
            *(float2*)(Cf + (size_t)gm * DM + n)       = p0;
            *(float2*)(Cf + (size_t)(gm + 8) * DM + n) = p1;
        } else if (omode == 1) {
            float* Cf = (float*)Cv;
            int head = n >> 5, d = n & 31;
            float* base = Cf + (((size_t)bb * HH + head) * LL + l) * DH + d;
            *(float2*)(base)          = p0;
            *(float2*)(base + 8 * DH) = p1;
        } else if (omode == 2) {
            __half* Ch = (__half*)Cv;
            int head = n >> 5, d = n & 31;
            __half* base = Ch + (((size_t)bb * HH + head) * LL + l) * DH + d;
            __half2 h0 = __floats2half2_rn(p0.x, p0.y);
            __half2 h1 = __floats2half2_rn(p1.x, p1.y);
            *(__half2*)(base)          = h0;
            *(__half2*)(base + 8 * DH) = h1;
        } else {
            __half* Ch = (__half*)Cv;
            int head = n >> 5, d = n & 31;
            __half* base = Ch + (((size_t)bb * HH + head) * DH + d) * LL + l;
            base[0]      = __float2half_rn(p0.x);
            base[LL]     = __float2half_rn(p0.y);
            base[8]      = __float2half_rn(p1.x);
            base[LL + 8] = __float2half_rn(p1.y);
        }
    }
}

__global__ __launch_bounds__(256)
void qkvp_gemm(const float* __restrict__ q, const float* __restrict__ k,
               const float* __restrict__ v, const float* __restrict__ p,
               const float* __restrict__ bq, const float* __restrict__ bk,
               const float* __restrict__ bv,
               float* __restrict__ oq)
{
    extern __shared__ float smem[];
    int z = blockIdx.z;
    if (z == 3 && blockIdx.y >= LL / TGM) return;
    const float* A = (z == 0) ? q : (z == 1) ? k : (z == 2) ? v : p;
    const float* W = g_wbuf + z * DM * DM;
    const float* b = (z == 0) ? bq : (z == 1) ? bk : (z == 2) ? bv : nullptr;
    void* C; int omode;
    if (z == 0)      { C = oq;   omode = 1; }
    else if (z == 1) { C = g_kh; omode = 2; }
    else if (z == 2) { C = g_vh; omode = 3; }
    else             { C = g_ph; omode = 2; }
    gemm_core<1>(A, W, b, C, 0, omode, smem);
}

__global__ __launch_bounds__(256)
void wo_gemm(const float* __restrict__ A, const float* __restrict__ bias,
             float* __restrict__ C)
{
    extern __shared__ float smem[];
    gemm_core<0>(A, g_wbuf + 4 * DM * DM, bias, C, 1, 0, smem);
}

// ---------------------------------------------------------------------------
// Warp-specialized ring-band attention, fp16 operands (fp32 accumulate).
// Shift: r=j-i; r<=0 -> p[L-1+r]; r==1 -> 0; r>=2 -> row i+1 uses p[r-2]
// ---------------------------------------------------------------------------
#define TI 64
#define TJ 64
#define HS 40    /* half stride for [j][dh] tiles (80B) */
#define HW 20    /* b32-word stride */
#define VS 72    /* half stride for V^T [ch][j] (144B) */
#define VW 36
#define PWW 38   /* weight buffer b32-word stride (76 halfs) */
#define SSTR 68
#define WSTR 132
#define RING 128

#define QU_B 0        /* 64x80B  = 5120  (reused: K buf1) */
#define QV_B 5120     /* 65x80B  = 5200  (rows 0..57 reused: V buf1) */
#define K0_B 10320    /* 5120 */
#define V0_B 15440    /* 32x144B = 4608 */
#define P0_B 20048    /* 5120 */
#define P1_B 25168    /* 5120 */
#define SS_B 30288    /* 64x68x4 = 17408 */
#define PW_B 47696    /* 64x76x2 = 9728 */
#define SW_B 57424    /* 65x132x4 = 34320 */
#define SC_B 91744    /* 256 */
#define SMEM_BYTES 92000

__global__ __launch_bounds__(256, 2)
void attn_mma(const float* __restrict__ qd, const __half* __restrict__ kd,
              const __half* __restrict__ vd, const __half* __restrict__ pd,
              const float* __restrict__ ub, const float* __restrict__ vb,
              float* __restrict__ ctx)
{
    extern __shared__ char smc[];
    float* sS    = (float*)(smc + SS_B);
    float* sW    = (float*)(smc + SW_B);
    float* sCorr = (float*)(smc + SC_B);
    const uint32_t smb = (uint32_t)__cvta_generic_to_shared(smc);

    const int tid  = threadIdx.x;
    const int lane = tid & 31;
    const int warp = tid >> 5;
    const int I0 = blockIdx.x * TI;
    const int h = blockIdx.y, b = blockIdx.z;

    const float*  qbase  = qd + (size_t)(b * HH + h) * LL * DH;
    const __half* kbase  = kd + (size_t)(b * HH + h) * LL * DH;
    const __half* vtbase = vd + (size_t)(b * HH + h) * DH * LL;
    const __half* pbase  = pd + (size_t)h * LL * DH;

    const int KbufB[2] = {K0_B, QU_B};
    const int VbufB[2] = {V0_B, QV_B};
    const int PbufB[2] = {P0_B, P1_B};

    // ---- stage Qu (64 rows) and Qv (65 rows) as rn-fp16
    for (int idx = tid; idx < TI * 8; idx += 256) {
        int row = idx >> 3, c4 = idx & 7;
        float4 q  = *(const float4*)(qbase + (size_t)(I0 + row) * DH + c4 * 4);
        float4 u4 = *(const float4*)(ub + h * DH + c4 * 4);
        __half2 h0 = __floats2half2_rn(q.x + u4.x, q.y + u4.y);
        __half2 h1 = __floats2half2_rn(q.z + u4.z, q.w + u4.w);
        *(uint2*)(smc + QU_B + row * 80 + c4 * 8) =
            make_uint2(*(uint32_t*)&h0, *(uint32_t*)&h1);
    }
    for (int idx = tid; idx < (TI + 1) * 8; idx += 256) {
        int row = idx >> 3, c4 = idx & 7;
        int g = I0 + row;
        uint2 o = make_uint2(0u, 0u);
        if (g < LL) {
            float4 q  = *(const float4*)(qbase + (size_t)g * DH + c4 * 4);
            float4 v4 = *(const float4*)(vb + h * DH + c4 * 4);
            __half2 h0 = __floats2half2_rn(q.x + v4.x, q.y + v4.y);
            __half2 h1 = __floats2half2_rn(q.z + v4.z, q.w + v4.w);
            o = make_uint2(*(uint32_t*)&h0, *(uint32_t*)&h1);
        }
        *(uint2*)(smc + QV_B + row * 80 + c4 * 8) = o;
    }
    // ---- stage prologue band cols r in [-I0-64, -I0-1] into P1 (half)
    {
        const int r0 = -I0 - 64;
        int row = tid >> 2, c4 = tid & 3;
        int r = r0 + row;
        uint4 v = make_uint4(0u, 0u, 0u, 0u);
        if (r <= 0) { if (r >= 1 - LL) v = *(const uint4*)(pbase + (size_t)(LL - 1 + r) * DH + c4 * 8); }
        else if (r >= 2 && r <= LL + 1) v = *(const uint4*)(pbase + (size_t)(r - 2) * DH + c4 * 8);
        *(uint4*)(smc + P1_B + row * 80 + c4 * 16) = v;
    }
    __syncthreads();

    if (warp < 4) {
        // ========================= PRODUCER =========================
        const int pw = warp;
        const int g = lane >> 2, tq = lane & 3;

        auto issueKP = [&](int J0k, int J0p, int nb) {
#pragma unroll
            for (int i = 0; i < 2; i++) {
                int idx = tid + i * 128;
                int row = idx >> 2, c4 = idx & 3;
                cp16(smb + (uint32_t)(KbufB[nb] + row * 80 + c4 * 16),
                     kbase + (size_t)(J0k + row) * DH + c4 * 8, 16);
                int r = J0p - I0 + row;
                const __half* psrc = pbase;
                int sz = 0;
                if (r <= 0) { if (r >= 1 - LL) { psrc = pbase + (size_t)(LL - 1 + r) * DH + c4 * 8; sz = 16; } }
                else if (r >= 2 && r <= LL + 1) { psrc = pbase + (size_t)(r - 2) * DH + c4 * 8; sz = 16; }
                cp16(smb + (uint32_t)(PbufB[nb] + row * 80 + c4 * 16), psrc, sz);
            }
        };
        auto issueV = [&](int J0k, int nb) {
#pragma unroll
            for (int i = 0; i < 2; i++) {
                int idx = tid + i * 128;
                int ch = idx >> 3, c8 = idx & 7;
                cp16(smb + (uint32_t)(VbufB[nb] + ch * 144 + c8 * 16),
                     vtbase + (size_t)ch * LL + J0k + c8 * 8, 16);
            }
        };

        issueKP(0, 0, 0); cp_commit();   // A(0)
        issueV(0, 0);     cp_commit();   // B(0)

        // hoist fp16 fragments (2 k-steps of k16)
        const uint32_t* QuW = (const uint32_t*)(smc + QU_B);
        const uint32_t* QvW = (const uint32_t*)(smc + QV_B);
        uint32_t afu[2][4], afv[2][4];
#pragma unroll
        for (int kt = 0; kt < 2; kt++) {
            int w0 = (16 * pw + g) * HW + tq + 8 * kt;
            int w1 = (16 * pw + g + 8) * HW + tq + 8 * kt;
            afu[kt][0] = QuW[w0];     afu[kt][1] = QuW[w1];
            afu[kt][2] = QuW[w0 + 4]; afu[kt][3] = QuW[w1 + 4];
            afv[kt][0] = QvW[w0];     afv[kt][1] = QvW[w1];
            afv[kt][2] = QvW[w0 + 4]; afv[kt][3] = QvW[w1 + 4];
        }

        // prologue W-mma from P1
        {
            const int slotbase = ((-I0 - 64) + 4096) & (RING - 1);
            const uint32_t* Pw = (const uint32_t*)(smc + P1_B);
#pragma unroll
            for (int nt = 0; nt < 8; nt++) {
                float d0 = 0.f, d1 = 0.f, d2 = 0.f, d3 = 0.f;
#pragma unroll
                for (int kt = 0; kt < 2; kt++) {
                    int bw = (nt * 8 + g) * HW + tq + 8 * kt;
                    mma_f16(d0, d1, d2, d3, afv[kt][0], afv[kt][1], afv[kt][2], afv[kt][3],
                            Pw[bw], Pw[bw + 4]);
                }
                int wr = 16 * pw + g;
                int wc = slotbase + nt * 8 + 2 * tq;
                *(float2*)&sW[wr * WSTR + wc]       = make_float2(d0, d1);
                *(float2*)&sW[(wr + 8) * WSTR + wc] = make_float2(d2, d3);
            }
            if (tid < 64) {
                const __half* qv64 = (const __half*)(smc + QV_B + 64 * 80);
                const __half* pr   = (const __half*)(smc + P1_B + tid * 80);
                float s = 0.f;
#pragma unroll
                for (int c = 0; c < DH; c++)
                    s += __half2float(qv64[c]) * __half2float(pr[c]);
                sW[TI * WSTR + slotbase + tid] = s;
            }
        }
        BARSYNC(4, 128);   // all producers done reading QU/P1 before overwriting

        for (int t = 0; t < 32; t++) {
            const int J0 = t * TJ;
            const int Jn = J0 + TJ;
            const int Jc = (Jn < LL) ? Jn : (LL - TJ);

            issueKP(Jc, Jn, (t + 1) & 1); cp_commit();   // A(t+1)
            cp_wait<2>();                                 // A(t) done

            const uint32_t* Kw = (const uint32_t*)(smc + KbufB[t & 1]);
            const uint32_t* Pw = (const uint32_t*)(smc + PbufB[t & 1]);

            float sreg[8][4], wreg[8][4];
#pragma unroll
            for (int nt = 0; nt < 8; nt++) {
                float s0 = 0.f, s1 = 0.f, s2 = 0.f, s3 = 0.f;
                float w0 = 0.f, w1 = 0.f, w2 = 0.f, w3 = 0.f;
#pragma unroll
                for (int kt = 0; kt < 2; kt++) {
                    int bw = (nt * 8 + g) * HW + tq + 8 * kt;
                    mma_f16(s0, s1, s2, s3, afu[kt][0], afu[kt][1], afu[kt][2], afu[kt][3],
                            Kw[bw], Kw[bw + 4]);
                    mma_f16(w0, w1, w2, w3, afv[kt][0], afv[kt][1], afv[kt][2], afv[kt][3],
                            Pw[bw], Pw[bw + 4]);
                }
                sreg[nt][0] = s0; sreg[nt][1] = s1; sreg[nt][2] = s2; sreg[nt][3] = s3;
                wreg[nt][0] = w0; wreg[nt][1] = w1; wreg[nt][2] = w2; wreg[nt][3] = w3;
            }
            float ereg = 0.f;
            if (tid < 64) {
                const __half* qv64 = (const __half*)(smc + QV_B + 64 * 80);
                const __half* pr   = (const __half*)(smc + PbufB[t & 1] + tid * 80);
#pragma unroll
                for (int c = 0; c < DH; c++)
                    ereg += __half2float(qv64[c]) * __half2float(pr[c]);
            }

            if (t > 0) BARSYNC(1, 256);                  // sS / ring-slots free

            issueV(Jc, (t + 1) & 1); cp_commit();        // B(t+1)
            cp_wait<2>();                                 // B(t) done

            const int slotbase = ((J0 - I0) + 4096) & (RING - 1);
            const int sr = 16 * pw + g;
#pragma unroll
            for (int nt = 0; nt < 8; nt++) {
                int sc = nt * 8 + 2 * tq;
                *(float2*)&sS[sr * SSTR + sc]       = make_float2(sreg[nt][0], sreg[nt][1]);
                *(float2*)&sS[(sr + 8) * SSTR + sc] = make_float2(sreg[nt][2], sreg[nt][3]);
                int wc = slotbase + nt * 8 + 2 * tq;
                *(float2*)&sW[sr * WSTR + wc]       = make_float2(wreg[nt][0], wreg[nt][1]);
                *(float2*)&sW[(sr + 8) * WSTR + wc] = make_float2(wreg[nt][2], wreg[nt][3]);
            }
            if (tid < 64) sW[TI * WSTR + slotbase + tid] = ereg;

            BARSYNC(2, 256);                             // publish S(t)/W(t)/V(t)
        }
    } else {
        // ========================= CONSUMER =========================
        const int cw = warp - 4;
        const int ctid = tid - 128;
        const int srow = ctid >> 1;
        const int half = ctid & 1;
        const int g = lane >> 2, tq = lane & 3;
        const int qi = I0 + srow;

        uint32_t* pwW = (uint32_t*)(smc + PW_B);
        float dacc[4][4];
#pragma unroll
        for (int nt = 0; nt < 4; nt++)
#pragma unroll
            for (int j = 0; j < 4; j++) dacc[nt][j] = 0.f;
        float rmax = -INFINITY, rsum = 0.f;

        for (int t = 0; t < 32; t++) {
            const int J0 = t * TJ;
            BARSYNC(2, 256);                             // S(t) ready

            // ---- softmax: thread (srow, half) owns 32 columns
            {
                float s[32];
#pragma unroll
                for (int k4 = 0; k4 < 8; k4++) {
                    float4 s4 = *(const float4*)&sS[srow * SSTR + half * 32 + k4 * 4];
                    s[k4 * 4 + 0] = s4.x; s[k4 * 4 + 1] = s4.y;
                    s[k4 * 4 + 2] = s4.z; s[k4 * 4 + 3] = s4.w;
                }
                float cmax = -INFINITY;
#pragma unroll
                for (int tt = 0; tt < 32; tt++) {
                    int jj = half * 32 + tt;
                    int r = J0 + jj - qi;
                    int slot = (r + 4096) & (RING - 1);
                    int wrow = srow + (r >= 1);
                    s[tt] = (s[tt] + sW[wrow * WSTR + slot]) * SCALE;
                    cmax = fmaxf(cmax, s[tt]);
                }
                cmax = fmaxf(cmax, __shfl_xor_sync(0xffffffffu, cmax, 1));
                float mnew = fmaxf(rmax, cmax);
                float corr = __expf(rmax - mnew);        // first tile: exp(-inf)=0
                float csum = 0.f;
#pragma unroll
                for (int k2 = 0; k2 < 16; k2++) {
                    __half h0 = __float2half_rn(__expf(s[2 * k2]     - mnew));
                    __half h1 = __float2half_rn(__expf(s[2 * k2 + 1] - mnew));
                    csum += __half2float(h0) + __half2float(h1);
                    __half2 hh = __halves2half2(h0, h1);
                    pwW[srow * PWW + half * 16 + k2] = *(uint32_t*)&hh;
                }
                csum += __shfl_xor_sync(0xffffffffu, csum, 1);
                rsum = rsum * corr + csum;
                rmax = mnew;
                if (half == 0) sCorr[srow] = corr;
            }
            BARSYNC(3, 128);                             // consumer-internal

            // ---- PV MMA: rows 16cw.., all 32 channels, k=64 in 4 k16 steps
            {
                const uint32_t* Vw = (const uint32_t*)(smc + VbufB[t & 1]);
                const int prow = 16 * cw + g;
                float c0 = sCorr[prow];
                float c1 = sCorr[prow + 8];
#pragma unroll
                for (int nt = 0; nt < 4; nt++) {
                    dacc[nt][0] *= c0; dacc[nt][1] *= c0;
                    dacc[nt][2] *= c1; dacc[nt][3] *= c1;
                }
#pragma unroll
                for (int kt = 0; kt < 4; kt++) {
                    int aw0 = prow * PWW + tq + 8 * kt;
                    int aw1 = (prow + 8) * PWW + tq + 8 * kt;
                    uint32_t a0 = pwW[aw0], a1 = pwW[aw1];
                    uint32_t a2 = pwW[aw0 + 4], a3 = pwW[aw1 + 4];
#pragma unroll
                    for (int nt = 0; nt < 4; nt++) {
                        int bw = (nt * 8 + g) * VW + tq + 8 * kt;
                        mma_f16(dacc[nt][0], dacc[nt][1], dacc[nt][2], dacc[nt][3],
                                a0, a1, a2, a3, Vw[bw], Vw[bw + 4]);
                    }
                }
            }
            if (t < 31) BARSYNC(1, 256);                 // release sS / ring slots
        }

        // ---- finalize (consumers only)
        BARSYNC(3, 128);
        if (half == 0) sCorr[srow] = 1.f / rsum;
        BARSYNC(3, 128);
        {
            const int prow = 16 * cw + g;
            float i0v = sCorr[prow];
            float i1v = sCorr[prow + 8];
            float* ob = ctx + (size_t)(b * HH + h) * LL * DH;
#pragma unroll
            for (int nt = 0; nt < 4; nt++) {
                int sc = nt * 8 + 2 * tq;
                *(float2*)(ob + (size_t)(I0 + prow) * DH + sc) =
                    make_float2(f2tf(dacc[nt][0] * i0v), f2tf(dacc[nt][1] * i0v));
                *(float2*)(ob + (size_t)(I0 + prow + 8) * DH + sc) =
                    make_float2(f2tf(dacc[nt][2] * i1v), f2tf(dacc[nt][3] * i1v));
            }
        }
    }
}

// ---------------------------------------------------------------------------
extern "C" void kernel_launch(void* const* d_in, const int* in_sizes, int n_in,
                              void* d_out, int out_size)
{
    const float* query = (const float*)d_in[0];
    const float* key   = (const float*)d_in[1];
    const float* value = (const float*)d_in[2];
    const float* pos   = (const float*)d_in[3];
    const float* Wq    = (const float*)d_in[4];
    const float* bq    = (const float*)d_in[5];
    const float* Wk    = (const float*)d_in[6];
    const float* bk    = (const float*)d_in[7];
    const float* Wv    = (const float*)d_in[8];
    const float* bv    = (const float*)d_in[9];
    const float* Wp    = (const float*)d_in[10];
    const float* ub    = (const float*)d_in[11];
    const float* vb    = (const float*)d_in[12];
    const float* Wo    = (const float*)d_in[13];
    const float* bo    = (const float*)d_in[14];

    float *pq, *pctx;
    __half *pk, *pv, *pp;
    cudaGetSymbolAddress((void**)&pq,   g_q);
    cudaGetSymbolAddress((void**)&pk,   g_kh);
    cudaGetSymbolAddress((void**)&pv,   g_vh);
    cudaGetSymbolAddress((void**)&pp,   g_ph);
    cudaGetSymbolAddress((void**)&pctx, g_ctx);

    static int attr_set = 0;
    if (!attr_set) {
        cudaFuncSetAttribute(attn_mma, cudaFuncAttributeMaxDynamicSharedMemorySize, SMEM_BYTES);
        cudaFuncSetAttribute(qkvp_gemm, cudaFuncAttributeMaxDynamicSharedMemorySize, GSMEM_BYTES);
        cudaFuncSetAttribute(wo_gemm, cudaFuncAttributeMaxDynamicSharedMemorySize, GSMEM_BYTES);
        attr_set = 1;
    }

    preround<<<dim3(DM * DM / 1024, 1, 5), 256>>>(Wq, Wk, Wv, Wp, Wo);

    qkvp_gemm<<<dim3(DM / TGN, (BB * LL) / TGM, 4), 256, GSMEM_BYTES>>>(
        query, key, value, pos, bq, bk, bv, pq);

    attn_mma<<<dim3(LL / TI, HH, BB), 256, SMEM_BYTES>>>(pq, pk, pv, pp, ub, vb, pctx);

    wo_gemm<<<dim3(DM / TGN, (BB * LL) / TGM), 256, GSMEM_BYTES>>>(
        pctx, bo, (float*)d_out);
}

// round 12
// speedup vs baseline: 6.0202x; 1.0818x over previous
#include <cuda_runtime.h>
#include <cuda_fp16.h>
#include <math.h>
#include <stdint.h>

#define BB 2
#define LL 2048
#define HH 16
#define DH 32
#define DM 512
#define SCALE 0.044194173824159216f  /* 1/sqrt(512) */
#define QN (BB*LL*DM)                /* 2097152 */

__device__ float  g_q[BB*HH*LL*DH];
__device__ __half g_kh[BB*HH*LL*DH];
__device__ __half g_vh[BB*HH*LL*DH];   // transposed [b,h,dh,l]
__device__ __half g_ph[HH*LL*DH];
__device__ __half g_ctxh[BB*HH*LL*DH];
__device__ __half g_wh[5*DM*DM];       // fp16 Wq,Wk,Wv,Wp,Wo
__device__ __half g_inh[3*QN + LL*DM]; // fp16 query,key,value,pos

__device__ __forceinline__ void mma_f16(float& d0, float& d1, float& d2, float& d3,
                                        uint32_t a0, uint32_t a1, uint32_t a2, uint32_t a3,
                                        uint32_t b0, uint32_t b1) {
    asm volatile(
        "mma.sync.aligned.m16n8k16.row.col.f32.f16.f16.f32 "
        "{%0,%1,%2,%3}, {%4,%5,%6,%7}, {%8,%9}, {%0,%1,%2,%3};\n"
        : "+f"(d0), "+f"(d1), "+f"(d2), "+f"(d3)
        : "r"(a0), "r"(a1), "r"(a2), "r"(a3), "r"(b0), "r"(b1));
}

__device__ __forceinline__ void cp16(uint32_t dst, const void* src, int szbytes) {
    asm volatile("cp.async.cg.shared.global [%0], [%1], 16, %2;\n"
                 :: "r"(dst), "l"(src), "r"(szbytes));
}
__device__ __forceinline__ void cp_commit() {
    asm volatile("cp.async.commit_group;\n" ::: "memory");
}
template<int N>
__device__ __forceinline__ void cp_wait() {
    asm volatile("cp.async.wait_group %0;\n" :: "n"(N) : "memory");
}
#define BARSYNC(id, cnt) asm volatile("bar.sync %0, %1;" :: "r"(id), "r"(cnt) : "memory")

// ---------------------------------------------------------------------------
// preround: weights -> fp16. grid (256,1,5), 4 elems/thread
// ---------------------------------------------------------------------------
__global__ __launch_bounds__(256)
void preround(const float* __restrict__ w0, const float* __restrict__ w1,
              const float* __restrict__ w2, const float* __restrict__ w3,
              const float* __restrict__ w4)
{
    const float* src[5] = {w0, w1, w2, w3, w4};
    int z = blockIdx.z;
    int i = (blockIdx.x * 256 + threadIdx.x) * 4;
    float4 v = *(const float4*)(src[z] + i);
    __half2 h0 = __floats2half2_rn(v.x, v.y);
    __half2 h1 = __floats2half2_rn(v.z, v.w);
    *(uint2*)(g_wh + (size_t)z * DM * DM + i) =
        make_uint2(*(uint32_t*)&h0, *(uint32_t*)&h1);
}

// ---------------------------------------------------------------------------
// tohalf: inputs (query,key,value,pos) -> fp16 into g_inh. 8 elems/thread.
// ---------------------------------------------------------------------------
__global__ __launch_bounds__(256)
void tohalf(const float* __restrict__ q, const float* __restrict__ k,
            const float* __restrict__ v, const float* __restrict__ p)
{
    size_t i = ((size_t)blockIdx.x * 256 + threadIdx.x) * 8;
    const float* src; size_t off;
    if (i < (size_t)QN)          { src = q; off = i; }
    else if (i < (size_t)2 * QN) { src = k; off = i - QN; }
    else if (i < (size_t)3 * QN) { src = v; off = i - 2 * (size_t)QN; }
    else                         { src = p; off = i - 3 * (size_t)QN; }
    float4 a = *(const float4*)(src + off);
    float4 b = *(const float4*)(src + off + 4);
    __half2 h0 = __floats2half2_rn(a.x, a.y);
    __half2 h1 = __floats2half2_rn(a.z, a.w);
    __half2 h2 = __floats2half2_rn(b.x, b.y);
    __half2 h3 = __floats2half2_rn(b.z, b.w);
    *(uint4*)(g_inh + i) = make_uint4(*(uint32_t*)&h0, *(uint32_t*)&h1,
                                      *(uint32_t*)&h2, *(uint32_t*)&h3);
}

// ---------------------------------------------------------------------------
// fp16 GEMM core, cp.async double-buffered, m16n8k16, fp32 accum.
// A [M,512] half (amode 0) or head-layout half (amode 1); W [N,512] half.
// omode: 0 fp32 [M,512]; 1 fp32 head; 2 half head; 3 half V^T
// ---------------------------------------------------------------------------
#define TGM 128
#define TGN 64
#define TGK 32
#define HGW 20            /* 40-half (80B) row stride, words */
#define HA0 0             /* A buf0: 128*80 = 10240 */
#define HA1 10240
#define HB0 20480         /* B buf:  64*80 = 5120  */
#define HB1 25600
#define GSMEM_BYTES 30720

__device__ __forceinline__ void gemm_core_h(
    const __half* __restrict__ A, const __half* __restrict__ W,
    const float* __restrict__ bias, void* __restrict__ Cv,
    int amode, int omode, char* smc)
{
    const int tid  = threadIdx.x;
    const int lane = tid & 31;
    const int warp = tid >> 5;
    const int g = lane >> 2;
    const int t = lane & 3;
    const int m0 = blockIdx.y * TGM;
    const int n0 = blockIdx.x * TGN;
    const uint32_t smb = (uint32_t)__cvta_generic_to_shared(smc);

    float acc[8][4];
#pragma unroll
    for (int nt = 0; nt < 8; nt++)
#pragma unroll
        for (int j = 0; j < 4; j++) acc[nt][j] = 0.f;

    auto issue = [&](int k0, int buf) {
        const int ab = buf ? HA1 : HA0;
        const int bb2 = buf ? HB1 : HB0;
#pragma unroll
        for (int i = 0; i < 2; i++) {
            int idx = tid + i * 256;
            int row = idx >> 2, c4 = idx & 3;
            int gm = m0 + row;
            const __half* src;
            if (amode == 0) {
                src = A + (size_t)gm * DM + k0 + c4 * 8;
            } else {
                int b = gm >> 11, l = gm & (LL - 1);
                int head = k0 >> 5;
                src = A + (((size_t)b * HH + head) * LL + l) * DH + c4 * 8;
            }
            cp16(smb + (uint32_t)(ab + row * 80 + c4 * 16), src, 16);
        }
        {
            int row = tid >> 2, c4 = tid & 3;
            const __half* src = W + (size_t)(n0 + row) * DM + k0 + c4 * 8;
            cp16(smb + (uint32_t)(bb2 + row * 80 + c4 * 16), src, 16);
        }
    };

    issue(0, 0);
    cp_commit();

    for (int c = 0; c < 16; c++) {
        cp_wait<0>();
        __syncthreads();
        if (c < 15) issue((c + 1) * TGK, (c + 1) & 1);
        cp_commit();

        const uint32_t* Aw = (const uint32_t*)(smc + ((c & 1) ? HA1 : HA0));
        const uint32_t* Bw = (const uint32_t*)(smc + ((c & 1) ? HB1 : HB0));
#pragma unroll
        for (int kt = 0; kt < 2; kt++) {
            int ar = warp * 16 + g;
            int aw0 = ar * HGW + t + 8 * kt;
            int aw1 = (ar + 8) * HGW + t + 8 * kt;
            uint32_t a0 = Aw[aw0], a1 = Aw[aw1];
            uint32_t a2 = Aw[aw0 + 4], a3 = Aw[aw1 + 4];
#pragma unroll
            for (int nt = 0; nt < 8; nt++) {
                int bw = (nt * 8 + g) * HGW + t + 8 * kt;
                mma_f16(acc[nt][0], acc[nt][1], acc[nt][2], acc[nt][3],
                        a0, a1, a2, a3, Bw[bw], Bw[bw + 4]);
            }
        }
    }

    const int sr = warp * 16 + g;
    const int gm = m0 + sr;
    const int bb = gm >> 11, l = gm & (LL - 1);
#pragma unroll
    for (int nt = 0; nt < 8; nt++) {
        int sc = nt * 8 + 2 * t;
        int n  = n0 + sc;
        float b0v = bias ? bias[n]     : 0.f;
        float b1v = bias ? bias[n + 1] : 0.f;
        float2 p0 = make_float2(acc[nt][0] + b0v, acc[nt][1] + b1v);
        float2 p1 = make_float2(acc[nt][2] + b0v, acc[nt][3] + b1v);
        if (omode == 0) {
            float* Cf = (float*)Cv;
            *(float2*)(Cf + (size_t)gm * DM + n)       = p0;
            *(float2*)(Cf + (size_t)(gm + 8) * DM + n) = p1;
        } else if (omode == 1) {
            float* Cf = (float*)Cv;
            int head = n >> 5, d = n & 31;
            float* base = Cf + (((size_t)bb * HH + head) * LL + l) * DH + d;
            *(float2*)(base)          = p0;
            *(float2*)(base + 8 * DH) = p1;
        } else if (omode == 2) {
            __half* Ch = (__half*)Cv;
            int head = n >> 5, d = n & 31;
            __half* base = Ch + (((size_t)bb * HH + head) * LL + l) * DH + d;
            __half2 h0 = __floats2half2_rn(p0.x, p0.y);
            __half2 h1 = __floats2half2_rn(p1.x, p1.y);
            *(__half2*)(base)          = h0;
            *(__half2*)(base + 8 * DH) = h1;
        } else {
            __half* Ch = (__half*)Cv;
            int head = n >> 5, d = n & 31;
            __half* base = Ch + (((size_t)bb * HH + head) * DH + d) * LL + l;
            base[0]      = __float2half_rn(p0.x);
            base[LL]     = __float2half_rn(p0.y);
            base[8]      = __float2half_rn(p1.x);
            base[LL + 8] = __float2half_rn(p1.y);
        }
    }
}

__global__ __launch_bounds__(256)
void qkvp_gemm(const float* __restrict__ bq, const float* __restrict__ bk,
               const float* __restrict__ bv, float* __restrict__ oq)
{
    extern __shared__ char smc[];
    int z = blockIdx.z;
    if (z == 3 && blockIdx.y >= LL / TGM) return;
    const __half* A = g_inh + (size_t)z * QN;   // pos sits at 3*QN
    const __half* W = g_wh + (size_t)z * DM * DM;
    const float* b = (z == 0) ? bq : (z == 1) ? bk : (z == 2) ? bv : nullptr;
    void* C; int omode;
    if (z == 0)      { C = oq;   omode = 1; }
    else if (z == 1) { C = g_kh; omode = 2; }
    else if (z == 2) { C = g_vh; omode = 3; }
    else             { C = g_ph; omode = 2; }
    gemm_core_h(A, W, b, C, 0, omode, smc);
}

__global__ __launch_bounds__(256)
void wo_gemm(const float* __restrict__ bias, float* __restrict__ C)
{
    extern __shared__ char smc[];
    gemm_core_h(g_ctxh, g_wh + (size_t)4 * DM * DM, bias, C, 1, 0, smc);
}

// ---------------------------------------------------------------------------
// Warp-specialized ring-band attention, fp16 operands (fp32 accumulate).
// Shift: r=j-i; r<=0 -> p[L-1+r]; r==1 -> 0; r>=2 -> row i+1 uses p[r-2]
// ---------------------------------------------------------------------------
#define TI 64
#define TJ 64
#define HW 20    /* K/P/Q tile word stride (80B rows) */
#define VW 36    /* V^T word stride (144B rows) */
#define PWW 38   /* weight buffer word stride */
#define SSTR 68
#define WSTR 134 /* == 6 mod 32: distinct gather banks across srow */
#define RING 128

#define QU_B 0        /* 64x80B  = 5120  (reused: K buf1) */
#define QV_B 5120     /* 65x80B  = 5200  (partial reuse: V buf1) */
#define K0_B 10320    /* 5120 */
#define V0_B 15440    /* 32x144B = 4608 */
#define P0_B 20048    /* 5120 */
#define P1_B 25168    /* 5120 */
#define SS_B 30288    /* 64x68x4 = 17408 */
#define PW_B 47696    /* 64x76x2 = 9728 */
#define SW_B 57424    /* 65x134x4 = 34840 */
#define SC_B 92264    /* 256 */
#define SMEM_BYTES 92520

__global__ __launch_bounds__(256, 2)
void attn_mma(const float* __restrict__ qd, const __half* __restrict__ kd,
              const __half* __restrict__ vd, const __half* __restrict__ pd,
              const float* __restrict__ ub, const float* __restrict__ vb,
              __half* __restrict__ ctx)
{
    extern __shared__ char smc[];
    float* sS    = (float*)(smc + SS_B);
    float* sW    = (float*)(smc + SW_B);
    float* sCorr = (float*)(smc + SC_B);
    const uint32_t smb = (uint32_t)__cvta_generic_to_shared(smc);

    const int tid  = threadIdx.x;
    const int lane = tid & 31;
    const int warp = tid >> 5;
    const int I0 = blockIdx.x * TI;
    const int h = blockIdx.y, b = blockIdx.z;

    const float*  qbase  = qd + (size_t)(b * HH + h) * LL * DH;
    const __half* kbase  = kd + (size_t)(b * HH + h) * LL * DH;
    const __half* vtbase = vd + (size_t)(b * HH + h) * DH * LL;
    const __half* pbase  = pd + (size_t)h * LL * DH;

    const int KbufB[2] = {K0_B, QU_B};
    const int VbufB[2] = {V0_B, QV_B};
    const int PbufB[2] = {P0_B, P1_B};

    // ---- stage Qu (64 rows) and Qv (65 rows) as rn-fp16
    for (int idx = tid; idx < TI * 8; idx += 256) {
        int row = idx >> 3, c4 = idx & 7;
        float4 q  = *(const float4*)(qbase + (size_t)(I0 + row) * DH + c4 * 4);
        float4 u4 = *(const float4*)(ub + h * DH + c4 * 4);
        __half2 h0 = __floats2half2_rn(q.x + u4.x, q.y + u4.y);
        __half2 h1 = __floats2half2_rn(q.z + u4.z, q.w + u4.w);
        *(uint2*)(smc + QU_B + row * 80 + c4 * 8) =
            make_uint2(*(uint32_t*)&h0, *(uint32_t*)&h1);
    }
    for (int idx = tid; idx < (TI + 1) * 8; idx += 256) {
        int row = idx >> 3, c4 = idx & 7;
        int g = I0 + row;
        uint2 o = make_uint2(0u, 0u);
        if (g < LL) {
            float4 q  = *(const float4*)(qbase + (size_t)g * DH + c4 * 4);
            float4 v4 = *(const float4*)(vb + h * DH + c4 * 4);
            __half2 h0 = __floats2half2_rn(q.x + v4.x, q.y + v4.y);
            __half2 h1 = __floats2half2_rn(q.z + v4.z, q.w + v4.w);
            o = make_uint2(*(uint32_t*)&h0, *(uint32_t*)&h1);
        }
        *(uint2*)(smc + QV_B + row * 80 + c4 * 8) = o;
    }
    // ---- stage prologue band cols r in [-I0-64, -I0-1] into P1 (half)
    {
        const int r0 = -I0 - 64;
        int row = tid >> 2, c4 = tid & 3;
        int r = r0 + row;
        uint4 v = make_uint4(0u, 0u, 0u, 0u);
        if (r <= 0) { if (r >= 1 - LL) v = *(const uint4*)(pbase + (size_t)(LL - 1 + r) * DH + c4 * 8); }
        else if (r >= 2 && r <= LL + 1) v = *(const uint4*)(pbase + (size_t)(r - 2) * DH + c4 * 8);
        *(uint4*)(smc + P1_B + row * 80 + c4 * 16) = v;
    }
    __syncthreads();

    if (warp < 4) {
        // ========================= PRODUCER =========================
        const int pw = warp;
        const int g = lane >> 2, tq = lane & 3;

        auto issueKP = [&](int J0k, int J0p, int nb) {
#pragma unroll
            for (int i = 0; i < 2; i++) {
                int idx = tid + i * 128;
                int row = idx >> 2, c4 = idx & 3;
                cp16(smb + (uint32_t)(KbufB[nb] + row * 80 + c4 * 16),
                     kbase + (size_t)(J0k + row) * DH + c4 * 8, 16);
                int r = J0p - I0 + row;
                const __half* psrc = pbase;
                int sz = 0;
                if (r <= 0) { if (r >= 1 - LL) { psrc = pbase + (size_t)(LL - 1 + r) * DH + c4 * 8; sz = 16; } }
                else if (r >= 2 && r <= LL + 1) { psrc = pbase + (size_t)(r - 2) * DH + c4 * 8; sz = 16; }
                cp16(smb + (uint32_t)(PbufB[nb] + row * 80 + c4 * 16), psrc, sz);
            }
        };
        auto issueV = [&](int J0k, int nb) {
#pragma unroll
            for (int i = 0; i < 2; i++) {
                int idx = tid + i * 128;
                int ch = idx >> 3, c8 = idx & 7;
                cp16(smb + (uint32_t)(VbufB[nb] + ch * 144 + c8 * 16),
                     vtbase + (size_t)ch * LL + J0k + c8 * 8, 16);
            }
        };

        issueKP(0, 0, 0); cp_commit();   // A(0)
        issueV(0, 0);     cp_commit();   // B(0)

        // hoist fp16 fragments (2 k-steps of k16)
        const uint32_t* QuW = (const uint32_t*)(smc + QU_B);
        const uint32_t* QvW = (const uint32_t*)(smc + QV_B);
        uint32_t afu[2][4], afv[2][4];
#pragma unroll
        for (int kt = 0; kt < 2; kt++) {
            int w0 = (16 * pw + g) * HW + tq + 8 * kt;
            int w1 = (16 * pw + g + 8) * HW + tq + 8 * kt;
            afu[kt][0] = QuW[w0];     afu[kt][1] = QuW[w1];
            afu[kt][2] = QuW[w0 + 4]; afu[kt][3] = QuW[w1 + 4];
            afv[kt][0] = QvW[w0];     afv[kt][1] = QvW[w1];
            afv[kt][2] = QvW[w0 + 4]; afv[kt][3] = QvW[w1 + 4];
        }

        // prologue W-mma from P1
        {
            const int slotbase = ((-I0 - 64) + 4096) & (RING - 1);
            const uint32_t* Pw = (const uint32_t*)(smc + P1_B);
#pragma unroll
            for (int nt = 0; nt < 8; nt++) {
                float d0 = 0.f, d1 = 0.f, d2 = 0.f, d3 = 0.f;
#pragma unroll
                for (int kt = 0; kt < 2; kt++) {
                    int bw = (nt * 8 + g) * HW + tq + 8 * kt;
                    mma_f16(d0, d1, d2, d3, afv[kt][0], afv[kt][1], afv[kt][2], afv[kt][3],
                            Pw[bw], Pw[bw + 4]);
                }
                int wr = 16 * pw + g;
                int wc = slotbase + nt * 8 + 2 * tq;
                *(float2*)&sW[wr * WSTR + wc]       = make_float2(d0, d1);
                *(float2*)&sW[(wr + 8) * WSTR + wc] = make_float2(d2, d3);
            }
            if (tid < 64) {
                const __half* qv64 = (const __half*)(smc + QV_B + 64 * 80);
                const __half* pr   = (const __half*)(smc + P1_B + tid * 80);
                float s = 0.f;
#pragma unroll
                for (int c = 0; c < DH; c++)
                    s += __half2float(qv64[c]) * __half2float(pr[c]);
                sW[TI * WSTR + slotbase + tid] = s;
            }
        }
        BARSYNC(4, 128);   // all producers done reading QU/P1 before overwriting

        for (int t = 0; t < 32; t++) {
            const int J0 = t * TJ;
            const int Jn = J0 + TJ;
            const int Jc = (Jn < LL) ? Jn : (LL - TJ);

            issueKP(Jc, Jn, (t + 1) & 1); cp_commit();   // A(t+1)
            cp_wait<2>();                                 // A(t) done

            const uint32_t* Kw = (const uint32_t*)(smc + KbufB[t & 1]);
            const uint32_t* Pw = (const uint32_t*)(smc + PbufB[t & 1]);

            float sreg[8][4], wreg[8][4];
#pragma unroll
            for (int nt = 0; nt < 8; nt++) {
                float s0 = 0.f, s1 = 0.f, s2 = 0.f, s3 = 0.f;
                float w0 = 0.f, w1 = 0.f, w2 = 0.f, w3 = 0.f;
#pragma unroll
                for (int kt = 0; kt < 2; kt++) {
                    int bw = (nt * 8 + g) * HW + tq + 8 * kt;
                    mma_f16(s0, s1, s2, s3, afu[kt][0], afu[kt][1], afu[kt][2], afu[kt][3],
                            Kw[bw], Kw[bw + 4]);
                    mma_f16(w0, w1, w2, w3, afv[kt][0], afv[kt][1], afv[kt][2], afv[kt][3],
                            Pw[bw], Pw[bw + 4]);
                }
                sreg[nt][0] = s0; sreg[nt][1] = s1; sreg[nt][2] = s2; sreg[nt][3] = s3;
                wreg[nt][0] = w0; wreg[nt][1] = w1; wreg[nt][2] = w2; wreg[nt][3] = w3;
            }
            float ereg = 0.f;
            if (tid < 64) {
                const __half* qv64 = (const __half*)(smc + QV_B + 64 * 80);
                const __half* pr   = (const __half*)(smc + PbufB[t & 1] + tid * 80);
#pragma unroll
                for (int c = 0; c < DH; c++)
                    ereg += __half2float(qv64[c]) * __half2float(pr[c]);
            }

            if (t > 0) BARSYNC(1, 256);                  // sS / ring-slots free

            issueV(Jc, (t + 1) & 1); cp_commit();        // B(t+1)
            cp_wait<2>();                                 // B(t) done

            const int slotbase = ((J0 - I0) + 4096) & (RING - 1);
            const int sr = 16 * pw + g;
#pragma unroll
            for (int nt = 0; nt < 8; nt++) {
                int sc = nt * 8 + 2 * tq;
                *(float2*)&sS[sr * SSTR + sc]       = make_float2(sreg[nt][0], sreg[nt][1]);
                *(float2*)&sS[(sr + 8) * SSTR + sc] = make_float2(sreg[nt][2], sreg[nt][3]);
                int wc = slotbase + nt * 8 + 2 * tq;
                *(float2*)&sW[sr * WSTR + wc]       = make_float2(wreg[nt][0], wreg[nt][1]);
                *(float2*)&sW[(sr + 8) * WSTR + wc] = make_float2(wreg[nt][2], wreg[nt][3]);
            }
            if (tid < 64) sW[TI * WSTR + slotbase + tid] = ereg;

            BARSYNC(2, 256);                             // publish S(t)/W(t)/V(t)
        }
    } else {
        // ========================= CONSUMER =========================
        const int cw = warp - 4;
        const int ctid = tid - 128;
        const int srow = ctid >> 1;
        const int half = ctid & 1;
        const int g = lane >> 2, tq = lane & 3;
        const int qi = I0 + srow;

        uint32_t* pwW = (uint32_t*)(smc + PW_B);
        float dacc[4][4];
#pragma unroll
        for (int nt = 0; nt < 4; nt++)
#pragma unroll
            for (int j = 0; j < 4; j++) dacc[nt][j] = 0.f;
        float rmax = -INFINITY, rsum = 0.f;

        for (int t = 0; t < 32; t++) {
            const int J0 = t * TJ;
            BARSYNC(2, 256);                             // S(t) ready

            // ---- softmax: thread (srow, half) owns 32 columns
            {
                float s[32];
#pragma unroll
                for (int k4 = 0; k4 < 8; k4++) {
                    float4 s4 = *(const float4*)&sS[srow * SSTR + half * 32 + k4 * 4];
                    s[k4 * 4 + 0] = s4.x; s[k4 * 4 + 1] = s4.y;
                    s[k4 * 4 + 2] = s4.z; s[k4 * 4 + 3] = s4.w;
                }
                float cmax = -INFINITY;
#pragma unroll
                for (int tt = 0; tt < 32; tt++) {
                    int jj = half * 32 + tt;
                    int r = J0 + jj - qi;
                    int slot = (r + 4096) & (RING - 1);
                    int wrow = srow + (r >= 1);
                    s[tt] = (s[tt] + sW[wrow * WSTR + slot]) * SCALE;
                    cmax = fmaxf(cmax, s[tt]);
                }
                cmax = fmaxf(cmax, __shfl_xor_sync(0xffffffffu, cmax, 1));
                float mnew = fmaxf(rmax, cmax);
                float corr = __expf(rmax - mnew);        // first tile: exp(-inf)=0
                float csum = 0.f;
#pragma unroll
                for (int k2 = 0; k2 < 16; k2++) {
                    __half h0 = __float2half_rn(__expf(s[2 * k2]     - mnew));
                    __half h1 = __float2half_rn(__expf(s[2 * k2 + 1] - mnew));
                    csum += __half2float(h0) + __half2float(h1);
                    __half2 hh = __halves2half2(h0, h1);
                    pwW[srow * PWW + half * 16 + k2] = *(uint32_t*)&hh;
                }
                csum += __shfl_xor_sync(0xffffffffu, csum, 1);
                rsum = rsum * corr + csum;
                rmax = mnew;
                if (half == 0) sCorr[srow] = corr;
            }
            BARSYNC(3, 128);                             // consumer-internal

            // ---- PV MMA: rows 16cw.., all 32 channels, k=64 in 4 k16 steps
            {
                const uint32_t* Vw = (const uint32_t*)(smc + VbufB[t & 1]);
                const int prow = 16 * cw + g;
                float c0 = sCorr[prow];
                float c1 = sCorr[prow + 8];
#pragma unroll
                for (int nt = 0; nt < 4; nt++) {
                    dacc[nt][0] *= c0; dacc[nt][1] *= c0;
                    dacc[nt][2] *= c1; dacc[nt][3] *= c1;
                }
#pragma unroll
                for (int kt = 0; kt < 4; kt++) {
                    int aw0 = prow * PWW + tq + 8 * kt;
                    int aw1 = (prow + 8) * PWW + tq + 8 * kt;
                    uint32_t a0 = pwW[aw0], a1 = pwW[aw1];
                    uint32_t a2 = pwW[aw0 + 4], a3 = pwW[aw1 + 4];
#pragma unroll
                    for (int nt = 0; nt < 4; nt++) {
                        int bw = (nt * 8 + g) * VW + tq + 8 * kt;
                        mma_f16(dacc[nt][0], dacc[nt][1], dacc[nt][2], dacc[nt][3],
                                a0, a1, a2, a3, Vw[bw], Vw[bw + 4]);
                    }
                }
            }
            if (t < 31) BARSYNC(1, 256);                 // release sS / ring slots
        }

        // ---- finalize (consumers only); ctx written as fp16
        BARSYNC(3, 128);
        if (half == 0) sCorr[srow] = 1.f / rsum;
        BARSYNC(3, 128);
        {
            const int prow = 16 * cw + g;
            float i0v = sCorr[prow];
            float i1v = sCorr[prow + 8];
            __half* ob = ctx + (size_t)(b * HH + h) * LL * DH;
#pragma unroll
            for (int nt = 0; nt < 4; nt++) {
                int sc = nt * 8 + 2 * tq;
                __half2 h0 = __floats2half2_rn(dacc[nt][0] * i0v, dacc[nt][1] * i0v);
                __half2 h1 = __floats2half2_rn(dacc[nt][2] * i1v, dacc[nt][3] * i1v);
                *(__half2*)(ob + (size_t)(I0 + prow) * DH + sc)     = h0;
                *(__half2*)(ob + (size_t)(I0 + prow + 8) * DH + sc) = h1;
            }
        }
    }
}

// ---------------------------------------------------------------------------
extern "C" void kernel_launch(void* const* d_in, const int* in_sizes, int n_in,
                              void* d_out, int out_size)
{
    const float* query = (const float*)d_in[0];
    const float* key   = (const float*)d_in[1];
    const float* value = (const float*)d_in[2];
    const float* pos   = (const float*)d_in[3];
    const float* Wq    = (const float*)d_in[4];
    const float* bq    = (const float*)d_in[5];
    const float* Wk    = (const float*)d_in[6];
    const float* bk    = (const float*)d_in[7];
    const float* Wv    = (const float*)d_in[8];
    const float* bv    = (const float*)d_in[9];
    const float* Wp    = (const float*)d_in[10];
    const float* ub    = (const float*)d_in[11];
    const float* vb    = (const float*)d_in[12];
    const float* Wo    = (const float*)d_in[13];
    const float* bo    = (const float*)d_in[14];

    float *pq;
    __half *pk, *pv, *pp, *pctx;
    cudaGetSymbolAddress((void**)&pq,   g_q);
    cudaGetSymbolAddress((void**)&pk,   g_kh);
    cudaGetSymbolAddress((void**)&pv,   g_vh);
    cudaGetSymbolAddress((void**)&pp,   g_ph);
    cudaGetSymbolAddress((void**)&pctx, g_ctxh);

    static int attr_set = 0;
    if (!attr_set) {
        cudaFuncSetAttribute(attn_mma, cudaFuncAttributeMaxDynamicSharedMemorySize, SMEM_BYTES);
        cudaFuncSetAttribute(qkvp_gemm, cudaFuncAttributeMaxDynamicSharedMemorySize, GSMEM_BYTES);
        cudaFuncSetAttribute(wo_gemm, cudaFuncAttributeMaxDynamicSharedMemorySize, GSMEM_BYTES);
        attr_set = 1;
    }

    preround<<<dim3(DM * DM / 1024, 1, 5), 256>>>(Wq, Wk, Wv, Wp, Wo);
    tohalf<<<(3 * QN + LL * DM) / 2048, 256>>>(query, key, value, pos);

    qkvp_gemm<<<dim3(DM / TGN, (BB * LL) / TGM, 4), 256, GSMEM_BYTES>>>(
        bq, bk, bv, pq);

    attn_mma<<<dim3(LL / TI, HH, BB), 256, SMEM_BYTES>>>(pq, pk, pv, pp, ub, vb, pctx);

    wo_gemm<<<dim3(DM / TGN, (BB * LL) / TGM), 256, GSMEM_BYTES>>>(
        bo, (float*)d_out);
}

// round 13
// speedup vs baseline: 6.5406x; 1.0864x over previous
#include <cuda_runtime.h>
#include <cuda_fp16.h>
#include <math.h>
#include <stdint.h>

#define BB 2
#define LL 2048
#define HH 16
#define DH 32
#define DM 512
#define SCALE 0.044194173824159216f  /* 1/sqrt(512) */
#define QN (BB*LL*DM)                /* 2097152 */

__device__ float  g_q[BB*HH*LL*DH];
__device__ __half g_kh[BB*HH*LL*DH];
__device__ __half g_vh[BB*HH*LL*DH];   // transposed [b,h,dh,l]
__device__ __half g_ph[HH*LL*DH];
__device__ __half g_ctxh[BB*HH*LL*DH];
__device__ __half g_wh[5*DM*DM];       // fp16 Wq,Wk,Wv,Wp,Wo
__device__ __half g_inh[3*QN + LL*DM]; // fp16 query,key,value,pos

__device__ __forceinline__ void mma_f16(float& d0, float& d1, float& d2, float& d3,
                                        uint32_t a0, uint32_t a1, uint32_t a2, uint32_t a3,
                                        uint32_t b0, uint32_t b1) {
    asm volatile(
        "mma.sync.aligned.m16n8k16.row.col.f32.f16.f16.f32 "
        "{%0,%1,%2,%3}, {%4,%5,%6,%7}, {%8,%9}, {%0,%1,%2,%3};\n"
        : "+f"(d0), "+f"(d1), "+f"(d2), "+f"(d3)
        : "r"(a0), "r"(a1), "r"(a2), "r"(a3), "r"(b0), "r"(b1));
}

__device__ __forceinline__ void cp16(uint32_t dst, const void* src, int szbytes) {
    asm volatile("cp.async.cg.shared.global [%0], [%1], 16, %2;\n"
                 :: "r"(dst), "l"(src), "r"(szbytes));
}
__device__ __forceinline__ void cp_commit() {
    asm volatile("cp.async.commit_group;\n" ::: "memory");
}
template<int N>
__device__ __forceinline__ void cp_wait() {
    asm volatile("cp.async.wait_group %0;\n" :: "n"(N) : "memory");
}
#define BARSYNC(id, cnt) asm volatile("bar.sync %0, %1;" :: "r"(id), "r"(cnt) : "memory")

// ---------------------------------------------------------------------------
// preround: weights -> fp16. grid (256,1,5), 4 elems/thread
// ---------------------------------------------------------------------------
__global__ __launch_bounds__(256)
void preround(const float* __restrict__ w0, const float* __restrict__ w1,
              const float* __restrict__ w2, const float* __restrict__ w3,
              const float* __restrict__ w4)
{
    const float* src[5] = {w0, w1, w2, w3, w4};
    int z = blockIdx.z;
    int i = (blockIdx.x * 256 + threadIdx.x) * 4;
    float4 v = *(const float4*)(src[z] + i);
    __half2 h0 = __floats2half2_rn(v.x, v.y);
    __half2 h1 = __floats2half2_rn(v.z, v.w);
    *(uint2*)(g_wh + (size_t)z * DM * DM + i) =
        make_uint2(*(uint32_t*)&h0, *(uint32_t*)&h1);
}

// ---------------------------------------------------------------------------
// tohalf: inputs (query,key,value,pos) -> fp16 into g_inh. 8 elems/thread.
// ---------------------------------------------------------------------------
__global__ __launch_bounds__(256)
void tohalf(const float* __restrict__ q, const float* __restrict__ k,
            const float* __restrict__ v, const float* __restrict__ p)
{
    size_t i = ((size_t)blockIdx.x * 256 + threadIdx.x) * 8;
    const float* src; size_t off;
    if (i < (size_t)QN)          { src = q; off = i; }
    else if (i < (size_t)2 * QN) { src = k; off = i - QN; }
    else if (i < (size_t)3 * QN) { src = v; off = i - 2 * (size_t)QN; }
    else                         { src = p; off = i - 3 * (size_t)QN; }
    float4 a = *(const float4*)(src + off);
    float4 b = *(const float4*)(src + off + 4);
    __half2 h0 = __floats2half2_rn(a.x, a.y);
    __half2 h1 = __floats2half2_rn(a.z, a.w);
    __half2 h2 = __floats2half2_rn(b.x, b.y);
    __half2 h3 = __floats2half2_rn(b.z, b.w);
    *(uint4*)(g_inh + i) = make_uint4(*(uint32_t*)&h0, *(uint32_t*)&h1,
                                      *(uint32_t*)&h2, *(uint32_t*)&h3);
}

// ---------------------------------------------------------------------------
// fp16 GEMM core, cp.async double-buffered, m16n8k16, fp32 accum.
// ---------------------------------------------------------------------------
#define TGM 128
#define TGN 64
#define TGK 32
#define HGW 20            /* 40-half (80B) row stride, words */
#define HA0 0
#define HA1 10240
#define HB0 20480
#define HB1 25600
#define GSMEM_BYTES 30720

__device__ __forceinline__ void gemm_core_h(
    const __half* __restrict__ A, const __half* __restrict__ W,
    const float* __restrict__ bias, void* __restrict__ Cv,
    int amode, int omode, char* smc)
{
    const int tid  = threadIdx.x;
    const int lane = tid & 31;
    const int warp = tid >> 5;
    const int g = lane >> 2;
    const int t = lane & 3;
    const int m0 = blockIdx.y * TGM;
    const int n0 = blockIdx.x * TGN;
    const uint32_t smb = (uint32_t)__cvta_generic_to_shared(smc);

    float acc[8][4];
#pragma unroll
    for (int nt = 0; nt < 8; nt++)
#pragma unroll
        for (int j = 0; j < 4; j++) acc[nt][j] = 0.f;

    auto issue = [&](int k0, int buf) {
        const int ab = buf ? HA1 : HA0;
        const int bb2 = buf ? HB1 : HB0;
#pragma unroll
        for (int i = 0; i < 2; i++) {
            int idx = tid + i * 256;
            int row = idx >> 2, c4 = idx & 3;
            int gm = m0 + row;
            const __half* src;
            if (amode == 0) {
                src = A + (size_t)gm * DM + k0 + c4 * 8;
            } else {
                int b = gm >> 11, l = gm & (LL - 1);
                int head = k0 >> 5;
                src = A + (((size_t)b * HH + head) * LL + l) * DH + c4 * 8;
            }
            cp16(smb + (uint32_t)(ab + row * 80 + c4 * 16), src, 16);
        }
        {
            int row = tid >> 2, c4 = tid & 3;
            const __half* src = W + (size_t)(n0 + row) * DM + k0 + c4 * 8;
            cp16(smb + (uint32_t)(bb2 + row * 80 + c4 * 16), src, 16);
        }
    };

    issue(0, 0);
    cp_commit();

    for (int c = 0; c < 16; c++) {
        cp_wait<0>();
        __syncthreads();
        if (c < 15) issue((c + 1) * TGK, (c + 1) & 1);
        cp_commit();

        const uint32_t* Aw = (const uint32_t*)(smc + ((c & 1) ? HA1 : HA0));
        const uint32_t* Bw = (const uint32_t*)(smc + ((c & 1) ? HB1 : HB0));
#pragma unroll
        for (int kt = 0; kt < 2; kt++) {
            int ar = warp * 16 + g;
            int aw0 = ar * HGW + t + 8 * kt;
            int aw1 = (ar + 8) * HGW + t + 8 * kt;
            uint32_t a0 = Aw[aw0], a1 = Aw[aw1];
            uint32_t a2 = Aw[aw0 + 4], a3 = Aw[aw1 + 4];
#pragma unroll
            for (int nt = 0; nt < 8; nt++) {
                int bw = (nt * 8 + g) * HGW + t + 8 * kt;
                mma_f16(acc[nt][0], acc[nt][1], acc[nt][2], acc[nt][3],
                        a0, a1, a2, a3, Bw[bw], Bw[bw + 4]);
            }
        }
    }

    const int sr = warp * 16 + g;
    const int gm = m0 + sr;
    const int bb = gm >> 11, l = gm & (LL - 1);
#pragma unroll
    for (int nt = 0; nt < 8; nt++) {
        int sc = nt * 8 + 2 * t;
        int n  = n0 + sc;
        float b0v = bias ? bias[n]     : 0.f;
        float b1v = bias ? bias[n + 1] : 0.f;
        float2 p0 = make_float2(acc[nt][0] + b0v, acc[nt][1] + b1v);
        float2 p1 = make_float2(acc[nt][2] + b0v, acc[nt][3] + b1v);
        if (omode == 0) {
            float* Cf = (float*)Cv;
            *(float2*)(Cf + (size_t)gm * DM + n)       = p0;
            *(float2*)(Cf + (size_t)(gm + 8) * DM + n) = p1;
        } else if (omode == 1) {
            float* Cf = (float*)Cv;
            int head = n >> 5, d = n & 31;
            float* base = Cf + (((size_t)bb * HH + head) * LL + l) * DH + d;
            *(float2*)(base)          = p0;
            *(float2*)(base + 8 * DH) = p1;
        } else if (omode == 2) {
            __half* Ch = (__half*)Cv;
            int head = n >> 5, d = n & 31;
            __half* base = Ch + (((size_t)bb * HH + head) * LL + l) * DH + d;
            __half2 h0 = __floats2half2_rn(p0.x, p0.y);
            __half2 h1 = __floats2half2_rn(p1.x, p1.y);
            *(__half2*)(base)          = h0;
            *(__half2*)(base + 8 * DH) = h1;
        } else {
            __half* Ch = (__half*)Cv;
            int head = n >> 5, d = n & 31;
            __half* base = Ch + (((size_t)bb * HH + head) * DH + d) * LL + l;
            base[0]      = __float2half_rn(p0.x);
            base[LL]     = __float2half_rn(p0.y);
            base[8]      = __float2half_rn(p1.x);
            base[LL + 8] = __float2half_rn(p1.y);
        }
    }
}

__global__ __launch_bounds__(256)
void qkvp_gemm(const float* __restrict__ bq, const float* __restrict__ bk,
               const float* __restrict__ bv, float* __restrict__ oq)
{
    extern __shared__ char smc[];
    int z = blockIdx.z;
    if (z == 3 && blockIdx.y >= LL / TGM) return;
    const __half* A = g_inh + (size_t)z * QN;
    const __half* W = g_wh + (size_t)z * DM * DM;
    const float* b = (z == 0) ? bq : (z == 1) ? bk : (z == 2) ? bv : nullptr;
    void* C; int omode;
    if (z == 0)      { C = g_q;  omode = 1; }
    else if (z == 1) { C = g_kh; omode = 2; }
    else if (z == 2) { C = g_vh; omode = 3; }
    else             { C = g_ph; omode = 2; }
    gemm_core_h(A, W, b, C, 0, omode, smc);
}

__global__ __launch_bounds__(256)
void wo_gemm(const float* __restrict__ bias, float* __restrict__ C)
{
    extern __shared__ char smc[];
    gemm_core_h(g_ctxh, g_wh + (size_t)4 * DM * DM, bias, C, 1, 0, smc);
}

// ---------------------------------------------------------------------------
// Warp-specialized ring-band attention, fp16 operands + fp16 sW ring.
// Producers: warps 0-1 content-S (32 rows each), warps 2-3 band-W (32 rows
// each + extra row 64). Consumers: warps 4-7 softmax + PV MMA.
// Shift: r=j-i; r<=0 -> p[L-1+r]; r==1 -> 0; r>=2 -> row i+1 uses p[r-2]
// ---------------------------------------------------------------------------
#define TI 64
#define TJ 64
#define HW 20     /* K/P/Q tile word stride (80B rows) */
#define VW 36     /* V^T word stride (144B rows) */
#define PWW 38    /* weight buffer word stride */
#define SSTR 68
#define WSTRH 134 /* sW half stride: 67 words == 3 mod 32 -> conflict-free */
#define RING 128

#define QU_B 0        /* 64x80B  = 5120  (reused: K buf1) */
#define QV_B 5120     /* 65x80B  = 5200  (rows<58 reused: V buf1) */
#define K0_B 10320    /* 5120 */
#define V0_B 15440    /* 32x144B = 4608 */
#define P0_B 20048    /* 5120 */
#define P1_B 25168    /* 5120 */
#define SS_B 30288    /* 64x68x4 = 17408 */
#define PW_B 47696    /* 64x38x4 = 9728 */
#define SW_B 57424    /* 65x134x2 = 17420 */
#define SC_B 74844    /* 256 */
#define SMEM_BYTES 75104

__global__ __launch_bounds__(256, 2)
void attn_mma(const float* __restrict__ qd, const __half* __restrict__ kd,
              const __half* __restrict__ vd, const __half* __restrict__ pd,
              const float* __restrict__ ub, const float* __restrict__ vb,
              __half* __restrict__ ctx)
{
    extern __shared__ char smc[];
    float*  sS    = (float*)(smc + SS_B);
    __half* sWh   = (__half*)(smc + SW_B);
    float*  sCorr = (float*)(smc + SC_B);
    const uint32_t smb = (uint32_t)__cvta_generic_to_shared(smc);

    const int tid  = threadIdx.x;
    const int lane = tid & 31;
    const int warp = tid >> 5;
    const int I0 = blockIdx.x * TI;
    const int h = blockIdx.y, b = blockIdx.z;

    const float*  qbase  = qd + (size_t)(b * HH + h) * LL * DH;
    const __half* kbase  = kd + (size_t)(b * HH + h) * LL * DH;
    const __half* vtbase = vd + (size_t)(b * HH + h) * DH * LL;
    const __half* pbase  = pd + (size_t)h * LL * DH;

    const int KbufB[2] = {K0_B, QU_B};
    const int VbufB[2] = {V0_B, QV_B};
    const int PbufB[2] = {P0_B, P1_B};

    // ---- stage Qu (64 rows) and Qv (65 rows) as rn-fp16
    for (int idx = tid; idx < TI * 8; idx += 256) {
        int row = idx >> 3, c4 = idx & 7;
        float4 q  = *(const float4*)(qbase + (size_t)(I0 + row) * DH + c4 * 4);
        float4 u4 = *(const float4*)(ub + h * DH + c4 * 4);
        __half2 h0 = __floats2half2_rn(q.x + u4.x, q.y + u4.y);
        __half2 h1 = __floats2half2_rn(q.z + u4.z, q.w + u4.w);
        *(uint2*)(smc + QU_B + row * 80 + c4 * 8) =
            make_uint2(*(uint32_t*)&h0, *(uint32_t*)&h1);
    }
    for (int idx = tid; idx < (TI + 1) * 8; idx += 256) {
        int row = idx >> 3, c4 = idx & 7;
        int g = I0 + row;
        uint2 o = make_uint2(0u, 0u);
        if (g < LL) {
            float4 q  = *(const float4*)(qbase + (size_t)g * DH + c4 * 4);
            float4 v4 = *(const float4*)(vb + h * DH + c4 * 4);
            __half2 h0 = __floats2half2_rn(q.x + v4.x, q.y + v4.y);
            __half2 h1 = __floats2half2_rn(q.z + v4.z, q.w + v4.w);
            o = make_uint2(*(uint32_t*)&h0, *(uint32_t*)&h1);
        }
        *(uint2*)(smc + QV_B + row * 80 + c4 * 8) = o;
    }
    // ---- stage prologue band cols r in [-I0-64, -I0-1] into P1 (half)
    {
        const int r0 = -I0 - 64;
        int row = tid >> 2, c4 = tid & 3;
        int r = r0 + row;
        uint4 v = make_uint4(0u, 0u, 0u, 0u);
        if (r <= 0) { if (r >= 1 - LL) v = *(const uint4*)(pbase + (size_t)(LL - 1 + r) * DH + c4 * 8); }
        else if (r >= 2 && r <= LL + 1) v = *(const uint4*)(pbase + (size_t)(r - 2) * DH + c4 * 8);
        *(uint4*)(smc + P1_B + row * 80 + c4 * 16) = v;
    }
    __syncthreads();

    if (warp < 4) {
        // ========================= PRODUCER =========================
        const bool isS = (warp < 2);
        const int rw = warp & 1;              // role-local row-warp: rows rw*32..+31
        const int g = lane >> 2, tq = lane & 3;

        auto issueKP = [&](int J0k, int J0p, int nb) {
#pragma unroll
            for (int i = 0; i < 2; i++) {
                int idx = tid + i * 128;
                int row = idx >> 2, c4 = idx & 3;
                cp16(smb + (uint32_t)(KbufB[nb] + row * 80 + c4 * 16),
                     kbase + (size_t)(J0k + row) * DH + c4 * 8, 16);
                int r = J0p - I0 + row;
                const __half* psrc = pbase;
                int sz = 0;
                if (r <= 0) { if (r >= 1 - LL) { psrc = pbase + (size_t)(LL - 1 + r) * DH + c4 * 8; sz = 16; } }
                else if (r >= 2 && r <= LL + 1) { psrc = pbase + (size_t)(r - 2) * DH + c4 * 8; sz = 16; }
                cp16(smb + (uint32_t)(PbufB[nb] + row * 80 + c4 * 16), psrc, sz);
            }
        };
        auto issueV = [&](int J0k, int nb) {
#pragma unroll
            for (int i = 0; i < 2; i++) {
                int idx = tid + i * 128;
                int ch = idx >> 3, c8 = idx & 7;
                cp16(smb + (uint32_t)(VbufB[nb] + ch * 144 + c8 * 16),
                     vtbase + (size_t)ch * LL + J0k + c8 * 8, 16);
            }
        };

        issueKP(0, 0, 0); cp_commit();   // A(0)
        issueV(0, 0);     cp_commit();   // B(0)

        // hoist fragments: 2 row-groups (mt) x 2 k-steps
        const uint32_t* Qsrc = (const uint32_t*)(smc + (isS ? QU_B : QV_B));
        uint32_t af[2][2][4];
#pragma unroll
        for (int mt = 0; mt < 2; mt++)
#pragma unroll
            for (int kt = 0; kt < 2; kt++) {
                int w0 = (rw * 32 + mt * 16 + g) * HW + tq + 8 * kt;
                int w1 = w0 + 8 * HW;
                af[mt][kt][0] = Qsrc[w0];     af[mt][kt][1] = Qsrc[w1];
                af[mt][kt][2] = Qsrc[w0 + 4]; af[mt][kt][3] = Qsrc[w1 + 4];
            }

        // prologue W-mma from P1 (band warps only)
        if (!isS) {
            const int slotbase = ((-I0 - 64) + 4096) & (RING - 1);
            const uint32_t* Pw = (const uint32_t*)(smc + P1_B);
#pragma unroll
            for (int mt = 0; mt < 2; mt++)
#pragma unroll
                for (int nt = 0; nt < 8; nt++) {
                    float d0 = 0.f, d1 = 0.f, d2 = 0.f, d3 = 0.f;
#pragma unroll
                    for (int kt = 0; kt < 2; kt++) {
                        int bw = (nt * 8 + g) * HW + tq + 8 * kt;
                        mma_f16(d0, d1, d2, d3,
                                af[mt][kt][0], af[mt][kt][1], af[mt][kt][2], af[mt][kt][3],
                                Pw[bw], Pw[bw + 4]);
                    }
                    int wr = rw * 32 + mt * 16 + g;
                    int wc = slotbase + nt * 8 + 2 * tq;   // even
                    *(__half2*)&sWh[wr * WSTRH + wc]       = __floats2half2_rn(d0, d1);
                    *(__half2*)&sWh[(wr + 8) * WSTRH + wc] = __floats2half2_rn(d2, d3);
                }
            {   // extra row 64 (tids 64..127)
                int t64 = tid - 64;
                const __half2* qv64 = (const __half2*)(smc + QV_B + 64 * 80);
                const __half2* pr   = (const __half2*)(smc + P1_B + t64 * 80);
                float s = 0.f;
#pragma unroll
                for (int c = 0; c < 16; c++) {
                    float2 a = __half22float2(qv64[c]);
                    float2 bb2 = __half22float2(pr[c]);
                    s += a.x * bb2.x + a.y * bb2.y;
                }
                sWh[TI * WSTRH + slotbase + t64] = __float2half_rn(s);
            }
        }
        BARSYNC(4, 128);   // producers done reading QU/P1 before overwrite

        for (int t = 0; t < 32; t++) {
            const int J0 = t * TJ;
            const int Jn = J0 + TJ;
            const int Jc = (Jn < LL) ? Jn : (LL - TJ);

            issueKP(Jc, Jn, (t + 1) & 1); cp_commit();   // A(t+1)
            cp_wait<2>();                                 // A(t) done

            const uint32_t* Bw = (const uint32_t*)(smc + (isS ? KbufB[t & 1] : PbufB[t & 1]));

            float reg[2][8][4];
#pragma unroll
            for (int mt = 0; mt < 2; mt++)
#pragma unroll
                for (int nt = 0; nt < 8; nt++) {
                    float d0 = 0.f, d1 = 0.f, d2 = 0.f, d3 = 0.f;
#pragma unroll
                    for (int kt = 0; kt < 2; kt++) {
                        int bw = (nt * 8 + g) * HW + tq + 8 * kt;
                        mma_f16(d0, d1, d2, d3,
                                af[mt][kt][0], af[mt][kt][1], af[mt][kt][2], af[mt][kt][3],
                                Bw[bw], Bw[bw + 4]);
                    }
                    reg[mt][nt][0] = d0; reg[mt][nt][1] = d1;
                    reg[mt][nt][2] = d2; reg[mt][nt][3] = d3;
                }
            float ereg = 0.f;
            if (!isS) {
                int t64 = tid - 64;
                const __half2* qv64 = (const __half2*)(smc + QV_B + 64 * 80);
                const __half2* pr   = (const __half2*)(smc + PbufB[t & 1] + t64 * 80);
#pragma unroll
                for (int c = 0; c < 16; c++) {
                    float2 a = __half22float2(qv64[c]);
                    float2 bb2 = __half22float2(pr[c]);
                    ereg += a.x * bb2.x + a.y * bb2.y;
                }
            }

            if (t > 0) BARSYNC(1, 256);                  // sS / ring-slots free

            issueV(Jc, (t + 1) & 1); cp_commit();        // B(t+1)
            cp_wait<2>();                                 // B(t) done

            const int slotbase = ((J0 - I0) + 4096) & (RING - 1);
            if (isS) {
#pragma unroll
                for (int mt = 0; mt < 2; mt++)
#pragma unroll
                    for (int nt = 0; nt < 8; nt++) {
                        int sr = rw * 32 + mt * 16 + g;
                        int sc = nt * 8 + 2 * tq;
                        *(float2*)&sS[sr * SSTR + sc]       = make_float2(reg[mt][nt][0], reg[mt][nt][1]);
                        *(float2*)&sS[(sr + 8) * SSTR + sc] = make_float2(reg[mt][nt][2], reg[mt][nt][3]);
                    }
            } else {
#pragma unroll
                for (int mt = 0; mt < 2; mt++)
#pragma unroll
                    for (int nt = 0; nt < 8; nt++) {
                        int wr = rw * 32 + mt * 16 + g;
                        int wc = slotbase + nt * 8 + 2 * tq;
                        *(__half2*)&sWh[wr * WSTRH + wc]       = __floats2half2_rn(reg[mt][nt][0], reg[mt][nt][1]);
                        *(__half2*)&sWh[(wr + 8) * WSTRH + wc] = __floats2half2_rn(reg[mt][nt][2], reg[mt][nt][3]);
                    }
                sWh[TI * WSTRH + slotbase + (tid - 64)] = __float2half_rn(ereg);
            }

            BARSYNC(2, 256);                             // publish S(t)/W(t)/V(t)
        }
    } else {
        // ========================= CONSUMER =========================
        const int cw = warp - 4;
        const int ctid = tid - 128;
        const int srow = ctid >> 1;
        const int half = ctid & 1;
        const int g = lane >> 2, tq = lane & 3;
        const int qi = I0 + srow;

        uint32_t* pwW = (uint32_t*)(smc + PW_B);
        const __half* bp0 = sWh + srow * WSTRH;
        const __half* bp1 = bp0 + WSTRH;
        float dacc[4][4];
#pragma unroll
        for (int nt = 0; nt < 4; nt++)
#pragma unroll
            for (int j = 0; j < 4; j++) dacc[nt][j] = 0.f;
        float rmax = -INFINITY, rsum = 0.f;

        for (int t = 0; t < 32; t++) {
            const int J0 = t * TJ;
            BARSYNC(2, 256);                             // S(t) ready

            // ---- softmax: thread (srow, half) owns 32 columns
            {
                float s[32];
#pragma unroll
                for (int k4 = 0; k4 < 8; k4++) {
                    float4 s4 = *(const float4*)&sS[srow * SSTR + half * 32 + k4 * 4];
                    s[k4 * 4 + 0] = s4.x; s[k4 * 4 + 1] = s4.y;
                    s[k4 * 4 + 2] = s4.z; s[k4 * 4 + 3] = s4.w;
                }
                const int rbase = J0 + half * 32 - qi;
                int slot = (rbase + 4096) & (RING - 1);
                float cmax = -INFINITY;
#pragma unroll
                for (int tt = 0; tt < 32; tt++) {
                    float wv = __half2float(((rbase + tt) >= 1 ? bp1 : bp0)[slot]);
                    s[tt] = (s[tt] + wv) * SCALE;
                    cmax = fmaxf(cmax, s[tt]);
                    slot = (slot + 1) & (RING - 1);
                }
                cmax = fmaxf(cmax, __shfl_xor_sync(0xffffffffu, cmax, 1));
                float mnew = fmaxf(rmax, cmax);
                float corr = __expf(rmax - mnew);        // first tile: exp(-inf)=0
                float csum = 0.f;
#pragma unroll
                for (int k2 = 0; k2 < 16; k2++) {
                    __half h0 = __float2half_rn(__expf(s[2 * k2]     - mnew));
                    __half h1 = __float2half_rn(__expf(s[2 * k2 + 1] - mnew));
                    csum += __half2float(h0) + __half2float(h1);
                    __half2 hh = __halves2half2(h0, h1);
                    pwW[srow * PWW + half * 16 + k2] = *(uint32_t*)&hh;
                }
                csum += __shfl_xor_sync(0xffffffffu, csum, 1);
                rsum = rsum * corr + csum;
                rmax = mnew;
                if (half == 0) sCorr[srow] = corr;
            }
            BARSYNC(3, 128);                             // consumer-internal

            // ---- PV MMA: rows 16cw.., all 32 channels, k=64 in 4 k16 steps
            {
                const uint32_t* Vw = (const uint32_t*)(smc + VbufB[t & 1]);
                const int prow = 16 * cw + g;
                float c0 = sCorr[prow];
                float c1 = sCorr[prow + 8];
#pragma unroll
                for (int nt = 0; nt < 4; nt++) {
                    dacc[nt][0] *= c0; dacc[nt][1] *= c0;
                    dacc[nt][2] *= c1; dacc[nt][3] *= c1;
                }
#pragma unroll
                for (int kt = 0; kt < 4; kt++) {
                    int aw0 = prow * PWW + tq + 8 * kt;
                    int aw1 = (prow + 8) * PWW + tq + 8 * kt;
                    uint32_t a0 = pwW[aw0], a1 = pwW[aw1];
                    uint32_t a2 = pwW[aw0 + 4], a3 = pwW[aw1 + 4];
#pragma unroll
                    for (int nt = 0; nt < 4; nt++) {
                        int bw = (nt * 8 + g) * VW + tq + 8 * kt;
                        mma_f16(dacc[nt][0], dacc[nt][1], dacc[nt][2], dacc[nt][3],
                                a0, a1, a2, a3, Vw[bw], Vw[bw + 4]);
                    }
                }
            }
            if (t < 31) BARSYNC(1, 256);                 // release sS / ring slots
        }

        // ---- finalize (consumers only); ctx written as fp16
        BARSYNC(3, 128);
        if (half == 0) sCorr[srow] = 1.f / rsum;
        BARSYNC(3, 128);
        {
            const int prow = 16 * cw + g;
            float i0v = sCorr[prow];
            float i1v = sCorr[prow + 8];
            __half* ob = ctx + (size_t)(b * HH + h) * LL * DH;
#pragma unroll
            for (int nt = 0; nt < 4; nt++) {
                int sc = nt * 8 + 2 * tq;
                __half2 h0 = __floats2half2_rn(dacc[nt][0] * i0v, dacc[nt][1] * i0v);
                __half2 h1 = __floats2half2_rn(dacc[nt][2] * i1v, dacc[nt][3] * i1v);
                *(__half2*)(ob + (size_t)(I0 + prow) * DH + sc)     = h0;
                *(__half2*)(ob + (size_t)(I0 + prow + 8) * DH + sc) = h1;
            }
        }
    }
}

// ---------------------------------------------------------------------------
extern "C" void kernel_launch(void* const* d_in, const int* in_sizes, int n_in,
                              void* d_out, int out_size)
{
    const float* query = (const float*)d_in[0];
    const float* key   = (const float*)d_in[1];
    const float* value = (const float*)d_in[2];
    const float* pos   = (const float*)d_in[3];
    const float* Wq    = (const float*)d_in[4];
    const float* bq    = (const float*)d_in[5];
    const float* Wk    = (const float*)d_in[6];
    const float* bk    = (const float*)d_in[7];
    const float* Wv    = (const float*)d_in[8];
    const float* bv    = (const float*)d_in[9];
    const float* Wp    = (const float*)d_in[10];
    const float* ub    = (const float*)d_in[11];
    const float* vb    = (const float*)d_in[12];
    const float* Wo    = (const float*)d_in[13];
    const float* bo    = (const float*)d_in[14];

    float *pq;
    __half *pk, *pv, *pp, *pctx;
    cudaGetSymbolAddress((void**)&pq,   g_q);
    cudaGetSymbolAddress((void**)&pk,   g_kh);
    cudaGetSymbolAddress((void**)&pv,   g_vh);
    cudaGetSymbolAddress((void**)&pp,   g_ph);
    cudaGetSymbolAddress((void**)&pctx, g_ctxh);

    static int attr_set = 0;
    if (!attr_set) {
        cudaFuncSetAttribute(attn_mma, cudaFuncAttributeMaxDynamicSharedMemorySize, SMEM_BYTES);
        cudaFuncSetAttribute(qkvp_gemm, cudaFuncAttributeMaxDynamicSharedMemorySize, GSMEM_BYTES);
        cudaFuncSetAttribute(wo_gemm, cudaFuncAttributeMaxDynamicSharedMemorySize, GSMEM_BYTES);
        attr_set = 1;
    }

    preround<<<dim3(DM * DM / 1024, 1, 5), 256>>>(Wq, Wk, Wv, Wp, Wo);
    tohalf<<<(3 * QN + LL * DM) / 2048, 256>>>(query, key, value, pos);

    qkvp_gemm<<<dim3(DM / TGN, (BB * LL) / TGM, 4), 256, GSMEM_BYTES>>>(
        bq, bk, bv, pq);

    attn_mma<<<dim3(LL / TI, HH, BB), 256, SMEM_BYTES>>>(pq, pk, pv, pp, ub, vb, pctx);

    wo_gemm<<<dim3(DM / TGN, (BB * LL) / TGM), 256, GSMEM_BYTES>>>(
        bo, (float*)d_out);
}

// round 14
// speedup vs baseline: 6.5475x; 1.0011x over previous
#include <cuda_runtime.h>
#include <cuda_fp16.h>
#include <math.h>
#include <stdint.h>

#define BB 2
#define LL 2048
#define HH 16
#define DH 32
#define DM 512
#define SCALE 0.044194173824159216f  /* 1/sqrt(512) */
#define SC2 0.063764568f             /* SCALE * log2(e) */
#define QN (BB*LL*DM)                /* 2097152 */

__device__ float  g_q[BB*HH*LL*DH];
__device__ __half g_kh[BB*HH*LL*DH];
__device__ __half g_vh[BB*HH*LL*DH];   // transposed [b,h,dh,l]
__device__ __half g_ph[HH*LL*DH];
__device__ __half g_ctxh[BB*HH*LL*DH];
__device__ __half g_wh[5*DM*DM];       // fp16 Wq,Wk,Wv,Wp,Wo
__device__ __half g_inh[3*QN + LL*DM]; // fp16 query,key,value,pos

__device__ __forceinline__ void mma_f16(float& d0, float& d1, float& d2, float& d3,
                                        uint32_t a0, uint32_t a1, uint32_t a2, uint32_t a3,
                                        uint32_t b0, uint32_t b1) {
    asm volatile(
        "mma.sync.aligned.m16n8k16.row.col.f32.f16.f16.f32 "
        "{%0,%1,%2,%3}, {%4,%5,%6,%7}, {%8,%9}, {%0,%1,%2,%3};\n"
        : "+f"(d0), "+f"(d1), "+f"(d2), "+f"(d3)
        : "r"(a0), "r"(a1), "r"(a2), "r"(a3), "r"(b0), "r"(b1));
}

__device__ __forceinline__ void cp16(uint32_t dst, const void* src, int szbytes) {
    asm volatile("cp.async.cg.shared.global [%0], [%1], 16, %2;\n"
                 :: "r"(dst), "l"(src), "r"(szbytes));
}
__device__ __forceinline__ void cp_commit() {
    asm volatile("cp.async.commit_group;\n" ::: "memory");
}
template<int N>
__device__ __forceinline__ void cp_wait() {
    asm volatile("cp.async.wait_group %0;\n" :: "n"(N) : "memory");
}
#define BARSYNC(id, cnt) asm volatile("bar.sync %0, %1;" :: "r"(id), "r"(cnt) : "memory")

// ---------------------------------------------------------------------------
// preround: weights -> fp16. grid (256,1,5), 4 elems/thread
// ---------------------------------------------------------------------------
__global__ __launch_bounds__(256)
void preround(const float* __restrict__ w0, const float* __restrict__ w1,
              const float* __restrict__ w2, const float* __restrict__ w3,
              const float* __restrict__ w4)
{
    const float* src[5] = {w0, w1, w2, w3, w4};
    int z = blockIdx.z;
    int i = (blockIdx.x * 256 + threadIdx.x) * 4;
    float4 v = *(const float4*)(src[z] + i);
    __half2 h0 = __floats2half2_rn(v.x, v.y);
    __half2 h1 = __floats2half2_rn(v.z, v.w);
    *(uint2*)(g_wh + (size_t)z * DM * DM + i) =
        make_uint2(*(uint32_t*)&h0, *(uint32_t*)&h1);
}

// ---------------------------------------------------------------------------
// tohalf: inputs (query,key,value,pos) -> fp16 into g_inh. 8 elems/thread.
// ---------------------------------------------------------------------------
__global__ __launch_bounds__(256)
void tohalf(const float* __restrict__ q, const float* __restrict__ k,
            const float* __restrict__ v, const float* __restrict__ p)
{
    size_t i = ((size_t)blockIdx.x * 256 + threadIdx.x) * 8;
    const float* src; size_t off;
    if (i < (size_t)QN)          { src = q; off = i; }
    else if (i < (size_t)2 * QN) { src = k; off = i - QN; }
    else if (i < (size_t)3 * QN) { src = v; off = i - 2 * (size_t)QN; }
    else                         { src = p; off = i - 3 * (size_t)QN; }
    float4 a = *(const float4*)(src + off);
    float4 b = *(const float4*)(src + off + 4);
    __half2 h0 = __floats2half2_rn(a.x, a.y);
    __half2 h1 = __floats2half2_rn(a.z, a.w);
    __half2 h2 = __floats2half2_rn(b.x, b.y);
    __half2 h3 = __floats2half2_rn(b.z, b.w);
    *(uint4*)(g_inh + i) = make_uint4(*(uint32_t*)&h0, *(uint32_t*)&h1,
                                      *(uint32_t*)&h2, *(uint32_t*)&h3);
}

// ---------------------------------------------------------------------------
// fp16 GEMM core, cp.async double-buffered, m16n8k16, fp32 accum.
// ---------------------------------------------------------------------------
#define TGM 128
#define TGN 64
#define TGK 32
#define HGW 20
#define HA0 0
#define HA1 10240
#define HB0 20480
#define HB1 25600
#define GSMEM_BYTES 30720

__device__ __forceinline__ void gemm_core_h(
    const __half* __restrict__ A, const __half* __restrict__ W,
    const float* __restrict__ bias, void* __restrict__ Cv,
    int amode, int omode, char* smc)
{
    const int tid  = threadIdx.x;
    const int lane = tid & 31;
    const int warp = tid >> 5;
    const int g = lane >> 2;
    const int t = lane & 3;
    const int m0 = blockIdx.y * TGM;
    const int n0 = blockIdx.x * TGN;
    const uint32_t smb = (uint32_t)__cvta_generic_to_shared(smc);

    float acc[8][4];
#pragma unroll
    for (int nt = 0; nt < 8; nt++)
#pragma unroll
        for (int j = 0; j < 4; j++) acc[nt][j] = 0.f;

    auto issue = [&](int k0, int buf) {
        const int ab = buf ? HA1 : HA0;
        const int bb2 = buf ? HB1 : HB0;
#pragma unroll
        for (int i = 0; i < 2; i++) {
            int idx = tid + i * 256;
            int row = idx >> 2, c4 = idx & 3;
            int gm = m0 + row;
            const __half* src;
            if (amode == 0) {
                src = A + (size_t)gm * DM + k0 + c4 * 8;
            } else {
                int b = gm >> 11, l = gm & (LL - 1);
                int head = k0 >> 5;
                src = A + (((size_t)b * HH + head) * LL + l) * DH + c4 * 8;
            }
            cp16(smb + (uint32_t)(ab + row * 80 + c4 * 16), src, 16);
        }
        {
            int row = tid >> 2, c4 = tid & 3;
            const __half* src = W + (size_t)(n0 + row) * DM + k0 + c4 * 8;
            cp16(smb + (uint32_t)(bb2 + row * 80 + c4 * 16), src, 16);
        }
    };

    issue(0, 0);
    cp_commit();

    for (int c = 0; c < 16; c++) {
        cp_wait<0>();
        __syncthreads();
        if (c < 15) issue((c + 1) * TGK, (c + 1) & 1);
        cp_commit();

        const uint32_t* Aw = (const uint32_t*)(smc + ((c & 1) ? HA1 : HA0));
        const uint32_t* Bw = (const uint32_t*)(smc + ((c & 1) ? HB1 : HB0));
#pragma unroll
        for (int kt = 0; kt < 2; kt++) {
            int ar = warp * 16 + g;
            int aw0 = ar * HGW + t + 8 * kt;
            int aw1 = (ar + 8) * HGW + t + 8 * kt;
            uint32_t a0 = Aw[aw0], a1 = Aw[aw1];
            uint32_t a2 = Aw[aw0 + 4], a3 = Aw[aw1 + 4];
#pragma unroll
            for (int nt = 0; nt < 8; nt++) {
                int bw = (nt * 8 + g) * HGW + t + 8 * kt;
                mma_f16(acc[nt][0], acc[nt][1], acc[nt][2], acc[nt][3],
                        a0, a1, a2, a3, Bw[bw], Bw[bw + 4]);
            }
        }
    }

    const int sr = warp * 16 + g;
    const int gm = m0 + sr;
    const int bb = gm >> 11, l = gm & (LL - 1);
#pragma unroll
    for (int nt = 0; nt < 8; nt++) {
        int sc = nt * 8 + 2 * t;
        int n  = n0 + sc;
        float b0v = bias ? bias[n]     : 0.f;
        float b1v = bias ? bias[n + 1] : 0.f;
        float2 p0 = make_float2(acc[nt][0] + b0v, acc[nt][1] + b1v);
        float2 p1 = make_float2(acc[nt][2] + b0v, acc[nt][3] + b1v);
        if (omode == 0) {
            float* Cf = (float*)Cv;
            *(float2*)(Cf + (size_t)gm * DM + n)       = p0;
            *(float2*)(Cf + (size_t)(gm + 8) * DM + n) = p1;
        } else if (omode == 1) {
            float* Cf = (float*)Cv;
            int head = n >> 5, d = n & 31;
            float* base = Cf + (((size_t)bb * HH + head) * LL + l) * DH + d;
            *(float2*)(base)          = p0;
            *(float2*)(base + 8 * DH) = p1;
        } else if (omode == 2) {
            __half* Ch = (__half*)Cv;
            int head = n >> 5, d = n & 31;
            __half* base = Ch + (((size_t)bb * HH + head) * LL + l) * DH + d;
            __half2 h0 = __floats2half2_rn(p0.x, p0.y);
            __half2 h1 = __floats2half2_rn(p1.x, p1.y);
            *(__half2*)(base)          = h0;
            *(__half2*)(base + 8 * DH) = h1;
        } else {
            __half* Ch = (__half*)Cv;
            int head = n >> 5, d = n & 31;
            __half* base = Ch + (((size_t)bb * HH + head) * DH + d) * LL + l;
            base[0]      = __float2half_rn(p0.x);
            base[LL]     = __float2half_rn(p0.y);
            base[8]      = __float2half_rn(p1.x);
            base[LL + 8] = __float2half_rn(p1.y);
        }
    }
}

__global__ __launch_bounds__(256)
void qkvp_gemm(const float* __restrict__ bq, const float* __restrict__ bk,
               const float* __restrict__ bv)
{
    extern __shared__ char smc[];
    int z = blockIdx.z;
    if (z == 3 && blockIdx.y >= LL / TGM) return;
    const __half* A = g_inh + (size_t)z * QN;
    const __half* W = g_wh + (size_t)z * DM * DM;
    const float* b = (z == 0) ? bq : (z == 1) ? bk : (z == 2) ? bv : nullptr;
    void* C; int omode;
    if (z == 0)      { C = g_q;  omode = 1; }
    else if (z == 1) { C = g_kh; omode = 2; }
    else if (z == 2) { C = g_vh; omode = 3; }
    else             { C = g_ph; omode = 2; }
    gemm_core_h(A, W, b, C, 0, omode, smc);
}

__global__ __launch_bounds__(256)
void wo_gemm(const float* __restrict__ bias, float* __restrict__ C)
{
    extern __shared__ char smc[];
    gemm_core_h(g_ctxh, g_wh + (size_t)4 * DM * DM, bias, C, 1, 0, smc);
}

// ---------------------------------------------------------------------------
// Warp-specialized ring-band attention, fp16 operands + fp16 RESOLVED sW ring.
// Q pre-scaled by SCALE*log2e -> logits in log2 domain; exp via exp2f.
// Resolved sW: producer stores W[s][r] to row s-(r>=1); consumer reads
// res[srow][slot] unconditionally.
// Shift: r=j-i; r<=0 -> p[L-1+r]; r==1 -> 0; r>=2 -> row i+1 uses p[r-2]
// ---------------------------------------------------------------------------
#define TI 64
#define TJ 64
#define HW 20     /* K/P/Q tile word stride (80B rows) */
#define VW 36     /* V^T word stride (144B rows) */
#define PWW 38    /* weight buffer word stride */
#define SSTR 68
#define WSTRH 134 /* sW half stride: 67 words == 3 mod 32 -> conflict-free */
#define RING 128

#define QU_B 0        /* 64x80B  = 5120  (reused: K buf1) */
#define QV_B 5120     /* 65x80B  = 5200  (rows<58 reused: V buf1) */
#define K0_B 10320
#define V0_B 15440    /* 32x144B = 4608 */
#define P0_B 20048
#define P1_B 25168
#define SS_B 30288    /* 64x68x4 = 17408 */
#define PW_B 47696    /* 64x38x4 = 9728 */
#define SW_B 57424    /* 65x134x2 = 17420 */
#define SC_B 74844
#define SMEM_BYTES 75104

__global__ __launch_bounds__(256, 2)
void attn_mma(const float* __restrict__ qd, const __half* __restrict__ kd,
              const __half* __restrict__ vd, const __half* __restrict__ pd,
              const float* __restrict__ ub, const float* __restrict__ vb,
              __half* __restrict__ ctx)
{
    extern __shared__ char smc[];
    float*  sS    = (float*)(smc + SS_B);
    __half* sWh   = (__half*)(smc + SW_B);
    float*  sCorr = (float*)(smc + SC_B);
    const uint32_t smb = (uint32_t)__cvta_generic_to_shared(smc);

    const int tid  = threadIdx.x;
    const int lane = tid & 31;
    const int warp = tid >> 5;
    const int I0 = blockIdx.x * TI;
    const int h = blockIdx.y, b = blockIdx.z;

    const float*  qbase  = qd + (size_t)(b * HH + h) * LL * DH;
    const __half* kbase  = kd + (size_t)(b * HH + h) * LL * DH;
    const __half* vtbase = vd + (size_t)(b * HH + h) * DH * LL;
    const __half* pbase  = pd + (size_t)h * LL * DH;

    const int KbufB[2] = {K0_B, QU_B};
    const int VbufB[2] = {V0_B, QV_B};
    const int PbufB[2] = {P0_B, P1_B};

    // ---- stage Qu (64 rows) and Qv (65 rows) as rn-fp16, PRE-SCALED by SC2
    for (int idx = tid; idx < TI * 8; idx += 256) {
        int row = idx >> 3, c4 = idx & 7;
        float4 q  = *(const float4*)(qbase + (size_t)(I0 + row) * DH + c4 * 4);
        float4 u4 = *(const float4*)(ub + h * DH + c4 * 4);
        __half2 h0 = __floats2half2_rn((q.x + u4.x) * SC2, (q.y + u4.y) * SC2);
        __half2 h1 = __floats2half2_rn((q.z + u4.z) * SC2, (q.w + u4.w) * SC2);
        *(uint2*)(smc + QU_B + row * 80 + c4 * 8) =
            make_uint2(*(uint32_t*)&h0, *(uint32_t*)&h1);
    }
    for (int idx = tid; idx < (TI + 1) * 8; idx += 256) {
        int row = idx >> 3, c4 = idx & 7;
        int g = I0 + row;
        uint2 o = make_uint2(0u, 0u);
        if (g < LL) {
            float4 q  = *(const float4*)(qbase + (size_t)g * DH + c4 * 4);
            float4 v4 = *(const float4*)(vb + h * DH + c4 * 4);
            __half2 h0 = __floats2half2_rn((q.x + v4.x) * SC2, (q.y + v4.y) * SC2);
            __half2 h1 = __floats2half2_rn((q.z + v4.z) * SC2, (q.w + v4.w) * SC2);
            o = make_uint2(*(uint32_t*)&h0, *(uint32_t*)&h1);
        }
        *(uint2*)(smc + QV_B + row * 80 + c4 * 8) = o;
    }
    // ---- stage prologue band cols r in [-I0-64, -I0-1] into P1 (half)
    {
        const int r0 = -I0 - 64;
        int row = tid >> 2, c4 = tid & 3;
        int r = r0 + row;
        uint4 v = make_uint4(0u, 0u, 0u, 0u);
        if (r <= 0) { if (r >= 1 - LL) v = *(const uint4*)(pbase + (size_t)(LL - 1 + r) * DH + c4 * 8); }
        else if (r >= 2 && r <= LL + 1) v = *(const uint4*)(pbase + (size_t)(r - 2) * DH + c4 * 8);
        *(uint4*)(smc + P1_B + row * 80 + c4 * 16) = v;
    }
    __syncthreads();

    if (warp < 4) {
        // ========================= PRODUCER =========================
        const bool isS = (warp < 2);
        const int rw = warp & 1;
        const int g = lane >> 2, tq = lane & 3;

        auto issueKP = [&](int J0k, int J0p, int nb) {
#pragma unroll
            for (int i = 0; i < 2; i++) {
                int idx = tid + i * 128;
                int row = idx >> 2, c4 = idx & 3;
                cp16(smb + (uint32_t)(KbufB[nb] + row * 80 + c4 * 16),
                     kbase + (size_t)(J0k + row) * DH + c4 * 8, 16);
                int r = J0p - I0 + row;
                const __half* psrc = pbase;
                int sz = 0;
                if (r <= 0) { if (r >= 1 - LL) { psrc = pbase + (size_t)(LL - 1 + r) * DH + c4 * 8; sz = 16; } }
                else if (r >= 2 && r <= LL + 1) { psrc = pbase + (size_t)(r - 2) * DH + c4 * 8; sz = 16; }
                cp16(smb + (uint32_t)(PbufB[nb] + row * 80 + c4 * 16), psrc, sz);
            }
        };
        auto issueV = [&](int J0k, int nb) {
#pragma unroll
            for (int i = 0; i < 2; i++) {
                int idx = tid + i * 128;
                int ch = idx >> 3, c8 = idx & 7;
                cp16(smb + (uint32_t)(VbufB[nb] + ch * 144 + c8 * 16),
                     vtbase + (size_t)ch * LL + J0k + c8 * 8, 16);
            }
        };

        issueKP(0, 0, 0); cp_commit();   // A(0)
        issueV(0, 0);     cp_commit();   // B(0)

        // hoist fragments: 2 row-groups x 2 k-steps
        const uint32_t* Qsrc = (const uint32_t*)(smc + (isS ? QU_B : QV_B));
        uint32_t af[2][2][4];
#pragma unroll
        for (int mt = 0; mt < 2; mt++)
#pragma unroll
            for (int kt = 0; kt < 2; kt++) {
                int w0 = (rw * 32 + mt * 16 + g) * HW + tq + 8 * kt;
                int w1 = w0 + 8 * HW;
                af[mt][kt][0] = Qsrc[w0];     af[mt][kt][1] = Qsrc[w1];
                af[mt][kt][2] = Qsrc[w0 + 4]; af[mt][kt][3] = Qsrc[w1 + 4];
            }

        // prologue W-mma from P1 (band warps; all r<=0 -> no resolve shift)
        if (!isS) {
            const int slotbase = ((-I0 - 64) + 4096) & (RING - 1);
            const uint32_t* Pw = (const uint32_t*)(smc + P1_B);
#pragma unroll
            for (int mt = 0; mt < 2; mt++)
#pragma unroll
                for (int nt = 0; nt < 8; nt++) {
                    float d0 = 0.f, d1 = 0.f, d2 = 0.f, d3 = 0.f;
#pragma unroll
                    for (int kt = 0; kt < 2; kt++) {
                        int bw = (nt * 8 + g) * HW + tq + 8 * kt;
                        mma_f16(d0, d1, d2, d3,
                                af[mt][kt][0], af[mt][kt][1], af[mt][kt][2], af[mt][kt][3],
                                Pw[bw], Pw[bw + 4]);
                    }
                    int wr = rw * 32 + mt * 16 + g;
                    int wc = slotbase + nt * 8 + 2 * tq;
                    *(__half2*)&sWh[wr * WSTRH + wc]       = __floats2half2_rn(d0, d1);
                    *(__half2*)&sWh[(wr + 8) * WSTRH + wc] = __floats2half2_rn(d2, d3);
                }
        }
        BARSYNC(4, 128);   // producers done reading QU/P1 before overwrite

        for (int t = 0; t < 32; t++) {
            const int J0 = t * TJ;
            const int Jn = J0 + TJ;
            const int Jc = (Jn < LL) ? Jn : (LL - TJ);

            issueKP(Jc, Jn, (t + 1) & 1); cp_commit();   // A(t+1)
            cp_wait<2>();                                 // A(t) done

            const uint32_t* Bw = (const uint32_t*)(smc + (isS ? KbufB[t & 1] : PbufB[t & 1]));

            float reg[2][8][4];
#pragma unroll
            for (int mt = 0; mt < 2; mt++)
#pragma unroll
                for (int nt = 0; nt < 8; nt++) {
                    float d0 = 0.f, d1 = 0.f, d2 = 0.f, d3 = 0.f;
#pragma unroll
                    for (int kt = 0; kt < 2; kt++) {
                        int bw = (nt * 8 + g) * HW + tq + 8 * kt;
                        mma_f16(d0, d1, d2, d3,
                                af[mt][kt][0], af[mt][kt][1], af[mt][kt][2], af[mt][kt][3],
                                Bw[bw], Bw[bw + 4]);
                    }
                    reg[mt][nt][0] = d0; reg[mt][nt][1] = d1;
                    reg[mt][nt][2] = d2; reg[mt][nt][3] = d3;
                }
            float ereg = 0.f;
            if (!isS) {
                int t64 = tid - 64;
                const __half2* qv64 = (const __half2*)(smc + QV_B + 64 * 80);
                const __half2* pr   = (const __half2*)(smc + PbufB[t & 1] + t64 * 80);
#pragma unroll
                for (int c = 0; c < 16; c++) {
                    float2 a = __half22float2(qv64[c]);
                    float2 bb2 = __half22float2(pr[c]);
                    ereg += a.x * bb2.x + a.y * bb2.y;
                }
            }

            if (t > 0) BARSYNC(1, 256);                  // sS / ring-slots free

            issueV(Jc, (t + 1) & 1); cp_commit();        // B(t+1)
            cp_wait<2>();                                 // B(t) done

            const int r0 = J0 - I0;
            const int slotbase = (r0 + 4096) & (RING - 1);
            if (isS) {
#pragma unroll
                for (int mt = 0; mt < 2; mt++)
#pragma unroll
                    for (int nt = 0; nt < 8; nt++) {
                        int sr = rw * 32 + mt * 16 + g;
                        int sc = nt * 8 + 2 * tq;
                        *(float2*)&sS[sr * SSTR + sc]       = make_float2(reg[mt][nt][0], reg[mt][nt][1]);
                        *(float2*)&sS[(sr + 8) * SSTR + sc] = make_float2(reg[mt][nt][2], reg[mt][nt][3]);
                    }
            } else {
                // resolved store: W[s][r] -> row s-(r>=1)
                if (r0 >= 1 || r0 <= -63) {
                    const int sh = (r0 >= 1) ? 1 : 0;
#pragma unroll
                    for (int mt = 0; mt < 2; mt++)
#pragma unroll
                        for (int nt = 0; nt < 8; nt++) {
                            int wr = rw * 32 + mt * 16 + g - sh;
                            int wc = slotbase + nt * 8 + 2 * tq;
                            if (wr >= 0)
                                *(__half2*)&sWh[wr * WSTRH + wc] = __floats2half2_rn(reg[mt][nt][0], reg[mt][nt][1]);
                            *(__half2*)&sWh[(wr + 8) * WSTRH + wc] = __floats2half2_rn(reg[mt][nt][2], reg[mt][nt][3]);
                        }
                } else {
                    // mixed tile (once per block): per-half resolve
#pragma unroll
                    for (int mt = 0; mt < 2; mt++)
#pragma unroll
                        for (int nt = 0; nt < 8; nt++) {
                            int src_r = rw * 32 + mt * 16 + g;
                            int c0 = nt * 8 + 2 * tq;
#pragma unroll
                            for (int e = 0; e < 2; e++) {
                                int r = r0 + c0 + e;
                                int sh = (r >= 1) ? 1 : 0;
                                int wc = slotbase + c0 + e;
                                int w0r = src_r - sh;
                                if (w0r >= 0)
                                    sWh[w0r * WSTRH + wc] = __float2half_rn(reg[mt][nt][2 * 0 + e]);
                                sWh[(src_r + 8 - sh) * WSTRH + wc] = __float2half_rn(reg[mt][nt][2 + e]);
                            }
                        }
                }
                {   // extra row 64 -> resolved row 63 when its r >= 1
                    int t64 = tid - 64;
                    int r = r0 + t64;
                    if (r >= 1)
                        sWh[63 * WSTRH + slotbase + t64] = __float2half_rn(ereg);
                }
            }

            BARSYNC(2, 256);                             // publish S(t)/W(t)/V(t)
        }
    } else {
        // ========================= CONSUMER =========================
        const int cw = warp - 4;
        const int ctid = tid - 128;
        const int srow = ctid >> 1;
        const int half = ctid & 1;
        const int g = lane >> 2, tq = lane & 3;
        const int qi = I0 + srow;

        uint32_t* pwW = (uint32_t*)(smc + PW_B);
        const __half* bp0 = sWh + srow * WSTRH;
        float dacc[4][4];
#pragma unroll
        for (int nt = 0; nt < 4; nt++)
#pragma unroll
            for (int j = 0; j < 4; j++) dacc[nt][j] = 0.f;
        float rmax = -INFINITY, rsum = 0.f;

        for (int t = 0; t < 32; t++) {
            const int J0 = t * TJ;
            BARSYNC(2, 256);                             // S(t) ready

            // ---- softmax (log2 domain): thread (srow, half) owns 32 columns
            {
                float s[32];
#pragma unroll
                for (int k4 = 0; k4 < 8; k4++) {
                    float4 s4 = *(const float4*)&sS[srow * SSTR + half * 32 + k4 * 4];
                    s[k4 * 4 + 0] = s4.x; s[k4 * 4 + 1] = s4.y;
                    s[k4 * 4 + 2] = s4.z; s[k4 * 4 + 3] = s4.w;
                }
                const int rbase = J0 + half * 32 - qi;
                int slot = (rbase + 4096) & (RING - 1);
                float cmax = -INFINITY;
#pragma unroll
                for (int tt = 0; tt < 32; tt++) {
                    s[tt] += __half2float(bp0[slot]);
                    cmax = fmaxf(cmax, s[tt]);
                    slot = (slot + 1) & (RING - 1);
                }
                cmax = fmaxf(cmax, __shfl_xor_sync(0xffffffffu, cmax, 1));
                float mnew = fmaxf(rmax, cmax);
                float corr = exp2f(rmax - mnew);         // first tile: 2^-inf=0
                float csum = 0.f;
#pragma unroll
                for (int k2 = 0; k2 < 16; k2++) {
                    float e0 = exp2f(s[2 * k2]     - mnew);
                    float e1 = exp2f(s[2 * k2 + 1] - mnew);
                    __half2 hh = __floats2half2_rn(e0, e1);
                    float2 f2 = __half22float2(hh);
                    csum += f2.x + f2.y;
                    pwW[srow * PWW + half * 16 + k2] = *(uint32_t*)&hh;
                }
                csum += __shfl_xor_sync(0xffffffffu, csum, 1);
                rsum = rsum * corr + csum;
                rmax = mnew;
                if (half == 0) sCorr[srow] = corr;
            }
            BARSYNC(3, 128);                             // consumer-internal

            // ---- PV MMA: rows 16cw.., all 32 channels, k=64 in 4 k16 steps
            {
                const uint32_t* Vw = (const uint32_t*)(smc + VbufB[t & 1]);
                const int prow = 16 * cw + g;
                float c0 = sCorr[prow];
                float c1 = sCorr[prow + 8];
#pragma unroll
                for (int nt = 0; nt < 4; nt++) {
                    dacc[nt][0] *= c0; dacc[nt][1] *= c0;
                    dacc[nt][2] *= c1; dacc[nt][3] *= c1;
                }
#pragma unroll
                for (int kt = 0; kt < 4; kt++) {
                    int aw0 = prow * PWW + tq + 8 * kt;
                    int aw1 = (prow + 8) * PWW + tq + 8 * kt;
                    uint32_t a0 = pwW[aw0], a1 = pwW[aw1];
                    uint32_t a2 = pwW[aw0 + 4], a3 = pwW[aw1 + 4];
#pragma unroll
                    for (int nt = 0; nt < 4; nt++) {
                        int bw = (nt * 8 + g) * VW + tq + 8 * kt;
                        mma_f16(dacc[nt][0], dacc[nt][1], dacc[nt][2], dacc[nt][3],
                                a0, a1, a2, a3, Vw[bw], Vw[bw + 4]);
                    }
                }
            }
            if (t < 31) BARSYNC(1, 256);                 // release sS / ring slots
        }

        // ---- finalize (consumers only); ctx written as fp16
        BARSYNC(3, 128);
        if (half == 0) sCorr[srow] = 1.f / rsum;
        BARSYNC(3, 128);
        {
            const int prow = 16 * cw + g;
            float i0v = sCorr[prow];
            float i1v = sCorr[prow + 8];
            __half* ob = ctx + (size_t)(b * HH + h) * LL * DH;
#pragma unroll
            for (int nt = 0; nt < 4; nt++) {
                int sc = nt * 8 + 2 * tq;
                __half2 h0 = __floats2half2_rn(dacc[nt][0] * i0v, dacc[nt][1] * i0v);
                __half2 h1 = __floats2half2_rn(dacc[nt][2] * i1v, dacc[nt][3] * i1v);
                *(__half2*)(ob + (size_t)(I0 + prow) * DH + sc)     = h0;
                *(__half2*)(ob + (size_t)(I0 + prow + 8) * DH + sc) = h1;
            }
        }
    }
}

// ---------------------------------------------------------------------------
extern "C" void kernel_launch(void* const* d_in, const int* in_sizes, int n_in,
                              void* d_out, int out_size)
{
    const float* query = (const float*)d_in[0];
    const float* key   = (const float*)d_in[1];
    const float* value = (const float*)d_in[2];
    const float* pos   = (const float*)d_in[3];
    const float* Wq    = (const float*)d_in[4];
    const float* bq    = (const float*)d_in[5];
    const float* Wk    = (const float*)d_in[6];
    const float* bk    = (const float*)d_in[7];
    const float* Wv    = (const float*)d_in[8];
    const float* bv    = (const float*)d_in[9];
    const float* Wp    = (const float*)d_in[10];
    const float* ub    = (const float*)d_in[11];
    const float* vb    = (const float*)d_in[12];
    const float* Wo    = (const float*)d_in[13];
    const float* bo    = (const float*)d_in[14];

    float *pq;
    __half *pk, *pv, *pp, *pctx;
    cudaGetSymbolAddress((void**)&pq,   g_q);
    cudaGetSymbolAddress((void**)&pk,   g_kh);
    cudaGetSymbolAddress((void**)&pv,   g_vh);
    cudaGetSymbolAddress((void**)&pp,   g_ph);
    cudaGetSymbolAddress((void**)&pctx, g_ctxh);

    static int attr_set = 0;
    if (!attr_set) {
        cudaFuncSetAttribute(attn_mma, cudaFuncAttributeMaxDynamicSharedMemorySize, SMEM_BYTES);
        cudaFuncSetAttribute(qkvp_gemm, cudaFuncAttributeMaxDynamicSharedMemorySize, GSMEM_BYTES);
        cudaFuncSetAttribute(wo_gemm, cudaFuncAttributeMaxDynamicSharedMemorySize, GSMEM_BYTES);
        attr_set = 1;
    }

    preround<<<dim3(DM * DM / 1024, 1, 5), 256>>>(Wq, Wk, Wv, Wp, Wo);
    tohalf<<<(3 * QN + LL * DM) / 2048, 256>>>(query, key, value, pos);

    qkvp_gemm<<<dim3(DM / TGN, (BB * LL) / TGM, 4), 256, GSMEM_BYTES>>>(bq, bk, bv);

    attn_mma<<<dim3(LL / TI, HH, BB), 256, SMEM_BYTES>>>(pq, pk, pv, pp, ub, vb, pctx);

    wo_gemm<<<dim3(DM / TGN, (BB * LL) / TGM), 256, GSMEM_BYTES>>>(
        bo, (float*)d_out);
}

// round 15
// speedup vs baseline: 6.8363x; 1.0441x over previous
#include <cuda_runtime.h>
#include <cuda_fp16.h>
#include <math.h>
#include <stdint.h>

#define BB 2
#define LL 2048
#define HH 16
#define DH 32
#define DM 512
#define SCALE 0.044194173824159216f  /* 1/sqrt(512) */
#define SC2 0.063764568f             /* SCALE * log2(e) */
#define QN (BB*LL*DM)                /* 2097152 */

__device__ float  g_q[BB*HH*LL*DH];
__device__ __half g_kh[BB*HH*LL*DH];
__device__ __half g_vh[BB*HH*LL*DH];   // transposed [b,h,dh,l]
__device__ __half g_ph[HH*LL*DH];
__device__ __half g_ctxh[BB*HH*LL*DH];
__device__ __half g_wh[5*DM*DM];       // fp16 Wq,Wk,Wv,Wp,Wo
__device__ __half g_inh[3*QN + LL*DM]; // fp16 query,key,value,pos

__device__ __forceinline__ void mma_f16(float& d0, float& d1, float& d2, float& d3,
                                        uint32_t a0, uint32_t a1, uint32_t a2, uint32_t a3,
                                        uint32_t b0, uint32_t b1) {
    asm volatile(
        "mma.sync.aligned.m16n8k16.row.col.f32.f16.f16.f32 "
        "{%0,%1,%2,%3}, {%4,%5,%6,%7}, {%8,%9}, {%0,%1,%2,%3};\n"
        : "+f"(d0), "+f"(d1), "+f"(d2), "+f"(d3)
        : "r"(a0), "r"(a1), "r"(a2), "r"(a3), "r"(b0), "r"(b1));
}

__device__ __forceinline__ void cp16(uint32_t dst, const void* src, int szbytes) {
    asm volatile("cp.async.cg.shared.global [%0], [%1], 16, %2;\n"
                 :: "r"(dst), "l"(src), "r"(szbytes));
}
__device__ __forceinline__ void cp_commit() {
    asm volatile("cp.async.commit_group;\n" ::: "memory");
}
template<int N>
__device__ __forceinline__ void cp_wait() {
    asm volatile("cp.async.wait_group %0;\n" :: "n"(N) : "memory");
}
#define BARSYNC(id, cnt) asm volatile("bar.sync %0, %1;" :: "r"(id), "r"(cnt) : "memory")

// ---------------------------------------------------------------------------
// preround: weights -> fp16. grid (256,1,5), 4 elems/thread
// ---------------------------------------------------------------------------
__global__ __launch_bounds__(256)
void preround(const float* __restrict__ w0, const float* __restrict__ w1,
              const float* __restrict__ w2, const float* __restrict__ w3,
              const float* __restrict__ w4)
{
    const float* src[5] = {w0, w1, w2, w3, w4};
    int z = blockIdx.z;
    int i = (blockIdx.x * 256 + threadIdx.x) * 4;
    float4 v = *(const float4*)(src[z] + i);
    __half2 h0 = __floats2half2_rn(v.x, v.y);
    __half2 h1 = __floats2half2_rn(v.z, v.w);
    *(uint2*)(g_wh + (size_t)z * DM * DM + i) =
        make_uint2(*(uint32_t*)&h0, *(uint32_t*)&h1);
}

// ---------------------------------------------------------------------------
// tohalf: inputs (query,key,value,pos) -> fp16 into g_inh. 8 elems/thread.
// ---------------------------------------------------------------------------
__global__ __launch_bounds__(256)
void tohalf(const float* __restrict__ q, const float* __restrict__ k,
            const float* __restrict__ v, const float* __restrict__ p)
{
    size_t i = ((size_t)blockIdx.x * 256 + threadIdx.x) * 8;
    const float* src; size_t off;
    if (i < (size_t)QN)          { src = q; off = i; }
    else if (i < (size_t)2 * QN) { src = k; off = i - QN; }
    else if (i < (size_t)3 * QN) { src = v; off = i - 2 * (size_t)QN; }
    else                         { src = p; off = i - 3 * (size_t)QN; }
    float4 a = *(const float4*)(src + off);
    float4 b = *(const float4*)(src + off + 4);
    __half2 h0 = __floats2half2_rn(a.x, a.y);
    __half2 h1 = __floats2half2_rn(a.z, a.w);
    __half2 h2 = __floats2half2_rn(b.x, b.y);
    __half2 h3 = __floats2half2_rn(b.z, b.w);
    *(uint4*)(g_inh + i) = make_uint4(*(uint32_t*)&h0, *(uint32_t*)&h1,
                                      *(uint32_t*)&h2, *(uint32_t*)&h3);
}

// ---------------------------------------------------------------------------
// fp16 GEMM core, cp.async double-buffered, m16n8k16, fp32 accum.
// ---------------------------------------------------------------------------
#define TGM 128
#define TGN 64
#define TGK 32
#define HGW 20
#define HA0 0
#define HA1 10240
#define HB0 20480
#define HB1 25600
#define GSMEM_BYTES 30720

__device__ __forceinline__ void gemm_core_h(
    const __half* __restrict__ A, const __half* __restrict__ W,
    const float* __restrict__ bias, void* __restrict__ Cv,
    int amode, int omode, char* smc)
{
    const int tid  = threadIdx.x;
    const int lane = tid & 31;
    const int warp = tid >> 5;
    const int g = lane >> 2;
    const int t = lane & 3;
    const int m0 = blockIdx.y * TGM;
    const int n0 = blockIdx.x * TGN;
    const uint32_t smb = (uint32_t)__cvta_generic_to_shared(smc);

    float acc[8][4];
#pragma unroll
    for (int nt = 0; nt < 8; nt++)
#pragma unroll
        for (int j = 0; j < 4; j++) acc[nt][j] = 0.f;

    auto issue = [&](int k0, int buf) {
        const int ab = buf ? HA1 : HA0;
        const int bb2 = buf ? HB1 : HB0;
#pragma unroll
        for (int i = 0; i < 2; i++) {
            int idx = tid + i * 256;
            int row = idx >> 2, c4 = idx & 3;
            int gm = m0 + row;
            const __half* src;
            if (amode == 0) {
                src = A + (size_t)gm * DM + k0 + c4 * 8;
            } else {
                int b = gm >> 11, l = gm & (LL - 1);
                int head = k0 >> 5;
                src = A + (((size_t)b * HH + head) * LL + l) * DH + c4 * 8;
            }
            cp16(smb + (uint32_t)(ab + row * 80 + c4 * 16), src, 16);
        }
        {
            int row = tid >> 2, c4 = tid & 3;
            const __half* src = W + (size_t)(n0 + row) * DM + k0 + c4 * 8;
            cp16(smb + (uint32_t)(bb2 + row * 80 + c4 * 16), src, 16);
        }
    };

    issue(0, 0);
    cp_commit();

    for (int c = 0; c < 16; c++) {
        cp_wait<0>();
        __syncthreads();
        if (c < 15) issue((c + 1) * TGK, (c + 1) & 1);
        cp_commit();

        const uint32_t* Aw = (const uint32_t*)(smc + ((c & 1) ? HA1 : HA0));
        const uint32_t* Bw = (const uint32_t*)(smc + ((c & 1) ? HB1 : HB0));
#pragma unroll
        for (int kt = 0; kt < 2; kt++) {
            int ar = warp * 16 + g;
            int aw0 = ar * HGW + t + 8 * kt;
            int aw1 = (ar + 8) * HGW + t + 8 * kt;
            uint32_t a0 = Aw[aw0], a1 = Aw[aw1];
            uint32_t a2 = Aw[aw0 + 4], a3 = Aw[aw1 + 4];
#pragma unroll
            for (int nt = 0; nt < 8; nt++) {
                int bw = (nt * 8 + g) * HGW + t + 8 * kt;
                mma_f16(acc[nt][0], acc[nt][1], acc[nt][2], acc[nt][3],
                        a0, a1, a2, a3, Bw[bw], Bw[bw + 4]);
            }
        }
    }

    const int sr = warp * 16 + g;
    const int gm = m0 + sr;
    const int bb = gm >> 11, l = gm & (LL - 1);
#pragma unroll
    for (int nt = 0; nt < 8; nt++) {
        int sc = nt * 8 + 2 * t;
        int n  = n0 + sc;
        float b0v = bias ? bias[n]     : 0.f;
        float b1v = bias ? bias[n + 1] : 0.f;
        float2 p0 = make_float2(acc[nt][0] + b0v, acc[nt][1] + b1v);
        float2 p1 = make_float2(acc[nt][2] + b0v, acc[nt][3] + b1v);
        if (omode == 0) {
            float* Cf = (float*)Cv;
            *(float2*)(Cf + (size_t)gm * DM + n)       = p0;
            *(float2*)(Cf + (size_t)(gm + 8) * DM + n) = p1;
        } else if (omode == 1) {
            float* Cf = (float*)Cv;
            int head = n >> 5, d = n & 31;
            float* base = Cf + (((size_t)bb * HH + head) * LL + l) * DH + d;
            *(float2*)(base)          = p0;
            *(float2*)(base + 8 * DH) = p1;
        } else if (omode == 2) {
            __half* Ch = (__half*)Cv;
            int head = n >> 5, d = n & 31;
            __half* base = Ch + (((size_t)bb * HH + head) * LL + l) * DH + d;
            __half2 h0 = __floats2half2_rn(p0.x, p0.y);
            __half2 h1 = __floats2half2_rn(p1.x, p1.y);
            *(__half2*)(base)          = h0;
            *(__half2*)(base + 8 * DH) = h1;
        } else {
            __half* Ch = (__half*)Cv;
            int head = n >> 5, d = n & 31;
            __half* base = Ch + (((size_t)bb * HH + head) * DH + d) * LL + l;
            base[0]      = __float2half_rn(p0.x);
            base[LL]     = __float2half_rn(p0.y);
            base[8]      = __float2half_rn(p1.x);
            base[LL + 8] = __float2half_rn(p1.y);
        }
    }
}

__global__ __launch_bounds__(256)
void qkvp_gemm(const float* __restrict__ bq, const float* __restrict__ bk,
               const float* __restrict__ bv)
{
    extern __shared__ char smc[];
    int z = blockIdx.z;
    if (z == 3 && blockIdx.y >= LL / TGM) return;
    const __half* A = g_inh + (size_t)z * QN;
    const __half* W = g_wh + (size_t)z * DM * DM;
    const float* b = (z == 0) ? bq : (z == 1) ? bk : (z == 2) ? bv : nullptr;
    void* C; int omode;
    if (z == 0)      { C = g_q;  omode = 1; }
    else if (z == 1) { C = g_kh; omode = 2; }
    else if (z == 2) { C = g_vh; omode = 3; }
    else             { C = g_ph; omode = 2; }
    gemm_core_h(A, W, b, C, 0, omode, smc);
}

__global__ __launch_bounds__(256)
void wo_gemm(const float* __restrict__ bias, float* __restrict__ C)
{
    extern __shared__ char smc[];
    gemm_core_h(g_ctxh, g_wh + (size_t)4 * DM * DM, bias, C, 1, 0, smc);
}

// ---------------------------------------------------------------------------
// Warp-specialized ring-band attention, fp16 operands + fp16 RESOLVED sW ring.
// Q pre-scaled by SCALE*log2e -> log2-domain logits; exp via exp2f.
// Gather reads the ring as aligned u32 words + PRMT realign (no scalar LDS).
// Shift: r=j-i; r<=0 -> p[L-1+r]; r==1 -> 0; r>=2 -> row i+1 uses p[r-2]
// ---------------------------------------------------------------------------
#define TI 64
#define TJ 64
#define HW 20     /* K/P/Q tile word stride (80B rows) */
#define VW 36     /* V^T word stride (144B rows) */
#define PWW 38    /* weight buffer word stride */
#define SSTR 68
#define WSTRH 134 /* sW half stride (67 words, == 3 mod 32) */
#define RING 128

#define QU_B 0        /* 64x80B  = 5120  (reused: K buf1) */
#define QV_B 5120     /* 65x80B  = 5200  (rows<58 reused: V buf1) */
#define K0_B 10320
#define V0_B 15440    /* 32x144B = 4608 */
#define P0_B 20048
#define P1_B 25168
#define SS_B 30288    /* 64x68x4 = 17408 */
#define PW_B 47696    /* 64x38x4 = 9728 */
#define SW_B 57424    /* 65x134x2 = 17420 */
#define SC_B 74844
#define SMEM_BYTES 75104

__global__ __launch_bounds__(256, 2)
void attn_mma(const float* __restrict__ qd, const __half* __restrict__ kd,
              const __half* __restrict__ vd, const __half* __restrict__ pd,
              const float* __restrict__ ub, const float* __restrict__ vb,
              __half* __restrict__ ctx)
{
    extern __shared__ char smc[];
    float*  sS    = (float*)(smc + SS_B);
    __half* sWh   = (__half*)(smc + SW_B);
    float*  sCorr = (float*)(smc + SC_B);
    const uint32_t smb = (uint32_t)__cvta_generic_to_shared(smc);

    const int tid  = threadIdx.x;
    const int lane = tid & 31;
    const int warp = tid >> 5;
    const int I0 = blockIdx.x * TI;
    const int h = blockIdx.y, b = blockIdx.z;

    const float*  qbase  = qd + (size_t)(b * HH + h) * LL * DH;
    const __half* kbase  = kd + (size_t)(b * HH + h) * LL * DH;
    const __half* vtbase = vd + (size_t)(b * HH + h) * DH * LL;
    const __half* pbase  = pd + (size_t)h * LL * DH;

    const int KbufB[2] = {K0_B, QU_B};
    const int VbufB[2] = {V0_B, QV_B};
    const int PbufB[2] = {P0_B, P1_B};

    // ---- stage Qu (64 rows) and Qv (65 rows) as rn-fp16, PRE-SCALED by SC2
    for (int idx = tid; idx < TI * 8; idx += 256) {
        int row = idx >> 3, c4 = idx & 7;
        float4 q  = *(const float4*)(qbase + (size_t)(I0 + row) * DH + c4 * 4);
        float4 u4 = *(const float4*)(ub + h * DH + c4 * 4);
        __half2 h0 = __floats2half2_rn((q.x + u4.x) * SC2, (q.y + u4.y) * SC2);
        __half2 h1 = __floats2half2_rn((q.z + u4.z) * SC2, (q.w + u4.w) * SC2);
        *(uint2*)(smc + QU_B + row * 80 + c4 * 8) =
            make_uint2(*(uint32_t*)&h0, *(uint32_t*)&h1);
    }
    for (int idx = tid; idx < (TI + 1) * 8; idx += 256) {
        int row = idx >> 3, c4 = idx & 7;
        int g = I0 + row;
        uint2 o = make_uint2(0u, 0u);
        if (g < LL) {
            float4 q  = *(const float4*)(qbase + (size_t)g * DH + c4 * 4);
            float4 v4 = *(const float4*)(vb + h * DH + c4 * 4);
            __half2 h0 = __floats2half2_rn((q.x + v4.x) * SC2, (q.y + v4.y) * SC2);
            __half2 h1 = __floats2half2_rn((q.z + v4.z) * SC2, (q.w + v4.w) * SC2);
            o = make_uint2(*(uint32_t*)&h0, *(uint32_t*)&h1);
        }
        *(uint2*)(smc + QV_B + row * 80 + c4 * 8) = o;
    }
    // ---- stage prologue band cols r in [-I0-64, -I0-1] into P1 (half)
    {
        const int r0 = -I0 - 64;
        int row = tid >> 2, c4 = tid & 3;
        int r = r0 + row;
        uint4 v = make_uint4(0u, 0u, 0u, 0u);
        if (r <= 0) { if (r >= 1 - LL) v = *(const uint4*)(pbase + (size_t)(LL - 1 + r) * DH + c4 * 8); }
        else if (r >= 2 && r <= LL + 1) v = *(const uint4*)(pbase + (size_t)(r - 2) * DH + c4 * 8);
        *(uint4*)(smc + P1_B + row * 80 + c4 * 16) = v;
    }
    __syncthreads();

    if (warp < 4) {
        // ========================= PRODUCER =========================
        const bool isS = (warp < 2);
        const int rw = warp & 1;
        const int g = lane >> 2, tq = lane & 3;

        auto issueKP = [&](int J0k, int J0p, int nb) {
#pragma unroll
            for (int i = 0; i < 2; i++) {
                int idx = tid + i * 128;
                int row = idx >> 2, c4 = idx & 3;
                cp16(smb + (uint32_t)(KbufB[nb] + row * 80 + c4 * 16),
                     kbase + (size_t)(J0k + row) * DH + c4 * 8, 16);
                int r = J0p - I0 + row;
                const __half* psrc = pbase;
                int sz = 0;
                if (r <= 0) { if (r >= 1 - LL) { psrc = pbase + (size_t)(LL - 1 + r) * DH + c4 * 8; sz = 16; } }
                else if (r >= 2 && r <= LL + 1) { psrc = pbase + (size_t)(r - 2) * DH + c4 * 8; sz = 16; }
                cp16(smb + (uint32_t)(PbufB[nb] + row * 80 + c4 * 16), psrc, sz);
            }
        };
        auto issueV = [&](int J0k, int nb) {
#pragma unroll
            for (int i = 0; i < 2; i++) {
                int idx = tid + i * 128;
                int ch = idx >> 3, c8 = idx & 7;
                cp16(smb + (uint32_t)(VbufB[nb] + ch * 144 + c8 * 16),
                     vtbase + (size_t)ch * LL + J0k + c8 * 8, 16);
            }
        };

        issueKP(0, 0, 0); cp_commit();   // A(0)
        issueV(0, 0);     cp_commit();   // B(0)

        // hoist fragments: 2 row-groups x 2 k-steps
        const uint32_t* Qsrc = (const uint32_t*)(smc + (isS ? QU_B : QV_B));
        uint32_t af[2][2][4];
#pragma unroll
        for (int mt = 0; mt < 2; mt++)
#pragma unroll
            for (int kt = 0; kt < 2; kt++) {
                int w0 = (rw * 32 + mt * 16 + g) * HW + tq + 8 * kt;
                int w1 = w0 + 8 * HW;
                af[mt][kt][0] = Qsrc[w0];     af[mt][kt][1] = Qsrc[w1];
                af[mt][kt][2] = Qsrc[w0 + 4]; af[mt][kt][3] = Qsrc[w1 + 4];
            }

        // prologue W-mma from P1 (band warps; all r<=0 -> no resolve shift)
        if (!isS) {
            const int slotbase = ((-I0 - 64) + 4096) & (RING - 1);
            const uint32_t* Pw = (const uint32_t*)(smc + P1_B);
#pragma unroll
            for (int nt = 0; nt < 8; nt++) {
                uint32_t pb0[2], pb1[2];
#pragma unroll
                for (int kt = 0; kt < 2; kt++) {
                    int bw = (nt * 8 + g) * HW + tq + 8 * kt;
                    pb0[kt] = Pw[bw]; pb1[kt] = Pw[bw + 4];
                }
#pragma unroll
                for (int mt = 0; mt < 2; mt++) {
                    float d0 = 0.f, d1 = 0.f, d2 = 0.f, d3 = 0.f;
#pragma unroll
                    for (int kt = 0; kt < 2; kt++)
                        mma_f16(d0, d1, d2, d3,
                                af[mt][kt][0], af[mt][kt][1], af[mt][kt][2], af[mt][kt][3],
                                pb0[kt], pb1[kt]);
                    int wr = rw * 32 + mt * 16 + g;
                    int wc = slotbase + nt * 8 + 2 * tq;
                    *(__half2*)&sWh[wr * WSTRH + wc]       = __floats2half2_rn(d0, d1);
                    *(__half2*)&sWh[(wr + 8) * WSTRH + wc] = __floats2half2_rn(d2, d3);
                }
            }
        }
        BARSYNC(4, 128);   // producers done reading QU/P1 before overwrite

        for (int t = 0; t < 32; t++) {
            const int J0 = t * TJ;
            const int Jn = J0 + TJ;
            const int Jc = (Jn < LL) ? Jn : (LL - TJ);

            issueKP(Jc, Jn, (t + 1) & 1); cp_commit();   // A(t+1)
            cp_wait<2>();                                 // A(t) done

            const uint32_t* Bw = (const uint32_t*)(smc + (isS ? KbufB[t & 1] : PbufB[t & 1]));

            float reg[2][8][4];
#pragma unroll
            for (int nt = 0; nt < 8; nt++) {
                uint32_t fb0[2], fb1[2];
#pragma unroll
                for (int kt = 0; kt < 2; kt++) {
                    int bw = (nt * 8 + g) * HW + tq + 8 * kt;
                    fb0[kt] = Bw[bw]; fb1[kt] = Bw[bw + 4];
                }
#pragma unroll
                for (int mt = 0; mt < 2; mt++) {
                    float d0 = 0.f, d1 = 0.f, d2 = 0.f, d3 = 0.f;
#pragma unroll
                    for (int kt = 0; kt < 2; kt++)
                        mma_f16(d0, d1, d2, d3,
                                af[mt][kt][0], af[mt][kt][1], af[mt][kt][2], af[mt][kt][3],
                                fb0[kt], fb1[kt]);
                    reg[mt][nt][0] = d0; reg[mt][nt][1] = d1;
                    reg[mt][nt][2] = d2; reg[mt][nt][3] = d3;
                }
            }
            float ereg = 0.f;
            if (!isS) {
                int t64 = tid - 64;
                const __half2* qv64 = (const __half2*)(smc + QV_B + 64 * 80);
                const __half2* pr   = (const __half2*)(smc + PbufB[t & 1] + t64 * 80);
#pragma unroll
                for (int c = 0; c < 16; c++) {
                    float2 a = __half22float2(qv64[c]);
                    float2 bb2 = __half22float2(pr[c]);
                    ereg += a.x * bb2.x + a.y * bb2.y;
                }
            }

            if (t > 0) BARSYNC(1, 256);                  // sS / ring-slots free

            issueV(Jc, (t + 1) & 1); cp_commit();        // B(t+1)
            cp_wait<2>();                                 // B(t) done

            const int r0 = J0 - I0;
            const int slotbase = (r0 + 4096) & (RING - 1);
            if (isS) {
#pragma unroll
                for (int mt = 0; mt < 2; mt++)
#pragma unroll
                    for (int nt = 0; nt < 8; nt++) {
                        int sr = rw * 32 + mt * 16 + g;
                        int sc = nt * 8 + 2 * tq;
                        *(float2*)&sS[sr * SSTR + sc]       = make_float2(reg[mt][nt][0], reg[mt][nt][1]);
                        *(float2*)&sS[(sr + 8) * SSTR + sc] = make_float2(reg[mt][nt][2], reg[mt][nt][3]);
                    }
            } else {
                // resolved store: W[s][r] -> row s-(r>=1)
                if (r0 >= 1 || r0 <= -63) {
                    const int sh = (r0 >= 1) ? 1 : 0;
#pragma unroll
                    for (int mt = 0; mt < 2; mt++)
#pragma unroll
                        for (int nt = 0; nt < 8; nt++) {
                            int wr = rw * 32 + mt * 16 + g - sh;
                            int wc = slotbase + nt * 8 + 2 * tq;
                            if (wr >= 0)
                                *(__half2*)&sWh[wr * WSTRH + wc] = __floats2half2_rn(reg[mt][nt][0], reg[mt][nt][1]);
                            *(__half2*)&sWh[(wr + 8) * WSTRH + wc] = __floats2half2_rn(reg[mt][nt][2], reg[mt][nt][3]);
                        }
                } else {
                    // mixed tile (once per block): per-half resolve
#pragma unroll
                    for (int mt = 0; mt < 2; mt++)
#pragma unroll
                        for (int nt = 0; nt < 8; nt++) {
                            int src_r = rw * 32 + mt * 16 + g;
                            int c0 = nt * 8 + 2 * tq;
#pragma unroll
                            for (int e = 0; e < 2; e++) {
                                int r = r0 + c0 + e;
                                int sh = (r >= 1) ? 1 : 0;
                                int wc = slotbase + c0 + e;
                                int w0r = src_r - sh;
                                if (w0r >= 0)
                                    sWh[w0r * WSTRH + wc] = __float2half_rn(reg[mt][nt][2 * 0 + e]);
                                sWh[(src_r + 8 - sh) * WSTRH + wc] = __float2half_rn(reg[mt][nt][2 + e]);
                            }
                        }
                }
                {   // extra row 64 -> resolved row 63 when its r >= 1
                    int t64 = tid - 64;
                    int r = r0 + t64;
                    if (r >= 1)
                        sWh[63 * WSTRH + slotbase + t64] = __float2half_rn(ereg);
                }
            }

            BARSYNC(2, 256);                             // publish S(t)/W(t)/V(t)
        }
    } else {
        // ========================= CONSUMER =========================
        const int cw = warp - 4;
        const int ctid = tid - 128;
        const int srow = ctid >> 1;
        const int half = ctid & 1;
        const int g = lane >> 2, tq = lane & 3;
        const int qi = I0 + srow;

        uint32_t* pwW = (uint32_t*)(smc + PW_B);
        const uint32_t* rowW = (const uint32_t*)(sWh + srow * WSTRH);  // even byte offset
        float dacc[4][4];
#pragma unroll
        for (int nt = 0; nt < 4; nt++)
#pragma unroll
            for (int j = 0; j < 4; j++) dacc[nt][j] = 0.f;
        float rmax = -INFINITY, rsum = 0.f;

        for (int t = 0; t < 32; t++) {
            const int J0 = t * TJ;
            BARSYNC(2, 256);                             // S(t) ready

            // ---- softmax (log2 domain): thread (srow, half) owns 32 columns
            {
                float s[32];
#pragma unroll
                for (int k4 = 0; k4 < 8; k4++) {
                    float4 s4 = *(const float4*)&sS[srow * SSTR + half * 32 + k4 * 4];
                    s[k4 * 4 + 0] = s4.x; s[k4 * 4 + 1] = s4.y;
                    s[k4 * 4 + 2] = s4.z; s[k4 * 4 + 3] = s4.w;
                }
                const int rbase = J0 + half * 32 - qi;
                const int slot = (rbase + 4096) & (RING - 1);
                const int wslot = slot >> 1;
                const uint32_t sel = (slot & 1) ? 0x5432u : 0x3210u;
                uint32_t wprev = rowW[wslot & 63];
                float cmax = -INFINITY;
#pragma unroll
                for (int k = 0; k < 16; k++) {
                    uint32_t wk = rowW[(wslot + k + 1) & 63];
                    uint32_t pairb = __byte_perm(wprev, wk, sel);
                    wprev = wk;
                    float2 f2 = __half22float2(*(__half2*)&pairb);
                    s[2 * k]     += f2.x;
                    s[2 * k + 1] += f2.y;
                    cmax = fmaxf(cmax, fmaxf(s[2 * k], s[2 * k + 1]));
                }
                cmax = fmaxf(cmax, __shfl_xor_sync(0xffffffffu, cmax, 1));
                float mnew = fmaxf(rmax, cmax);
                float corr = exp2f(rmax - mnew);         // first tile: 2^-inf=0
                float csum = 0.f;
#pragma unroll
                for (int k2 = 0; k2 < 16; k2++) {
                    float e0 = exp2f(s[2 * k2]     - mnew);
                    float e1 = exp2f(s[2 * k2 + 1] - mnew);
                    __half2 hh = __floats2half2_rn(e0, e1);
                    float2 f2 = __half22float2(hh);
                    csum += f2.x + f2.y;
                    pwW[srow * PWW + half * 16 + k2] = *(uint32_t*)&hh;
                }
                csum += __shfl_xor_sync(0xffffffffu, csum, 1);
                rsum = rsum * corr + csum;
                rmax = mnew;
                if (half == 0) sCorr[srow] = corr;
            }
            BARSYNC(3, 128);                             // consumer-internal

            // ---- PV MMA: rows 16cw.., all 32 channels, k=64 in 4 k16 steps
            {
                const uint32_t* Vw = (const uint32_t*)(smc + VbufB[t & 1]);
                const int prow = 16 * cw + g;
                float c0 = sCorr[prow];
                float c1 = sCorr[prow + 8];
#pragma unroll
                for (int nt = 0; nt < 4; nt++) {
                    dacc[nt][0] *= c0; dacc[nt][1] *= c0;
                    dacc[nt][2] *= c1; dacc[nt][3] *= c1;
                }
#pragma unroll
                for (int kt = 0; kt < 4; kt++) {
                    int aw0 = prow * PWW + tq + 8 * kt;
                    int aw1 = (prow + 8) * PWW + tq + 8 * kt;
                    uint32_t a0 = pwW[aw0], a1 = pwW[aw1];
                    uint32_t a2 = pwW[aw0 + 4], a3 = pwW[aw1 + 4];
#pragma unroll
                    for (int nt = 0; nt < 4; nt++) {
                        int bw = (nt * 8 + g) * VW + tq + 8 * kt;
                        mma_f16(dacc[nt][0], dacc[nt][1], dacc[nt][2], dacc[nt][3],
                                a0, a1, a2, a3, Vw[bw], Vw[bw + 4]);
                    }
                }
            }
            if (t < 31) BARSYNC(1, 256);                 // release sS / ring slots
        }

        // ---- finalize (consumers only); ctx written as fp16
        BARSYNC(3, 128);
        if (half == 0) sCorr[srow] = 1.f / rsum;
        BARSYNC(3, 128);
        {
            const int prow = 16 * cw + g;
            float i0v = sCorr[prow];
            float i1v = sCorr[prow + 8];
            __half* ob = ctx + (size_t)(b * HH + h) * LL * DH;
#pragma unroll
            for (int nt = 0; nt < 4; nt++) {
                int sc = nt * 8 + 2 * tq;
                __half2 h0 = __floats2half2_rn(dacc[nt][0] * i0v, dacc[nt][1] * i0v);
                __half2 h1 = __floats2half2_rn(dacc[nt][2] * i1v, dacc[nt][3] * i1v);
                *(__half2*)(ob + (size_t)(I0 + prow) * DH + sc)     = h0;
                *(__half2*)(ob + (size_t)(I0 + prow + 8) * DH + sc) = h1;
            }
        }
    }
}

// ---------------------------------------------------------------------------
extern "C" void kernel_launch(void* const* d_in, const int* in_sizes, int n_in,
                              void* d_out, int out_size)
{
    const float* query = (const float*)d_in[0];
    const float* key   = (const float*)d_in[1];
    const float* value = (const float*)d_in[2];
    const float* pos   = (const float*)d_in[3];
    const float* Wq    = (const float*)d_in[4];
    const float* bq    = (const float*)d_in[5];
    const float* Wk    = (const float*)d_in[6];
    const float* bk    = (const float*)d_in[7];
    const float* Wv    = (const float*)d_in[8];
    const float* bv    = (const float*)d_in[9];
    const float* Wp    = (const float*)d_in[10];
    const float* ub    = (const float*)d_in[11];
    const float* vb    = (const float*)d_in[12];
    const float* Wo    = (const float*)d_in[13];
    const float* bo    = (const float*)d_in[14];

    float *pq;
    __half *pk, *pv, *pp, *pctx;
    cudaGetSymbolAddress((void**)&pq,   g_q);
    cudaGetSymbolAddress((void**)&pk,   g_kh);
    cudaGetSymbolAddress((void**)&pv,   g_vh);
    cudaGetSymbolAddress((void**)&pp,   g_ph);
    cudaGetSymbolAddress((void**)&pctx, g_ctxh);

    static int attr_set = 0;
    if (!attr_set) {
        cudaFuncSetAttribute(attn_mma, cudaFuncAttributeMaxDynamicSharedMemorySize, SMEM_BYTES);
        cudaFuncSetAttribute(qkvp_gemm, cudaFuncAttributeMaxDynamicSharedMemorySize, GSMEM_BYTES);
        cudaFuncSetAttribute(wo_gemm, cudaFuncAttributeMaxDynamicSharedMemorySize, GSMEM_BYTES);
        attr_set = 1;
    }

    preround<<<dim3(DM * DM / 1024, 1, 5), 256>>>(Wq, Wk, Wv, Wp, Wo);
    tohalf<<<(3 * QN + LL * DM) / 2048, 256>>>(query, key, value, pos);

    qkvp_gemm<<<dim3(DM / TGN, (BB * LL) / TGM, 4), 256, GSMEM_BYTES>>>(bq, bk, bv);

    attn_mma<<<dim3(LL / TI, HH, BB), 256, SMEM_BYTES>>>(pq, pk, pv, pp, ub, vb, pctx);

    wo_gemm<<<dim3(DM / TGN, (BB * LL) / TGM), 256, GSMEM_BYTES>>>(
        bo, (float*)d_out);
}

// round 16
// speedup vs baseline: 8.5656x; 1.2530x over previous
#include <cuda_runtime.h>
#include <cuda_fp16.h>
#include <math.h>
#include <stdint.h>

#define BB 2
#define LL 2048
#define HH 16
#define DH 32
#define DM 512
#define SC2 0.063764568f             /* (1/sqrt(512)) * log2(e) */
#define QN (BB*LL*DM)                /* 2097152 */

__device__ float  g_q[BB*HH*LL*DH];
__device__ __half g_kh[BB*HH*LL*DH];
__device__ __half g_vh[BB*HH*LL*DH];   // transposed [b,h,dh,l]
__device__ __half g_ph[HH*LL*DH];
__device__ __half g_ctxh[BB*HH*LL*DH];
__device__ __half g_wh[5*DM*DM];       // fp16 Wq,Wk,Wv,Wp,Wo
__device__ __half g_inh[3*QN + LL*DM]; // fp16 query,key,value,pos

__device__ __forceinline__ void mma_f16(float& d0, float& d1, float& d2, float& d3,
                                        uint32_t a0, uint32_t a1, uint32_t a2, uint32_t a3,
                                        uint32_t b0, uint32_t b1) {
    asm volatile(
        "mma.sync.aligned.m16n8k16.row.col.f32.f16.f16.f32 "
        "{%0,%1,%2,%3}, {%4,%5,%6,%7}, {%8,%9}, {%0,%1,%2,%3};\n"
        : "+f"(d0), "+f"(d1), "+f"(d2), "+f"(d3)
        : "r"(a0), "r"(a1), "r"(a2), "r"(a3), "r"(b0), "r"(b1));
}

__device__ __forceinline__ void cp16(uint32_t dst, const void* src, int szbytes) {
    asm volatile("cp.async.cg.shared.global [%0], [%1], 16, %2;\n"
                 :: "r"(dst), "l"(src), "r"(szbytes));
}
__device__ __forceinline__ void cp_commit() {
    asm volatile("cp.async.commit_group;\n" ::: "memory");
}
template<int N>
__device__ __forceinline__ void cp_wait() {
    asm volatile("cp.async.wait_group %0;\n" :: "n"(N) : "memory");
}

// ---------------------------------------------------------------------------
// preround: weights -> fp16. grid (256,1,5), 4 elems/thread
// ---------------------------------------------------------------------------
__global__ __launch_bounds__(256)
void preround(const float* __restrict__ w0, const float* __restrict__ w1,
              const float* __restrict__ w2, const float* __restrict__ w3,
              const float* __restrict__ w4)
{
    const float* src[5] = {w0, w1, w2, w3, w4};
    int z = blockIdx.z;
    int i = (blockIdx.x * 256 + threadIdx.x) * 4;
    float4 v = *(const float4*)(src[z] + i);
    __half2 h0 = __floats2half2_rn(v.x, v.y);
    __half2 h1 = __floats2half2_rn(v.z, v.w);
    *(uint2*)(g_wh + (size_t)z * DM * DM + i) =
        make_uint2(*(uint32_t*)&h0, *(uint32_t*)&h1);
}

// ---------------------------------------------------------------------------
// tohalf: inputs (query,key,value,pos) -> fp16 into g_inh. 8 elems/thread.
// ---------------------------------------------------------------------------
__global__ __launch_bounds__(256)
void tohalf(const float* __restrict__ q, const float* __restrict__ k,
            const float* __restrict__ v, const float* __restrict__ p)
{
    size_t i = ((size_t)blockIdx.x * 256 + threadIdx.x) * 8;
    const float* src; size_t off;
    if (i < (size_t)QN)          { src = q; off = i; }
    else if (i < (size_t)2 * QN) { src = k; off = i - QN; }
    else if (i < (size_t)3 * QN) { src = v; off = i - 2 * (size_t)QN; }
    else                         { src = p; off = i - 3 * (size_t)QN; }
    float4 a = *(const float4*)(src + off);
    float4 b = *(const float4*)(src + off + 4);
    __half2 h0 = __floats2half2_rn(a.x, a.y);
    __half2 h1 = __floats2half2_rn(a.z, a.w);
    __half2 h2 = __floats2half2_rn(b.x, b.y);
    __half2 h3 = __floats2half2_rn(b.z, b.w);
    *(uint4*)(g_inh + i) = make_uint4(*(uint32_t*)&h0, *(uint32_t*)&h1,
                                      *(uint32_t*)&h2, *(uint32_t*)&h3);
}

// ---------------------------------------------------------------------------
// fp16 GEMM core, cp.async double-buffered, m16n8k16, fp32 accum. (unchanged)
// ---------------------------------------------------------------------------
#define TGM 128
#define TGN 64
#define TGK 32
#define HGW 20
#define HA0 0
#define HA1 10240
#define HB0 20480
#define HB1 25600
#define GSMEM_BYTES 30720

__device__ __forceinline__ void gemm_core_h(
    const __half* __restrict__ A, const __half* __restrict__ W,
    const float* __restrict__ bias, void* __restrict__ Cv,
    int amode, int omode, char* smc)
{
    const int tid  = threadIdx.x;
    const int lane = tid & 31;
    const int warp = tid >> 5;
    const int g = lane >> 2;
    const int t = lane & 3;
    const int m0 = blockIdx.y * TGM;
    const int n0 = blockIdx.x * TGN;
    const uint32_t smb = (uint32_t)__cvta_generic_to_shared(smc);

    float acc[8][4];
#pragma unroll
    for (int nt = 0; nt < 8; nt++)
#pragma unroll
        for (int j = 0; j < 4; j++) acc[nt][j] = 0.f;

    auto issue = [&](int k0, int buf) {
        const int ab = buf ? HA1 : HA0;
        const int bb2 = buf ? HB1 : HB0;
#pragma unroll
        for (int i = 0; i < 2; i++) {
            int idx = tid + i * 256;
            int row = idx >> 2, c4 = idx & 3;
            int gm = m0 + row;
            const __half* src;
            if (amode == 0) {
                src = A + (size_t)gm * DM + k0 + c4 * 8;
            } else {
                int b = gm >> 11, l = gm & (LL - 1);
                int head = k0 >> 5;
                src = A + (((size_t)b * HH + head) * LL + l) * DH + c4 * 8;
            }
            cp16(smb + (uint32_t)(ab + row * 80 + c4 * 16), src, 16);
        }
        {
            int row = tid >> 2, c4 = tid & 3;
            const __half* src = W + (size_t)(n0 + row) * DM + k0 + c4 * 8;
            cp16(smb + (uint32_t)(bb2 + row * 80 + c4 * 16), src, 16);
        }
    };

    issue(0, 0);
    cp_commit();

    for (int c = 0; c < 16; c++) {
        cp_wait<0>();
        __syncthreads();
        if (c < 15) issue((c + 1) * TGK, (c + 1) & 1);
        cp_commit();

        const uint32_t* Aw = (const uint32_t*)(smc + ((c & 1) ? HA1 : HA0));
        const uint32_t* Bw = (const uint32_t*)(smc + ((c & 1) ? HB1 : HB0));
#pragma unroll
        for (int kt = 0; kt < 2; kt++) {
            int ar = warp * 16 + g;
            int aw0 = ar * HGW + t + 8 * kt;
            int aw1 = (ar + 8) * HGW + t + 8 * kt;
            uint32_t a0 = Aw[aw0], a1 = Aw[aw1];
            uint32_t a2 = Aw[aw0 + 4], a3 = Aw[aw1 + 4];
#pragma unroll
            for (int nt = 0; nt < 8; nt++) {
                int bw = (nt * 8 + g) * HGW + t + 8 * kt;
                mma_f16(acc[nt][0], acc[nt][1], acc[nt][2], acc[nt][3],
                        a0, a1, a2, a3, Bw[bw], Bw[bw + 4]);
            }
        }
    }

    const int sr = warp * 16 + g;
    const int gm = m0 + sr;
    const int bb = gm >> 11, l = gm & (LL - 1);
#pragma unroll
    for (int nt = 0; nt < 8; nt++) {
        int sc = nt * 8 + 2 * t;
        int n  = n0 + sc;
        float b0v = bias ? bias[n]     : 0.f;
        float b1v = bias ? bias[n + 1] : 0.f;
        float2 p0 = make_float2(acc[nt][0] + b0v, acc[nt][1] + b1v);
        float2 p1 = make_float2(acc[nt][2] + b0v, acc[nt][3] + b1v);
        if (omode == 0) {
            float* Cf = (float*)Cv;
            *(float2*)(Cf + (size_t)gm * DM + n)       = p0;
            *(float2*)(Cf + (size_t)(gm + 8) * DM + n) = p1;
        } else if (omode == 1) {
            float* Cf = (float*)Cv;
            int head = n >> 5, d = n & 31;
            float* base = Cf + (((size_t)bb * HH + head) * LL + l) * DH + d;
            *(float2*)(base)          = p0;
            *(float2*)(base + 8 * DH) = p1;
        } else if (omode == 2) {
            __half* Ch = (__half*)Cv;
            int head = n >> 5, d = n & 31;
            __half* base = Ch + (((size_t)bb * HH + head) * LL + l) * DH + d;
            __half2 h0 = __floats2half2_rn(p0.x, p0.y);
            __half2 h1 = __floats2half2_rn(p1.x, p1.y);
            *(__half2*)(base)          = h0;
            *(__half2*)(base + 8 * DH) = h1;
        } else {
            __half* Ch = (__half*)Cv;
            int head = n >> 5, d = n & 31;
            __half* base = Ch + (((size_t)bb * HH + head) * DH + d) * LL + l;
            base[0]      = __float2half_rn(p0.x);
            base[LL]     = __float2half_rn(p0.y);
            base[8]      = __float2half_rn(p1.x);
            base[LL + 8] = __float2half_rn(p1.y);
        }
    }
}

__global__ __launch_bounds__(256)
void qkvp_gemm(const float* __restrict__ bq, const float* __restrict__ bk,
               const float* __restrict__ bv)
{
    extern __shared__ char smc[];
    int z = blockIdx.z;
    if (z == 3 && blockIdx.y >= LL / TGM) return;
    const __half* A = g_inh + (size_t)z * QN;
    const __half* W = g_wh + (size_t)z * DM * DM;
    const float* b = (z == 0) ? bq : (z == 1) ? bk : (z == 2) ? bv : nullptr;
    void* C; int omode;
    if (z == 0)      { C = g_q;  omode = 1; }
    else if (z == 1) { C = g_kh; omode = 2; }
    else if (z == 2) { C = g_vh; omode = 3; }
    else             { C = g_ph; omode = 2; }
    gemm_core_h(A, W, b, C, 0, omode, smc);
}

__global__ __launch_bounds__(256)
void wo_gemm(const float* __restrict__ bias, float* __restrict__ C)
{
    extern __shared__ char smc[];
    gemm_core_h(g_ctxh, g_wh + (size_t)4 * DM * DM, bias, C, 1, 0, smc);
}

// ---------------------------------------------------------------------------
// FA2-style uniform-warp attention. 4 warps; warp w owns rows 16w..16w+15.
// Per tile: W-band MMA -> resolved fp16 ring; S MMA (register accumulator);
// sync; in-fragment gather+softmax (log2 domain); P packed to A-frags in
// registers; PV MMA to persistent dacc. No sS / no pwW smem round trips.
// Shift: r=j-i; r<=0 -> p[L-1+r]; r==1 -> 0; r>=2 -> row i+1 uses p[r-2]
// (resolved ring: W[s][r] stored at row s-(r>=1); mixed tile iff r0==0)
// ---------------------------------------------------------------------------
#define TI 64
#define TJ 64
#define HW 20     /* K/P/Q tile word stride (80B rows) */
#define VW 36     /* V^T word stride (144B rows) */
#define WSTRH 134 /* ring half stride */
#define RING 128

#define QU_B 0        /* 64x80  = 5120 (reused: K buf1 after frag hoist) */
#define QV_B 5120     /* 65x80  = 5200 (bytes<4608 reused: V buf1; qv64 safe) */
#define K0_B 10320
#define V0_B 15440    /* 32x144 = 4608 */
#define P0_B 20048
#define P1_B 25168
#define SW_B 30288    /* 64x134x2 = 17152 */
#define SMEM_BYTES 47488

__global__ __launch_bounds__(128, 4)
void attn_mma(const float* __restrict__ qd, const __half* __restrict__ kd,
              const __half* __restrict__ vd, const __half* __restrict__ pd,
              const float* __restrict__ ub, const float* __restrict__ vb,
              __half* __restrict__ ctx)
{
    extern __shared__ char smc[];
    __half* sWh = (__half*)(smc + SW_B);
    const uint32_t smb = (uint32_t)__cvta_generic_to_shared(smc);

    const int tid  = threadIdx.x;
    const int lane = tid & 31;
    const int warp = tid >> 5;
    const int g = lane >> 2, tq = lane & 3;
    const int I0 = blockIdx.x * TI;
    const int h = blockIdx.y, b = blockIdx.z;

    const float*  qbase  = qd + (size_t)(b * HH + h) * LL * DH;
    const __half* kbase  = kd + (size_t)(b * HH + h) * LL * DH;
    const __half* vtbase = vd + (size_t)(b * HH + h) * DH * LL;
    const __half* pbase  = pd + (size_t)h * LL * DH;

    const int KbufB[2] = {K0_B, QU_B};
    const int VbufB[2] = {V0_B, QV_B};
    const int PbufB[2] = {P0_B, P1_B};

    // ---- stage Qu (64 rows) / Qv (65 rows), rn-fp16, pre-scaled by SC2
    for (int idx = tid; idx < TI * 8; idx += 128) {
        int row = idx >> 3, c4 = idx & 7;
        float4 q  = *(const float4*)(qbase + (size_t)(I0 + row) * DH + c4 * 4);
        float4 u4 = *(const float4*)(ub + h * DH + c4 * 4);
        __half2 h0 = __floats2half2_rn((q.x + u4.x) * SC2, (q.y + u4.y) * SC2);
        __half2 h1 = __floats2half2_rn((q.z + u4.z) * SC2, (q.w + u4.w) * SC2);
        *(uint2*)(smc + QU_B + row * 80 + c4 * 8) =
            make_uint2(*(uint32_t*)&h0, *(uint32_t*)&h1);
    }
    for (int idx = tid; idx < (TI + 1) * 8; idx += 128) {
        int row = idx >> 3, c4 = idx & 7;
        int gr = I0 + row;
        uint2 o = make_uint2(0u, 0u);
        if (gr < LL) {
            float4 q  = *(const float4*)(qbase + (size_t)gr * DH + c4 * 4);
            float4 v4 = *(const float4*)(vb + h * DH + c4 * 4);
            __half2 h0 = __floats2half2_rn((q.x + v4.x) * SC2, (q.y + v4.y) * SC2);
            __half2 h1 = __floats2half2_rn((q.z + v4.z) * SC2, (q.w + v4.w) * SC2);
            o = make_uint2(*(uint32_t*)&h0, *(uint32_t*)&h1);
        }
        *(uint2*)(smc + QV_B + row * 80 + c4 * 8) = o;
    }
    // ---- stage prologue band cols r in [-I0-64, -I0-1] into P1
    for (int idx = tid; idx < 64 * 4; idx += 128) {
        int row = idx >> 2, c4 = idx & 3;
        int r = -I0 - 64 + row;
        uint4 v = make_uint4(0u, 0u, 0u, 0u);
        if (r <= 0) { if (r >= 1 - LL) v = *(const uint4*)(pbase + (size_t)(LL - 1 + r) * DH + c4 * 8); }
        else if (r >= 2 && r <= LL + 1) v = *(const uint4*)(pbase + (size_t)(r - 2) * DH + c4 * 8);
        *(uint4*)(smc + P1_B + row * 80 + c4 * 16) = v;
    }
    __syncthreads();

    auto issueKPV = [&](int Jk, int Jp, int nb) {
#pragma unroll
        for (int i = 0; i < 2; i++) {
            int idx = tid + i * 128;
            int row = idx >> 2, c4 = idx & 3;
            cp16(smb + (uint32_t)(KbufB[nb] + row * 80 + c4 * 16),
                 kbase + (size_t)(Jk + row) * DH + c4 * 8, 16);
            int r = Jp - I0 + row;
            const __half* psrc = pbase;
            int sz = 0;
            if (r <= 0) { if (r >= 1 - LL) { psrc = pbase + (size_t)(LL - 1 + r) * DH + c4 * 8; sz = 16; } }
            else if (r >= 2 && r <= LL + 1) { psrc = pbase + (size_t)(r - 2) * DH + c4 * 8; sz = 16; }
            cp16(smb + (uint32_t)(PbufB[nb] + row * 80 + c4 * 16), psrc, sz);
        }
#pragma unroll
        for (int i = 0; i < 2; i++) {
            int idx = tid + i * 128;
            int ch = idx >> 3, c8 = idx & 7;
            cp16(smb + (uint32_t)(VbufB[nb] + ch * 144 + c8 * 16),
                 vtbase + (size_t)ch * LL + Jk + c8 * 8, 16);
        }
    };

    issueKPV(0, 0, 0);
    cp_commit();

    // ---- hoist A-frags (rows 16w..16w+15)
    const uint32_t* QuW = (const uint32_t*)(smc + QU_B);
    const uint32_t* QvW = (const uint32_t*)(smc + QV_B);
    uint32_t afu[2][4], afv[2][4];
#pragma unroll
    for (int kt = 0; kt < 2; kt++) {
        int w0 = (16 * warp + g) * HW + tq + 8 * kt;
        int w1 = w0 + 8 * HW;
        afu[kt][0] = QuW[w0];     afu[kt][1] = QuW[w1];
        afu[kt][2] = QuW[w0 + 4]; afu[kt][3] = QuW[w1 + 4];
        afv[kt][0] = QvW[w0];     afv[kt][1] = QvW[w1];
        afv[kt][2] = QvW[w0 + 4]; afv[kt][3] = QvW[w1 + 4];
    }

    // ---- prologue W from P1 (all r<=0: resolved row == source row)
    {
        const int slotbase = ((-I0 - 64) + 4096) & (RING - 1);
        const uint32_t* Pw = (const uint32_t*)(smc + P1_B);
#pragma unroll
        for (int nt = 0; nt < 8; nt++) {
            float d0 = 0.f, d1 = 0.f, d2 = 0.f, d3 = 0.f;
#pragma unroll
            for (int kt = 0; kt < 2; kt++) {
                int bw = (nt * 8 + g) * HW + tq + 8 * kt;
                mma_f16(d0, d1, d2, d3,
                        afv[kt][0], afv[kt][1], afv[kt][2], afv[kt][3],
                        Pw[bw], Pw[bw + 4]);
            }
            int wr = 16 * warp + g;
            int wc = slotbase + nt * 8 + 2 * tq;
            *(__half2*)&sWh[wr * WSTRH + wc]       = __floats2half2_rn(d0, d1);
            *(__half2*)&sWh[(wr + 8) * WSTRH + wc] = __floats2half2_rn(d2, d3);
        }
    }
    __syncthreads();   // ring ready; QU/QV/P1 free for reuse

    // ---- persistent state
    float dacc[4][4];
#pragma unroll
    for (int nt = 0; nt < 4; nt++)
#pragma unroll
        for (int j = 0; j < 4; j++) dacc[nt][j] = 0.f;
    float rmax0 = -INFINITY, rmax1 = -INFINITY, rsum0 = 0.f, rsum1 = 0.f;

    const int row0 = 16 * warp + g;
    const __half* w0row = sWh + row0 * WSTRH;
    const __half* w1row = w0row + 8 * WSTRH;

    for (int t = 0; t < 32; t++) {
        const int J0 = t * TJ;
        cp_wait<0>();
        __syncthreads();   // tile t visible; prev tile fully consumed

        if (t < 31) {
            const int Jn = J0 + TJ;
            const int Jc = (Jn < LL) ? Jn : (LL - TJ);
            issueKPV(Jc, Jn, (t + 1) & 1);
            cp_commit();
        }

        const uint32_t* Kw = (const uint32_t*)(smc + KbufB[t & 1]);
        const uint32_t* Pw = (const uint32_t*)(smc + PbufB[t & 1]);
        const uint32_t* Vw = (const uint32_t*)(smc + VbufB[t & 1]);
        const int r0 = J0 - I0;
        const int slotbase = (r0 + 4096) & (RING - 1);

        // ---- W band MMA + resolved store
        {
            float wacc[8][4];
#pragma unroll
            for (int nt = 0; nt < 8; nt++) {
                float d0 = 0.f, d1 = 0.f, d2 = 0.f, d3 = 0.f;
#pragma unroll
                for (int kt = 0; kt < 2; kt++) {
                    int bw = (nt * 8 + g) * HW + tq + 8 * kt;
                    mma_f16(d0, d1, d2, d3,
                            afv[kt][0], afv[kt][1], afv[kt][2], afv[kt][3],
                            Pw[bw], Pw[bw + 4]);
                }
                wacc[nt][0] = d0; wacc[nt][1] = d1; wacc[nt][2] = d2; wacc[nt][3] = d3;
            }
            if (r0 != 0) {
                const int sh = (r0 >= 1) ? 1 : 0;
#pragma unroll
                for (int nt = 0; nt < 8; nt++) {
                    int wr = row0 - sh;
                    int wc = slotbase + nt * 8 + 2 * tq;
                    if (wr >= 0)
                        *(__half2*)&sWh[wr * WSTRH + wc] = __floats2half2_rn(wacc[nt][0], wacc[nt][1]);
                    *(__half2*)&sWh[(wr + 8) * WSTRH + wc] = __floats2half2_rn(wacc[nt][2], wacc[nt][3]);
                }
            } else {
                // mixed tile (r0==0, once per block): per-element resolve
#pragma unroll
                for (int nt = 0; nt < 8; nt++) {
                    int c0 = nt * 8 + 2 * tq;
#pragma unroll
                    for (int e = 0; e < 2; e++) {
                        int c = c0 + e;
                        int sh = (c >= 1) ? 1 : 0;
                        int wc = slotbase + c;
                        int w0r = row0 - sh;
                        if (w0r >= 0)
                            sWh[w0r * WSTRH + wc] = __float2half_rn(wacc[nt][e]);
                        sWh[(row0 + 8 - sh) * WSTRH + wc] = __float2half_rn(wacc[nt][2 + e]);
                    }
                }
            }
            // extra row 64 -> resolved row 63 (only where its r >= 1)
            if (tid < 64) {
                int r = r0 + tid;
                if (r >= 1) {
                    const __half2* qv64 = (const __half2*)(smc + QV_B + 64 * 80);
                    const __half2* pr   = (const __half2*)(smc + PbufB[t & 1] + tid * 80);
                    float s = 0.f;
#pragma unroll
                    for (int c = 0; c < 16; c++) {
                        float2 a = __half22float2(qv64[c]);
                        float2 bb2 = __half22float2(pr[c]);
                        s += a.x * bb2.x + a.y * bb2.y;
                    }
                    sWh[63 * WSTRH + slotbase + tid] = __float2half_rn(s);
                }
            }
        }

        // ---- S MMA (register accumulator)
        float sacc[8][4];
#pragma unroll
        for (int nt = 0; nt < 8; nt++) {
            float d0 = 0.f, d1 = 0.f, d2 = 0.f, d3 = 0.f;
#pragma unroll
            for (int kt = 0; kt < 2; kt++) {
                int bw = (nt * 8 + g) * HW + tq + 8 * kt;
                mma_f16(d0, d1, d2, d3,
                        afu[kt][0], afu[kt][1], afu[kt][2], afu[kt][3],
                        Kw[bw], Kw[bw + 4]);
            }
            sacc[nt][0] = d0; sacc[nt][1] = d1; sacc[nt][2] = d2; sacc[nt][3] = d3;
        }

        __syncthreads();   // ring W(t) complete

        // ---- in-fragment gather + softmax (log2 domain)
        const int rb0 = (J0 - I0 - row0 + 8192) & (RING - 1);
        const int rb1 = (J0 - I0 - row0 - 8 + 8192) & (RING - 1);
        float m0 = -INFINITY, m1 = -INFINITY;
#pragma unroll
        for (int nt = 0; nt < 8; nt++) {
            int c = nt * 8 + 2 * tq;
            sacc[nt][0] += __half2float(w0row[(rb0 + c) & (RING - 1)]);
            sacc[nt][1] += __half2float(w0row[(rb0 + c + 1) & (RING - 1)]);
            sacc[nt][2] += __half2float(w1row[(rb1 + c) & (RING - 1)]);
            sacc[nt][3] += __half2float(w1row[(rb1 + c + 1) & (RING - 1)]);
            m0 = fmaxf(m0, fmaxf(sacc[nt][0], sacc[nt][1]));
            m1 = fmaxf(m1, fmaxf(sacc[nt][2], sacc[nt][3]));
        }
        m0 = fmaxf(m0, __shfl_xor_sync(0xffffffffu, m0, 1));
        m0 = fmaxf(m0, __shfl_xor_sync(0xffffffffu, m0, 2));
        m1 = fmaxf(m1, __shfl_xor_sync(0xffffffffu, m1, 1));
        m1 = fmaxf(m1, __shfl_xor_sync(0xffffffffu, m1, 2));
        float mnew0 = fmaxf(rmax0, m0);
        float mnew1 = fmaxf(rmax1, m1);
        float corr0 = exp2f(rmax0 - mnew0);   // first tile: 2^-inf = 0
        float corr1 = exp2f(rmax1 - mnew1);

        uint32_t ha[8], hb[8];
        float csum0 = 0.f, csum1 = 0.f;
#pragma unroll
        for (int nt = 0; nt < 8; nt++) {
            __half2 h0 = __floats2half2_rn(exp2f(sacc[nt][0] - mnew0),
                                           exp2f(sacc[nt][1] - mnew0));
            __half2 h1 = __floats2half2_rn(exp2f(sacc[nt][2] - mnew1),
                                           exp2f(sacc[nt][3] - mnew1));
            float2 f0 = __half22float2(h0);
            float2 f1 = __half22float2(h1);
            csum0 += f0.x + f0.y;
            csum1 += f1.x + f1.y;
            ha[nt] = *(uint32_t*)&h0;
            hb[nt] = *(uint32_t*)&h1;
        }
        csum0 += __shfl_xor_sync(0xffffffffu, csum0, 1);
        csum0 += __shfl_xor_sync(0xffffffffu, csum0, 2);
        csum1 += __shfl_xor_sync(0xffffffffu, csum1, 1);
        csum1 += __shfl_xor_sync(0xffffffffu, csum1, 2);
        rsum0 = rsum0 * corr0 + csum0;
        rsum1 = rsum1 * corr1 + csum1;
        rmax0 = mnew0; rmax1 = mnew1;

        // ---- rescale + PV MMA (P from registers)
#pragma unroll
        for (int nt = 0; nt < 4; nt++) {
            dacc[nt][0] *= corr0; dacc[nt][1] *= corr0;
            dacc[nt][2] *= corr1; dacc[nt][3] *= corr1;
        }
#pragma unroll
        for (int kt = 0; kt < 4; kt++) {
            uint32_t a0 = ha[2 * kt], a1 = hb[2 * kt];
            uint32_t a2 = ha[2 * kt + 1], a3 = hb[2 * kt + 1];
#pragma unroll
            for (int nt = 0; nt < 4; nt++) {
                int bw = (nt * 8 + g) * VW + tq + 8 * kt;
                mma_f16(dacc[nt][0], dacc[nt][1], dacc[nt][2], dacc[nt][3],
                        a0, a1, a2, a3, Vw[bw], Vw[bw + 4]);
            }
        }
    }

    // ---- finalize: per-lane normalize, ctx as fp16
    {
        float inv0 = 1.f / rsum0;
        float inv1 = 1.f / rsum1;
        __half* ob = ctx + (size_t)(b * HH + h) * LL * DH;
#pragma unroll
        for (int nt = 0; nt < 4; nt++) {
            int sc = nt * 8 + 2 * tq;
            __half2 h0 = __floats2half2_rn(dacc[nt][0] * inv0, dacc[nt][1] * inv0);
            __half2 h1 = __floats2half2_rn(dacc[nt][2] * inv1, dacc[nt][3] * inv1);
            *(__half2*)(ob + (size_t)(I0 + row0) * DH + sc)     = h0;
            *(__half2*)(ob + (size_t)(I0 + row0 + 8) * DH + sc) = h1;
        }
    }
}

// ---------------------------------------------------------------------------
extern "C" void kernel_launch(void* const* d_in, const int* in_sizes, int n_in,
                              void* d_out, int out_size)
{
    const float* query = (const float*)d_in[0];
    const float* key   = (const float*)d_in[1];
    const float* value = (const float*)d_in[2];
    const float* pos   = (const float*)d_in[3];
    const float* Wq    = (const float*)d_in[4];
    const float* bq    = (const float*)d_in[5];
    const float* Wk    = (const float*)d_in[6];
    const float* bk    = (const float*)d_in[7];
    const float* Wv    = (const float*)d_in[8];
    const float* bv    = (const float*)d_in[9];
    const float* Wp    = (const float*)d_in[10];
    const float* ub    = (const float*)d_in[11];
    const float* vb    = (const float*)d_in[12];
    const float* Wo    = (const float*)d_in[13];
    const float* bo    = (const float*)d_in[14];

    float *pq;
    __half *pk, *pv, *pp, *pctx;
    cudaGetSymbolAddress((void**)&pq,   g_q);
    cudaGetSymbolAddress((void**)&pk,   g_kh);
    cudaGetSymbolAddress((void**)&pv,   g_vh);
    cudaGetSymbolAddress((void**)&pp,   g_ph);
    cudaGetSymbolAddress((void**)&pctx, g_ctxh);

    static int attr_set = 0;
    if (!attr_set) {
        cudaFuncSetAttribute(attn_mma, cudaFuncAttributeMaxDynamicSharedMemorySize, SMEM_BYTES);
        cudaFuncSetAttribute(qkvp_gemm, cudaFuncAttributeMaxDynamicSharedMemorySize, GSMEM_BYTES);
        cudaFuncSetAttribute(wo_gemm, cudaFuncAttributeMaxDynamicSharedMemorySize, GSMEM_BYTES);
        attr_set = 1;
    }

    preround<<<dim3(DM * DM / 1024, 1, 5), 256>>>(Wq, Wk, Wv, Wp, Wo);
    tohalf<<<(3 * QN + LL * DM) / 2048, 256>>>(query, key, value, pos);

    qkvp_gemm<<<dim3(DM / TGN, (BB * LL) / TGM, 4), 256, GSMEM_BYTES>>>(bq, bk, bv);

    attn_mma<<<dim3(LL / TI, HH, BB), 128, SMEM_BYTES>>>(pq, pk, pv, pp, ub, vb, pctx);

    wo_gemm<<<dim3(DM / TGN, (BB * LL) / TGM), 256, GSMEM_BYTES>>>(
        bo, (float*)d_out);
}